// round 3
// baseline (speedup 1.0000x reference)
#include <cuda_runtime.h>
#include <stdint.h>
#include <stddef.h>
#include <math.h>

#define T_ 11
#define N_NODES 50000
#define D_ 128
#define H_ 64
#define B_ 16384
#define K_ 10
#define MN 163840   // B_*K_

// ---------------- scratch (device globals; total ~530 MB to keep the host link
// inside the +/-2GB small-code-model relocation range) ----------------
__device__ float g_W1[(size_t)T_*128*384];     // packed content Wih (gates i,g,o x 2 dirs), [t][kk][384]
__device__ float g_B1[T_*384];
__device__ float g_W2[(size_t)T_*128*512];     // packed seq Wih (4 gates x 2 dirs), [t][kk][512]
__device__ float g_B2[T_*512];
__device__ float g_Whh[(size_t)T_*2*64*256];   // [t][dir][hh][n] transposed recurrent weights
__device__ float g_CE[(size_t)MN*128];         // content-encoded neighbors, ONE type (84 MB)
__device__ float g_IG[(size_t)MN*512];         // input-gate preacts, ONE type (336 MB)
__device__ float g_SELF[(size_t)B_*128];
__device__ float g_AGG[(size_t)T_*B_*128];

__device__ __forceinline__ float sigmoidf_(float x){ return 1.0f/(1.0f+expf(-x)); }

// ---------------- weight packing ----------------
__global__ void pack_kernel(const float* __restrict__ cWih_f, const float* __restrict__ cb_f,
                            const float* __restrict__ cWih_b, const float* __restrict__ cb_b,
                            const float* __restrict__ nWih_f, const float* __restrict__ nb_f,
                            const float* __restrict__ nWih_b, const float* __restrict__ nb_b,
                            const float* __restrict__ nWhh_f, const float* __restrict__ nWhh_b)
{
    int stride = gridDim.x*blockDim.x;
    int tid0 = blockIdx.x*blockDim.x + threadIdx.x;

    // W1: [t][kk][n], n = dir*192 + gate*64 + j, gate 0:i 1:g 2:o  (f-gate dead: zero state)
    for (size_t idx = tid0; idx < (size_t)T_*128*384; idx += stride) {
        int n = (int)(idx % 384); size_t rest = idx / 384;
        int kk = (int)(rest % 128); int t = (int)(rest / 128);
        int dir = n/192, rem = n%192, g = rem/64, j = rem%64;
        int row = (g==0) ? j : (g==1) ? 128+j : 192+j;
        const float* W = dir ? cWih_b : cWih_f;
        g_W1[idx] = W[((size_t)t*256 + row)*128 + kk];
    }
    for (int idx = tid0; idx < T_*384; idx += stride) {
        int n = idx % 384; int t = idx / 384;
        int dir = n/192, rem = n%192, g = rem/64, j = rem%64;
        int row = (g==0) ? j : (g==1) ? 128+j : 192+j;
        g_B1[idx] = (dir ? cb_b : cb_f)[t*256 + row];
    }
    // W2: [t][kk][n], n = dir*256 + r  (natural gate rows i,f,g,o)
    for (size_t idx = tid0; idx < (size_t)T_*128*512; idx += stride) {
        int n = (int)(idx % 512); size_t rest = idx/512;
        int kk = (int)(rest % 128); int t = (int)(rest/128);
        int dir = n/256, r = n%256;
        const float* W = dir ? nWih_b : nWih_f;
        g_W2[idx] = W[((size_t)t*256 + r)*128 + kk];
    }
    for (int idx = tid0; idx < T_*512; idx += stride) {
        int n = idx % 512; int t = idx/512;
        int dir = n/256, r = n%256;
        g_B2[idx] = (dir ? nb_b : nb_f)[t*256 + r];
    }
    // Whh transposed: [t][dir][hh][n]
    for (size_t idx = tid0; idx < (size_t)T_*2*64*256; idx += stride) {
        int n = (int)(idx % 256); size_t rest = idx/256;
        int hh = (int)(rest % 64); rest /= 64;
        int dir = (int)(rest % 2); int t = (int)(rest/2);
        const float* W = dir ? nWhh_b : nWhh_f;
        g_Whh[idx] = W[((size_t)t*256 + n)*64 + hh];
    }
}

// ---------------- stage A: content encode (gathered GEMM + LSTM epilogue) ----------------
// block: 256 thr, 64 rows x 1 direction (gates i,g,o x 64)
__global__ __launch_bounds__(256) void content_kernel(
    const float* __restrict__ features, const int* __restrict__ ids_all,
    int t, int self_mode)
{
    extern __shared__ float sm[];
    float* As = sm;                 // [128][68]  transposed A tile
    float* Ws = sm + 128*68;        // [32][196]  weight K-chunk

    const int* ids = self_mode ? ids_all : ids_all + (size_t)t*MN;
    const float* feat = features + (size_t)t*N_NODES*128;
    float* ce = self_mode ? g_SELF : g_CE;
    int dir = blockIdx.y;
    int m0 = blockIdx.x*64;
    int tid = threadIdx.x;

    {   // gather 64 feature rows, store transposed
        int rl = tid >> 5, c4 = tid & 31;
        for (int it = 0; it < 8; it++) {
            int r = rl + it*8;
            int id = ids[m0 + r];
            float4 v = *(const float4*)(feat + (size_t)id*128 + c4*4);
            As[(c4*4+0)*68 + r] = v.x;
            As[(c4*4+1)*68 + r] = v.y;
            As[(c4*4+2)*68 + r] = v.z;
            As[(c4*4+3)*68 + r] = v.w;
        }
    }

    float acc[3][4][4];
    #pragma unroll
    for (int g=0;g<3;g++)
        #pragma unroll
        for (int i=0;i<4;i++)
            #pragma unroll
            for (int jj=0;jj<4;jj++) acc[g][i][jj]=0.f;

    int tx = tid & 15;   // j tile (4 cols)
    int ty = tid >> 4;   // row tile (4 rows)
    const float* W1t = g_W1 + (size_t)t*128*384 + dir*192;

    for (int kc = 0; kc < 4; kc++) {
        __syncthreads();
        for (int it = 0; it < 6; it++) {          // 32x48 float4 = 1536
            int idx = tid + it*256;
            int kk = idx / 48, c4 = idx % 48;
            float4 v = *(const float4*)(W1t + (size_t)(kc*32+kk)*384 + c4*4);
            *(float4*)&Ws[kk*196 + c4*4] = v;
        }
        __syncthreads();
        #pragma unroll 8
        for (int kk = 0; kk < 32; kk++) {
            float4 a  = *(float4*)&As[(kc*32+kk)*68 + ty*4];
            float4 w0 = *(float4*)&Ws[kk*196 +   0 + tx*4];
            float4 w1 = *(float4*)&Ws[kk*196 +  64 + tx*4];
            float4 w2 = *(float4*)&Ws[kk*196 + 128 + tx*4];
            float av[4] = {a.x,a.y,a.z,a.w};
            float wv[3][4] = {{w0.x,w0.y,w0.z,w0.w},{w1.x,w1.y,w1.z,w1.w},{w2.x,w2.y,w2.z,w2.w}};
            #pragma unroll
            for (int i=0;i<4;i++)
                #pragma unroll
                for (int g=0;g<3;g++)
                    #pragma unroll
                    for (int jj=0;jj<4;jj++)
                        acc[g][i][jj] += av[i]*wv[g][jj];
        }
    }

    const float* B1t = g_B1 + t*384 + dir*192;
    #pragma unroll
    for (int i=0;i<4;i++) {
        int m = m0 + ty*4 + i;
        float o4[4];
        #pragma unroll
        for (int jj=0;jj<4;jj++) {
            int j = tx*4+jj;
            float gi = acc[0][i][jj] + B1t[j];
            float gg = acc[1][i][jj] + B1t[64+j];
            float go = acc[2][i][jj] + B1t[128+j];
            float cc = sigmoidf_(gi) * tanhf(gg);
            o4[jj] = sigmoidf_(go) * tanhf(cc);
        }
        float4 v; v.x=o4[0]; v.y=o4[1]; v.z=o4[2]; v.w=o4[3];
        *(float4*)(ce + (size_t)m*128 + dir*64 + tx*4) = v;
    }
}

// ---------------- stage B1: seq-LSTM input projections (GEMM) ----------------
// block: 256 thr, 128 rows x 64 cols
__global__ __launch_bounds__(256) void ig_kernel(int t)
{
    extern __shared__ float sm[];
    float* As = sm;            // [128][132]
    float* Ws = sm + 128*132;  // [32][68]

    int nt = blockIdx.y;       // 0..7
    int m0 = blockIdx.x*128;
    int tid = threadIdx.x;

    {   // load 128x128 CE tile transposed
        int rl = tid >> 5, c4 = tid & 31;
        for (int it=0; it<16; it++) {
            int r = rl + it*8;
            float4 v = *(const float4*)(g_CE + (size_t)(m0+r)*128 + c4*4);
            As[(c4*4+0)*132 + r] = v.x;
            As[(c4*4+1)*132 + r] = v.y;
            As[(c4*4+2)*132 + r] = v.z;
            As[(c4*4+3)*132 + r] = v.w;
        }
    }

    float acc[8][4];
    #pragma unroll
    for (int i=0;i<8;i++)
        #pragma unroll
        for (int jj=0;jj<4;jj++) acc[i][jj]=0.f;

    int tx = tid & 15, ty = tid >> 4;
    const float* W2t = g_W2 + (size_t)t*128*512 + nt*64;

    for (int kc=0; kc<4; kc++) {
        __syncthreads();
        for (int it=0; it<2; it++) {     // 32x16 float4 = 512
            int idx = tid + it*256;
            int kk = idx / 16, c4 = idx % 16;
            float4 v = *(const float4*)(W2t + (size_t)(kc*32+kk)*512 + c4*4);
            *(float4*)&Ws[kk*68 + c4*4] = v;
        }
        __syncthreads();
        #pragma unroll 8
        for (int kk=0; kk<32; kk++) {
            float4 a0 = *(float4*)&As[(kc*32+kk)*132 + ty*8];
            float4 a1 = *(float4*)&As[(kc*32+kk)*132 + ty*8 + 4];
            float4 w  = *(float4*)&Ws[kk*68 + tx*4];
            float av[8] = {a0.x,a0.y,a0.z,a0.w,a1.x,a1.y,a1.z,a1.w};
            float wv[4] = {w.x,w.y,w.z,w.w};
            #pragma unroll
            for (int i=0;i<8;i++)
                #pragma unroll
                for (int jj=0;jj<4;jj++)
                    acc[i][jj] += av[i]*wv[jj];
        }
    }

    const float* B2t = g_B2 + t*512 + nt*64;
    float b[4];
    #pragma unroll
    for (int jj=0;jj<4;jj++) b[jj] = B2t[tx*4+jj];
    #pragma unroll
    for (int i=0;i<8;i++) {
        int m = m0 + ty*8 + i;
        float4 v;
        v.x = acc[i][0]+b[0]; v.y = acc[i][1]+b[1];
        v.z = acc[i][2]+b[2]; v.w = acc[i][3]+b[3];
        *(float4*)(g_IG + (size_t)m*512 + nt*64 + tx*4) = v;
    }
}

// ---------------- stage B2: LSTM recurrence over K=10 ----------------
// block: 256 thr, 64 batch rows; Whh resident in smem; h double-buffered transposed
__global__ __launch_bounds__(256) void recur_kernel(int t)
{
    extern __shared__ float sm[];
    float* Whh_s = sm;             // [64][260]
    float* hT0 = sm + 64*260;      // [64][68]
    float* hT1 = hT0 + 64*68;

    int dir = blockIdx.y;
    int b0 = blockIdx.x*64;
    int tid = threadIdx.x;
    int tx = tid & 15, ty = tid >> 4;

    const float* Wsrc = g_Whh + ((size_t)t*2 + dir)*64*256;
    for (int it=0; it<16; it++) {        // 64x64 float4 = 4096
        int idx = tid + it*256;
        int hh = idx / 64, c4 = idx % 64;
        float4 v = *(const float4*)(Wsrc + (size_t)hh*256 + c4*4);
        *(float4*)&Whh_s[hh*260 + c4*4] = v;
    }
    for (int idx = tid; idx < 64*68; idx += 256) hT0[idx] = 0.f;
    __syncthreads();

    const float* ig = g_IG + dir*256;
    float c[4][4], hs[4][4];
    #pragma unroll
    for (int i=0;i<4;i++)
        #pragma unroll
        for (int jj=0;jj<4;jj++){ c[i][jj]=0.f; hs[i][jj]=0.f; }

    float* cur = hT0; float* nxt = hT1;

    for (int step=0; step<K_; step++) {
        int k = dir ? (K_-1-step) : step;
        float acc[4][4][4];    // [row][gate][jj]
        #pragma unroll
        for (int i=0;i<4;i++) {
            size_t base = ((size_t)(b0+ty*4+i)*K_ + k)*512;
            #pragma unroll
            for (int g=0; g<4; g++) {
                float4 v = *(const float4*)(ig + base + g*64 + tx*4);
                acc[i][g][0]=v.x; acc[i][g][1]=v.y; acc[i][g][2]=v.z; acc[i][g][3]=v.w;
            }
        }
        #pragma unroll 4
        for (int hh=0; hh<64; hh++) {
            float4 a  = *(float4*)&cur[hh*68 + ty*4];
            float4 w0 = *(float4*)&Whh_s[hh*260 +   0 + tx*4];
            float4 w1 = *(float4*)&Whh_s[hh*260 +  64 + tx*4];
            float4 w2 = *(float4*)&Whh_s[hh*260 + 128 + tx*4];
            float4 w3 = *(float4*)&Whh_s[hh*260 + 192 + tx*4];
            float av[4] = {a.x,a.y,a.z,a.w};
            float wv[4][4] = {{w0.x,w0.y,w0.z,w0.w},{w1.x,w1.y,w1.z,w1.w},
                              {w2.x,w2.y,w2.z,w2.w},{w3.x,w3.y,w3.z,w3.w}};
            #pragma unroll
            for (int i=0;i<4;i++)
                #pragma unroll
                for (int g=0;g<4;g++)
                    #pragma unroll
                    for (int jj=0;jj<4;jj++)
                        acc[i][g][jj] += av[i]*wv[g][jj];
        }
        #pragma unroll
        for (int i=0;i<4;i++)
            #pragma unroll
            for (int jj=0;jj<4;jj++) {
                float ii = sigmoidf_(acc[i][0][jj]);
                float ff = sigmoidf_(acc[i][1][jj]);
                float gg = tanhf   (acc[i][2][jj]);
                float oo = sigmoidf_(acc[i][3][jj]);
                c[i][jj] = ff*c[i][jj] + ii*gg;
                float h = oo*tanhf(c[i][jj]);
                hs[i][jj] += h;
                nxt[(tx*4+jj)*68 + ty*4 + i] = h;
            }
        __syncthreads();
        float* tmp = cur; cur = nxt; nxt = tmp;
    }

    #pragma unroll
    for (int i=0;i<4;i++) {
        int b = b0 + ty*4 + i;
        #pragma unroll
        for (int jj=0;jj<4;jj++)
            g_AGG[((size_t)t*B_ + b)*128 + dir*64 + tx*4 + jj] = hs[i][jj] * (1.0f/K_);
    }
}

// ---------------- stage C: attention combine ----------------
__global__ __launch_bounds__(256) void attn_kernel(const float* __restrict__ att,
                                                   float* __restrict__ out)
{
    int warp = threadIdx.x >> 5;
    int lane = threadIdx.x & 31;
    int b = blockIdx.x*8 + warp;

    float e[12][4], a0[4], a1[4];
    #pragma unroll
    for (int i=0;i<4;i++) {
        int d = i*32 + lane;
        a0[i] = att[d];
        a1[i] = att[128+d];
        e[0][i] = g_SELF[(size_t)b*128 + d];
    }
    #pragma unroll
    for (int t=0;t<T_;t++)
        #pragma unroll
        for (int i=0;i<4;i++)
            e[1+t][i] = g_AGG[((size_t)t*B_ + b)*128 + i*32 + lane];

    float pself = 0.f;
    #pragma unroll
    for (int i=0;i<4;i++) pself += e[0][i]*a0[i];
    float sc[12];
    #pragma unroll
    for (int j=0;j<12;j++) {
        float p = 0.f;
        #pragma unroll
        for (int i=0;i<4;i++) p += e[j][i]*a1[i];
        sc[j] = p;
    }
    #pragma unroll
    for (int off=16; off>0; off>>=1) {
        pself += __shfl_xor_sync(0xffffffff, pself, off);
        #pragma unroll
        for (int j=0;j<12;j++) sc[j] += __shfl_xor_sync(0xffffffff, sc[j], off);
    }
    float mx = -1e30f;
    #pragma unroll
    for (int j=0;j<12;j++) {
        float s = pself + sc[j];
        s = (s > 0.f) ? s : 0.01f*s;    // leaky_relu(0.01)
        sc[j] = s;
        mx = fmaxf(mx, s);
    }
    float sum = 0.f;
    #pragma unroll
    for (int j=0;j<12;j++) { sc[j] = expf(sc[j]-mx); sum += sc[j]; }
    float inv = 1.f/sum;
    #pragma unroll
    for (int i=0;i<4;i++) {
        float o = 0.f;
        #pragma unroll
        for (int j=0;j<12;j++) o += sc[j]*e[j][i];
        out[(size_t)b*128 + i*32 + lane] = o*inv;
    }
}

// ---------------- launch ----------------
extern "C" void kernel_launch(void* const* d_in, const int* in_sizes, int n_in,
                              void* d_out, int out_size)
{
    const float* features = (const float*)d_in[0];
    const int*   id_batch = (const int*)d_in[1];
    const int*   neigh_ids= (const int*)d_in[2];
    const float* cWih_f   = (const float*)d_in[3];
    // d_in[4] = cWhh_f : unused (zero-state content LSTM)
    const float* cb_f     = (const float*)d_in[5];
    const float* cWih_b   = (const float*)d_in[6];
    // d_in[7] = cWhh_b : unused
    const float* cb_b     = (const float*)d_in[8];
    const float* nWih_f   = (const float*)d_in[9];
    const float* nWhh_f   = (const float*)d_in[10];
    const float* nb_f     = (const float*)d_in[11];
    const float* nWih_b   = (const float*)d_in[12];
    const float* nWhh_b   = (const float*)d_in[13];
    const float* nb_b     = (const float*)d_in[14];
    const float* att      = (const float*)d_in[15];
    float* out = (float*)d_out;

    const int SMEM_CONTENT = (128*68 + 32*196) * 4;        // 59904
    const int SMEM_IG      = (128*132 + 32*68) * 4;        // 76288
    const int SMEM_RECUR   = (64*260 + 2*64*68) * 4;       // 101376
    cudaFuncSetAttribute(content_kernel, cudaFuncAttributeMaxDynamicSharedMemorySize, SMEM_CONTENT);
    cudaFuncSetAttribute(ig_kernel,      cudaFuncAttributeMaxDynamicSharedMemorySize, SMEM_IG);
    cudaFuncSetAttribute(recur_kernel,   cudaFuncAttributeMaxDynamicSharedMemorySize, SMEM_RECUR);

    pack_kernel<<<512, 256>>>(cWih_f, cb_f, cWih_b, cb_b,
                              nWih_f, nb_f, nWih_b, nb_b, nWhh_f, nWhh_b);

    // self content encode (type 0, id_batch)
    {
        dim3 g(B_/64, 2);
        content_kernel<<<g, 256, SMEM_CONTENT>>>(features, id_batch, 0, 1);
    }

    // per-type pipeline, reusing single-type CE/IG scratch (stream-serialized)
    for (int t = 0; t < T_; t++) {
        dim3 gc(MN/64, 2);
        content_kernel<<<gc, 256, SMEM_CONTENT>>>(features, neigh_ids, t, 0);
        dim3 gi(MN/128, 8);
        ig_kernel<<<gi, 256, SMEM_IG>>>(t);
        dim3 gr(B_/64, 2);
        recur_kernel<<<gr, 256, SMEM_RECUR>>>(t);
    }

    attn_kernel<<<B_/8, 256>>>(att, out);
}

// round 4
// speedup vs baseline: 2.3189x; 2.3189x over previous
#include <cuda_runtime.h>
#include <stdint.h>
#include <stddef.h>
#include <math.h>

#define T_ 11
#define N_NODES 50000
#define D_ 128
#define H_ 64
#define B_ 16384
#define K_ 10
#define MN 163840        // B_*K_
#define NROW_BLKS 391    // ceil(50000/128)

// ---------------- scratch (device globals; ~250 MB total) ----------------
__device__ float g_W1[(size_t)T_*128*384];     // packed content Wih (gates i,g,o x 2 dirs), [t][kk][384]
__device__ float g_B1[T_*384];
__device__ float g_W2[(size_t)T_*128*512];     // packed seq Wih (4 gates x 2 dirs), [t][kk][512]
__device__ float g_B2[T_*512];
__device__ float g_Whh[(size_t)T_*2*64*256];   // [t][dir][hh][n] transposed recurrent weights
__device__ float g_CE[(size_t)N_NODES*128];    // per-node content encodings, ONE type (25.6 MB)
__device__ float g_IG[(size_t)N_NODES*512];    // per-node seq-LSTM input preacts, ONE type (102 MB)
__device__ float g_SELF[(size_t)B_*128];
__device__ float g_AGG[(size_t)T_*B_*128];

__device__ __forceinline__ float sigmoid_f(float x){
    return __fdividef(1.0f, 1.0f + __expf(-x));
}
__device__ __forceinline__ float tanh_f(float x){
    // 1 - 2*sigmoid(-2x); saturates correctly, abs err ~1e-6
    return 1.0f - __fdividef(2.0f, 1.0f + __expf(2.0f*x));
}

// ---------------- weight packing ----------------
__global__ void pack_kernel(const float* __restrict__ cWih_f, const float* __restrict__ cb_f,
                            const float* __restrict__ cWih_b, const float* __restrict__ cb_b,
                            const float* __restrict__ nWih_f, const float* __restrict__ nb_f,
                            const float* __restrict__ nWih_b, const float* __restrict__ nb_b,
                            const float* __restrict__ nWhh_f, const float* __restrict__ nWhh_b)
{
    int stride = gridDim.x*blockDim.x;
    int tid0 = blockIdx.x*blockDim.x + threadIdx.x;

    // W1: [t][kk][n], n = dir*192 + gate*64 + j, gate 0:i 1:g 2:o (f-gate dead: zero state)
    for (size_t idx = tid0; idx < (size_t)T_*128*384; idx += stride) {
        int n = (int)(idx % 384); size_t rest = idx / 384;
        int kk = (int)(rest % 128); int t = (int)(rest / 128);
        int dir = n/192, rem = n%192, g = rem/64, j = rem%64;
        int row = (g==0) ? j : (g==1) ? 128+j : 192+j;
        const float* W = dir ? cWih_b : cWih_f;
        g_W1[idx] = W[((size_t)t*256 + row)*128 + kk];
    }
    for (int idx = tid0; idx < T_*384; idx += stride) {
        int n = idx % 384; int t = idx / 384;
        int dir = n/192, rem = n%192, g = rem/64, j = rem%64;
        int row = (g==0) ? j : (g==1) ? 128+j : 192+j;
        g_B1[idx] = (dir ? cb_b : cb_f)[t*256 + row];
    }
    // W2: [t][kk][n], n = dir*256 + r  (natural gate rows i,f,g,o)
    for (size_t idx = tid0; idx < (size_t)T_*128*512; idx += stride) {
        int n = (int)(idx % 512); size_t rest = idx/512;
        int kk = (int)(rest % 128); int t = (int)(rest/128);
        int dir = n/256, r = n%256;
        const float* W = dir ? nWih_b : nWih_f;
        g_W2[idx] = W[((size_t)t*256 + r)*128 + kk];
    }
    for (int idx = tid0; idx < T_*512; idx += stride) {
        int n = idx % 512; int t = idx/512;
        int dir = n/256, r = n%256;
        g_B2[idx] = (dir ? nb_b : nb_f)[t*256 + r];
    }
    // Whh transposed: [t][dir][hh][n]
    for (size_t idx = tid0; idx < (size_t)T_*2*64*256; idx += stride) {
        int n = (int)(idx % 256); size_t rest = idx/256;
        int hh = (int)(rest % 64); rest /= 64;
        int dir = (int)(rest % 2); int t = (int)(rest/2);
        const float* W = dir ? nWhh_b : nWhh_f;
        g_Whh[idx] = W[((size_t)t*256 + n)*64 + hh];
    }
}

// ---------------- stage A: dense per-node content encode ----------------
// grid (391, 2); block 256 thr; tile 128 rows x 192 cols (one dir: gates i,g,o x 64)
__global__ __launch_bounds__(256) void content_kernel(
    const float* __restrict__ features, int t)
{
    extern __shared__ float sm[];
    float* As = sm;                 // [128][132]  transposed feature tile As[kk][r]
    float* Ws = sm + 128*132;       // [32][196]   weight K-chunk

    const float* feat = features + (size_t)t*N_NODES*128;
    int dir = blockIdx.y;
    int m0 = blockIdx.x*128;
    int tid = threadIdx.x;

    {   // load 128x128 tile transposed (dense, coalesced), clamp tail rows
        int rl = tid >> 5, c4 = tid & 31;
        for (int it = 0; it < 16; it++) {
            int r = rl + it*8;
            int row = m0 + r; if (row >= N_NODES) row = N_NODES-1;
            float4 v = *(const float4*)(feat + (size_t)row*128 + c4*4);
            As[(c4*4+0)*132 + r] = v.x;
            As[(c4*4+1)*132 + r] = v.y;
            As[(c4*4+2)*132 + r] = v.z;
            As[(c4*4+3)*132 + r] = v.w;
        }
    }

    float acc[3][8][4];
    #pragma unroll
    for (int g=0;g<3;g++)
        #pragma unroll
        for (int i=0;i<8;i++)
            #pragma unroll
            for (int jj=0;jj<4;jj++) acc[g][i][jj]=0.f;

    int tx = tid & 15;   // j tile (4 cols per gate)
    int ty = tid >> 4;   // row tile (8 rows)
    const float* W1t = g_W1 + (size_t)t*128*384 + dir*192;

    for (int kc = 0; kc < 4; kc++) {
        __syncthreads();
        for (int it = 0; it < 6; it++) {          // 32x48 float4 = 1536
            int idx = tid + it*256;
            int kk = idx / 48, c4 = idx % 48;
            float4 v = *(const float4*)(W1t + (size_t)(kc*32+kk)*384 + c4*4);
            *(float4*)&Ws[kk*196 + c4*4] = v;
        }
        __syncthreads();
        #pragma unroll 2
        for (int kk = 0; kk < 32; kk++) {
            float4 a0 = *(float4*)&As[(kc*32+kk)*132 + ty*8];
            float4 a1 = *(float4*)&As[(kc*32+kk)*132 + ty*8 + 4];
            float4 w0 = *(float4*)&Ws[kk*196 +   0 + tx*4];
            float4 w1 = *(float4*)&Ws[kk*196 +  64 + tx*4];
            float4 w2 = *(float4*)&Ws[kk*196 + 128 + tx*4];
            float av[8] = {a0.x,a0.y,a0.z,a0.w,a1.x,a1.y,a1.z,a1.w};
            float wv[3][4] = {{w0.x,w0.y,w0.z,w0.w},{w1.x,w1.y,w1.z,w1.w},{w2.x,w2.y,w2.z,w2.w}};
            #pragma unroll
            for (int i=0;i<8;i++)
                #pragma unroll
                for (int g=0;g<3;g++)
                    #pragma unroll
                    for (int jj=0;jj<4;jj++)
                        acc[g][i][jj] += av[i]*wv[g][jj];
        }
    }

    const float* B1t = g_B1 + t*384 + dir*192;
    float bi[4], bg[4], bo[4];
    #pragma unroll
    for (int jj=0;jj<4;jj++) {
        int j = tx*4+jj;
        bi[jj] = B1t[j]; bg[jj] = B1t[64+j]; bo[jj] = B1t[128+j];
    }
    #pragma unroll
    for (int i=0;i<8;i++) {
        int m = m0 + ty*8 + i;
        if (m < N_NODES) {
            float o4[4];
            #pragma unroll
            for (int jj=0;jj<4;jj++) {
                float gi = acc[0][i][jj] + bi[jj];
                float gg = acc[1][i][jj] + bg[jj];
                float go = acc[2][i][jj] + bo[jj];
                float cc = sigmoid_f(gi) * tanh_f(gg);
                o4[jj] = sigmoid_f(go) * tanh_f(cc);
            }
            float4 v; v.x=o4[0]; v.y=o4[1]; v.z=o4[2]; v.w=o4[3];
            *(float4*)(g_CE + (size_t)m*128 + dir*64 + tx*4) = v;
        }
    }
}

// ---------------- self embed: gather type-0 CE rows ----------------
__global__ void self_gather_kernel(const int* __restrict__ id_batch)
{
    int b = blockIdx.x;
    int tid = threadIdx.x;                 // 32 threads, one float4 each
    int id = id_batch[b];
    float4 v = *(const float4*)(g_CE + (size_t)id*128 + tid*4);
    *(float4*)(g_SELF + (size_t)b*128 + tid*4) = v;
}

// ---------------- stage B1: dense per-node seq-LSTM input projection ----------------
// grid (391, 4); block 256 thr; tile 128 rows x 128 cols
__global__ __launch_bounds__(256) void ig_kernel(int t)
{
    extern __shared__ float sm[];
    float* As = sm;            // [128][132]
    float* Ws = sm + 128*132;  // [32][132]

    int nt = blockIdx.y;       // 0..3 : 128-col chunk of 512
    int m0 = blockIdx.x*128;
    int tid = threadIdx.x;

    {   // load 128x128 CE tile transposed, clamp tail rows
        int rl = tid >> 5, c4 = tid & 31;
        for (int it=0; it<16; it++) {
            int r = rl + it*8;
            int row = m0 + r; if (row >= N_NODES) row = N_NODES-1;
            float4 v = *(const float4*)(g_CE + (size_t)row*128 + c4*4);
            As[(c4*4+0)*132 + r] = v.x;
            As[(c4*4+1)*132 + r] = v.y;
            As[(c4*4+2)*132 + r] = v.z;
            As[(c4*4+3)*132 + r] = v.w;
        }
    }

    float acc[8][8];
    #pragma unroll
    for (int i=0;i<8;i++)
        #pragma unroll
        for (int jj=0;jj<8;jj++) acc[i][jj]=0.f;

    int tx = tid & 15, ty = tid >> 4;
    const float* W2t = g_W2 + (size_t)t*128*512 + nt*128;

    for (int kc=0; kc<4; kc++) {
        __syncthreads();
        for (int it=0; it<4; it++) {     // 32x32 float4 = 1024
            int idx = tid + it*256;
            int kk = idx / 32, c4 = idx % 32;
            float4 v = *(const float4*)(W2t + (size_t)(kc*32+kk)*512 + c4*4);
            *(float4*)&Ws[kk*132 + c4*4] = v;
        }
        __syncthreads();
        #pragma unroll 2
        for (int kk=0; kk<32; kk++) {
            float4 a0 = *(float4*)&As[(kc*32+kk)*132 + ty*8];
            float4 a1 = *(float4*)&As[(kc*32+kk)*132 + ty*8 + 4];
            float4 w0 = *(float4*)&Ws[kk*132 + tx*8];
            float4 w1 = *(float4*)&Ws[kk*132 + tx*8 + 4];
            float av[8] = {a0.x,a0.y,a0.z,a0.w,a1.x,a1.y,a1.z,a1.w};
            float wv[8] = {w0.x,w0.y,w0.z,w0.w,w1.x,w1.y,w1.z,w1.w};
            #pragma unroll
            for (int i=0;i<8;i++)
                #pragma unroll
                for (int jj=0;jj<8;jj++)
                    acc[i][jj] += av[i]*wv[jj];
        }
    }

    const float* B2t = g_B2 + t*512 + nt*128;
    float b[8];
    #pragma unroll
    for (int jj=0;jj<8;jj++) b[jj] = B2t[tx*8+jj];
    #pragma unroll
    for (int i=0;i<8;i++) {
        int m = m0 + ty*8 + i;
        if (m < N_NODES) {
            float4 v0, v1;
            v0.x = acc[i][0]+b[0]; v0.y = acc[i][1]+b[1];
            v0.z = acc[i][2]+b[2]; v0.w = acc[i][3]+b[3];
            v1.x = acc[i][4]+b[4]; v1.y = acc[i][5]+b[5];
            v1.z = acc[i][6]+b[6]; v1.w = acc[i][7]+b[7];
            *(float4*)(g_IG + (size_t)m*512 + nt*128 + tx*8)     = v0;
            *(float4*)(g_IG + (size_t)m*512 + nt*128 + tx*8 + 4) = v1;
        }
    }
}

// ---------------- stage B2: LSTM recurrence over K=10 (gathers IG by node id) ----------------
// grid (256, 2); block 256 thr, 64 batch rows; Whh in smem; h double-buffered transposed
__global__ __launch_bounds__(256) void recur_kernel(const int* __restrict__ neigh_ids, int t)
{
    extern __shared__ float sm[];
    float* Whh_s = sm;             // [64][260]
    float* hT0 = sm + 64*260;      // [64][68]
    float* hT1 = hT0 + 64*68;
    int*   ids_s = (int*)(hT1 + 64*68);  // [64][10]

    int dir = blockIdx.y;
    int b0 = blockIdx.x*64;
    int tid = threadIdx.x;
    int tx = tid & 15, ty = tid >> 4;

    const float* Wsrc = g_Whh + ((size_t)t*2 + dir)*64*256;
    for (int it=0; it<16; it++) {        // 64x64 float4 = 4096
        int idx = tid + it*256;
        int hh = idx / 64, c4 = idx % 64;
        float4 v = *(const float4*)(Wsrc + (size_t)hh*256 + c4*4);
        *(float4*)&Whh_s[hh*260 + c4*4] = v;
    }
    for (int idx = tid; idx < 64*68; idx += 256) hT0[idx] = 0.f;
    {   // stage neighbor ids for this block's 64 rows
        const int* nsrc = neigh_ids + ((size_t)t*B_ + b0)*K_;
        for (int idx = tid; idx < 64*K_; idx += 256) ids_s[idx] = nsrc[idx];
    }
    __syncthreads();

    float c[4][4], hs[4][4];
    #pragma unroll
    for (int i=0;i<4;i++)
        #pragma unroll
        for (int jj=0;jj<4;jj++){ c[i][jj]=0.f; hs[i][jj]=0.f; }

    float* cur = hT0; float* nxt = hT1;

    for (int step=0; step<K_; step++) {
        int k = dir ? (K_-1-step) : step;
        float acc[4][4][4];    // [row][gate][jj]
        #pragma unroll
        for (int i=0;i<4;i++) {
            int id = ids_s[(ty*4+i)*K_ + k];
            const float* igrow = g_IG + (size_t)id*512 + dir*256;
            #pragma unroll
            for (int g=0; g<4; g++) {
                float4 v = *(const float4*)(igrow + g*64 + tx*4);
                acc[i][g][0]=v.x; acc[i][g][1]=v.y; acc[i][g][2]=v.z; acc[i][g][3]=v.w;
            }
        }
        #pragma unroll 4
        for (int hh=0; hh<64; hh++) {
            float4 a  = *(float4*)&cur[hh*68 + ty*4];
            float4 w0 = *(float4*)&Whh_s[hh*260 +   0 + tx*4];
            float4 w1 = *(float4*)&Whh_s[hh*260 +  64 + tx*4];
            float4 w2 = *(float4*)&Whh_s[hh*260 + 128 + tx*4];
            float4 w3 = *(float4*)&Whh_s[hh*260 + 192 + tx*4];
            float av[4] = {a.x,a.y,a.z,a.w};
            float wv[4][4] = {{w0.x,w0.y,w0.z,w0.w},{w1.x,w1.y,w1.z,w1.w},
                              {w2.x,w2.y,w2.z,w2.w},{w3.x,w3.y,w3.z,w3.w}};
            #pragma unroll
            for (int i=0;i<4;i++)
                #pragma unroll
                for (int g=0;g<4;g++)
                    #pragma unroll
                    for (int jj=0;jj<4;jj++)
                        acc[i][g][jj] += av[i]*wv[g][jj];
        }
        #pragma unroll
        for (int i=0;i<4;i++)
            #pragma unroll
            for (int jj=0;jj<4;jj++) {
                float ii = sigmoid_f(acc[i][0][jj]);
                float ff = sigmoid_f(acc[i][1][jj]);
                float gg = tanh_f   (acc[i][2][jj]);
                float oo = sigmoid_f(acc[i][3][jj]);
                c[i][jj] = ff*c[i][jj] + ii*gg;
                float h = oo*tanh_f(c[i][jj]);
                hs[i][jj] += h;
                nxt[(tx*4+jj)*68 + ty*4 + i] = h;
            }
        __syncthreads();
        float* tmp = cur; cur = nxt; nxt = tmp;
    }

    #pragma unroll
    for (int i=0;i<4;i++) {
        int b = b0 + ty*4 + i;
        #pragma unroll
        for (int jj=0;jj<4;jj++)
            g_AGG[((size_t)t*B_ + b)*128 + dir*64 + tx*4 + jj] = hs[i][jj] * (1.0f/K_);
    }
}

// ---------------- stage C: attention combine ----------------
__global__ __launch_bounds__(256) void attn_kernel(const float* __restrict__ att,
                                                   float* __restrict__ out)
{
    int warp = threadIdx.x >> 5;
    int lane = threadIdx.x & 31;
    int b = blockIdx.x*8 + warp;

    float e[12][4], a0[4], a1[4];
    #pragma unroll
    for (int i=0;i<4;i++) {
        int d = i*32 + lane;
        a0[i] = att[d];
        a1[i] = att[128+d];
        e[0][i] = g_SELF[(size_t)b*128 + d];
    }
    #pragma unroll
    for (int t=0;t<T_;t++)
        #pragma unroll
        for (int i=0;i<4;i++)
            e[1+t][i] = g_AGG[((size_t)t*B_ + b)*128 + i*32 + lane];

    float pself = 0.f;
    #pragma unroll
    for (int i=0;i<4;i++) pself += e[0][i]*a0[i];
    float sc[12];
    #pragma unroll
    for (int j=0;j<12;j++) {
        float p = 0.f;
        #pragma unroll
        for (int i=0;i<4;i++) p += e[j][i]*a1[i];
        sc[j] = p;
    }
    #pragma unroll
    for (int off=16; off>0; off>>=1) {
        pself += __shfl_xor_sync(0xffffffff, pself, off);
        #pragma unroll
        for (int j=0;j<12;j++) sc[j] += __shfl_xor_sync(0xffffffff, sc[j], off);
    }
    float mx = -1e30f;
    #pragma unroll
    for (int j=0;j<12;j++) {
        float s = pself + sc[j];
        s = (s > 0.f) ? s : 0.01f*s;    // leaky_relu(0.01)
        sc[j] = s;
        mx = fmaxf(mx, s);
    }
    float sum = 0.f;
    #pragma unroll
    for (int j=0;j<12;j++) { sc[j] = expf(sc[j]-mx); sum += sc[j]; }
    float inv = 1.f/sum;
    #pragma unroll
    for (int i=0;i<4;i++) {
        float o = 0.f;
        #pragma unroll
        for (int j=0;j<12;j++) o += sc[j]*e[j][i];
        out[(size_t)b*128 + i*32 + lane] = o*inv;
    }
}

// ---------------- launch ----------------
extern "C" void kernel_launch(void* const* d_in, const int* in_sizes, int n_in,
                              void* d_out, int out_size)
{
    const float* features = (const float*)d_in[0];
    const int*   id_batch = (const int*)d_in[1];
    const int*   neigh_ids= (const int*)d_in[2];
    const float* cWih_f   = (const float*)d_in[3];
    // d_in[4] = cWhh_f : unused (zero-state content LSTM)
    const float* cb_f     = (const float*)d_in[5];
    const float* cWih_b   = (const float*)d_in[6];
    // d_in[7] = cWhh_b : unused
    const float* cb_b     = (const float*)d_in[8];
    const float* nWih_f   = (const float*)d_in[9];
    const float* nWhh_f   = (const float*)d_in[10];
    const float* nb_f     = (const float*)d_in[11];
    const float* nWih_b   = (const float*)d_in[12];
    const float* nWhh_b   = (const float*)d_in[13];
    const float* nb_b     = (const float*)d_in[14];
    const float* att      = (const float*)d_in[15];
    float* out = (float*)d_out;

    const int SMEM_CONTENT = (128*132 + 32*196) * 4;            // 92672
    const int SMEM_IG      = (128*132 + 32*132) * 4;            // 84480
    const int SMEM_RECUR   = (64*260 + 2*64*68 + 64*K_) * 4;    // 103936
    cudaFuncSetAttribute(content_kernel, cudaFuncAttributeMaxDynamicSharedMemorySize, SMEM_CONTENT);
    cudaFuncSetAttribute(ig_kernel,      cudaFuncAttributeMaxDynamicSharedMemorySize, SMEM_IG);
    cudaFuncSetAttribute(recur_kernel,   cudaFuncAttributeMaxDynamicSharedMemorySize, SMEM_RECUR);

    pack_kernel<<<512, 256>>>(cWih_f, cb_f, cWih_b, cb_b,
                              nWih_f, nb_f, nWih_b, nb_b, nWhh_f, nWhh_b);

    for (int t = 0; t < T_; t++) {
        dim3 gc(NROW_BLKS, 2);
        content_kernel<<<gc, 256, SMEM_CONTENT>>>(features, t);
        if (t == 0)
            self_gather_kernel<<<B_, 32>>>(id_batch);   // c_self = CE0[id_batch]
        dim3 gi(NROW_BLKS, 4);
        ig_kernel<<<gi, 256, SMEM_IG>>>(t);
        dim3 gr(B_/64, 2);
        recur_kernel<<<gr, 256, SMEM_RECUR>>>(neigh_ids, t);
    }

    attn_kernel<<<B_/8, 256>>>(att, out);
}

// round 7
// speedup vs baseline: 3.4804x; 1.5009x over previous
#include <cuda_runtime.h>
#include <stdint.h>
#include <stddef.h>
#include <math.h>

#define T_ 11
#define N_NODES 50000
#define D_ 128
#define H_ 64
#define B_ 16384
#define K_ 10
#define NROW_BLKS 391    // ceil(50000/128)

// ---------------- scratch (device globals; ~250 MB total) ----------------
__device__ float g_W1[(size_t)T_*128*384];     // packed content Wih (gates i,g,o x 2 dirs), [t][kk][384], tf32-rounded
__device__ float g_B1[T_*384];
__device__ float g_W2[(size_t)T_*128*512];     // packed seq Wih (4 gates x 2 dirs), [t][kk][512], tf32-rounded
__device__ float g_B2[T_*512];
__device__ float g_Whh[(size_t)T_*2*64*256];   // [t][dir][hh][n] transposed recurrent weights (fp32)
__device__ float g_CE[(size_t)N_NODES*128];    // per-node content encodings, ONE type (25.6 MB)
__device__ float g_IG[(size_t)N_NODES*512];    // per-node seq-LSTM input preacts, ONE type (102 MB)
__device__ float g_SELF[(size_t)B_*128];
__device__ float g_AGG[(size_t)T_*B_*128];

__device__ __forceinline__ float sigmoid_f(float x){
    return __fdividef(1.0f, 1.0f + __expf(-x));
}
__device__ __forceinline__ float tanh_f(float x){
    return 1.0f - __fdividef(2.0f, 1.0f + __expf(2.0f*x));
}
__device__ __forceinline__ float f2tf32(float x){
    uint32_t r;
    asm("cvt.rna.tf32.f32 %0, %1;" : "=r"(r) : "f"(x));
    return __uint_as_float(r);
}
__device__ __forceinline__ void mma_tf32(float& c0, float& c1, float& c2, float& c3,
                                         uint32_t a0, uint32_t a1, uint32_t a2, uint32_t a3,
                                         uint32_t b0, uint32_t b1){
    asm volatile("mma.sync.aligned.m16n8k8.row.col.f32.tf32.tf32.f32 "
                 "{%0,%1,%2,%3},{%4,%5,%6,%7},{%8,%9},{%0,%1,%2,%3};"
                 : "+f"(c0), "+f"(c1), "+f"(c2), "+f"(c3)
                 : "r"(a0), "r"(a1), "r"(a2), "r"(a3), "r"(b0), "r"(b1));
}

// ---------------- weight packing (weights tf32-rounded for mma; biases fp32) ----------------
__global__ void pack_kernel(const float* __restrict__ cWih_f, const float* __restrict__ cb_f,
                            const float* __restrict__ cWih_b, const float* __restrict__ cb_b,
                            const float* __restrict__ nWih_f, const float* __restrict__ nb_f,
                            const float* __restrict__ nWih_b, const float* __restrict__ nb_b,
                            const float* __restrict__ nWhh_f, const float* __restrict__ nWhh_b)
{
    int stride = gridDim.x*blockDim.x;
    int tid0 = blockIdx.x*blockDim.x + threadIdx.x;

    // W1: [t][kk][n], n = dir*192 + gate*64 + j, gate 0:i 1:g 2:o (f-gate dead: zero state)
    for (size_t idx = tid0; idx < (size_t)T_*128*384; idx += stride) {
        int n = (int)(idx % 384); size_t rest = idx / 384;
        int kk = (int)(rest % 128); int t = (int)(rest / 128);
        int dir = n/192, rem = n%192, g = rem/64, j = rem%64;
        int row = (g==0) ? j : (g==1) ? 128+j : 192+j;
        const float* W = dir ? cWih_b : cWih_f;
        g_W1[idx] = f2tf32(W[((size_t)t*256 + row)*128 + kk]);
    }
    for (int idx = tid0; idx < T_*384; idx += stride) {
        int n = idx % 384; int t = idx / 384;
        int dir = n/192, rem = n%192, g = rem/64, j = rem%64;
        int row = (g==0) ? j : (g==1) ? 128+j : 192+j;
        g_B1[idx] = (dir ? cb_b : cb_f)[t*256 + row];
    }
    // W2: [t][kk][n], n = dir*256 + r  (natural gate rows i,f,g,o)
    for (size_t idx = tid0; idx < (size_t)T_*128*512; idx += stride) {
        int n = (int)(idx % 512); size_t rest = idx/512;
        int kk = (int)(rest % 128); int t = (int)(rest/128);
        int dir = n/256, r = n%256;
        const float* W = dir ? nWih_b : nWih_f;
        g_W2[idx] = f2tf32(W[((size_t)t*256 + r)*128 + kk]);
    }
    for (int idx = tid0; idx < T_*512; idx += stride) {
        int n = idx % 512; int t = idx/512;
        int dir = n/256, r = n%256;
        g_B2[idx] = (dir ? nb_b : nb_f)[t*256 + r];
    }
    // Whh transposed: [t][dir][hh][n]  (fp32 for SIMT recurrence)
    for (size_t idx = tid0; idx < (size_t)T_*2*64*256; idx += stride) {
        int n = (int)(idx % 256); size_t rest = idx/256;
        int hh = (int)(rest % 64); rest /= 64;
        int dir = (int)(rest % 2); int t = (int)(rest/2);
        const float* W = dir ? nWhh_b : nWhh_f;
        g_Whh[idx] = W[((size_t)t*256 + n)*64 + hh];
    }
}

// ---------------- stage A: dense per-node content encode (tf32 tensor cores) ----------------
// grid (391, 2 dirs); block 256 (8 warps); block tile 128(M) x 192(N: 3 gates x 64)
// warp tile: 64 rows x 16 j-cols x 3 gates  (thread holds i/g/o for the same (row,j))
__global__ __launch_bounds__(256) void content_kernel(
    const float* __restrict__ features, int t)
{
    extern __shared__ float sm[];
    float* As  = sm;             // [128][132]  row-major, tf32-rounded
    float* W1s = sm + 128*132;   // [32][200]   k-chunk of weights (192 cols + pad)

    const float* feat = features + (size_t)t*N_NODES*128;
    int dir = blockIdx.y;
    int m0 = blockIdx.x*128;
    int tid = threadIdx.x;
    int warp = tid >> 5, lane = tid & 31;
    int wm = warp >> 2;          // 0..1 : 64-row half
    int wj = warp & 3;           // 0..3 : 16-j slice
    int lr = lane >> 2;          // 0..7
    int lc = lane & 3;           // 0..3

    {   // stage A row-major with tf32 rounding; clamp tail rows
        int rl = tid >> 5, c4 = tid & 31;
        #pragma unroll
        for (int it = 0; it < 16; it++) {
            int r = rl + it*8;
            int row = m0 + r; if (row >= N_NODES) row = N_NODES-1;
            float4 v = *(const float4*)(feat + (size_t)row*128 + c4*4);
            float4 o; o.x=f2tf32(v.x); o.y=f2tf32(v.y); o.z=f2tf32(v.z); o.w=f2tf32(v.w);
            *(float4*)&As[r*132 + c4*4] = o;
        }
    }

    float acc[4][3][2][4];   // [mtile][gate][jtile][c-regs]
    #pragma unroll
    for (int mt=0;mt<4;mt++)
        #pragma unroll
        for (int g=0;g<3;g++)
            #pragma unroll
            for (int jt=0;jt<2;jt++)
                #pragma unroll
                for (int r=0;r<4;r++) acc[mt][g][jt][r]=0.f;

    const float* W1t = g_W1 + (size_t)t*128*384 + dir*192;

    for (int kc = 0; kc < 4; kc++) {
        __syncthreads();
        for (int it = 0; it < 6; it++) {          // 32x48 float4 = 1536
            int idx = tid + it*256;
            int kk = idx / 48, c4 = idx % 48;
            float4 v = *(const float4*)(W1t + (size_t)(kc*32+kk)*384 + c4*4);
            *(float4*)&W1s[kk*200 + c4*4] = v;    // already tf32-rounded in pack
        }
        __syncthreads();
        #pragma unroll
        for (int k8 = 0; k8 < 4; k8++) {
            int kb = k8*8;
            uint32_t a[4][4];
            #pragma unroll
            for (int mt=0; mt<4; mt++) {
                const float* Ab = As + (wm*64 + mt*16)*132 + kc*32 + kb;
                a[mt][0] = __float_as_uint(Ab[lr*132 + lc]);
                a[mt][1] = __float_as_uint(Ab[(lr+8)*132 + lc]);
                a[mt][2] = __float_as_uint(Ab[lr*132 + lc+4]);
                a[mt][3] = __float_as_uint(Ab[(lr+8)*132 + lc+4]);
            }
            uint32_t b[3][2][2];
            #pragma unroll
            for (int g=0; g<3; g++)
                #pragma unroll
                for (int jt=0; jt<2; jt++) {
                    const float* Bb = W1s + kb*200 + g*64 + wj*16 + jt*8;
                    b[g][jt][0] = __float_as_uint(Bb[lc*200 + lr]);
                    b[g][jt][1] = __float_as_uint(Bb[(lc+4)*200 + lr]);
                }
            #pragma unroll
            for (int mt=0; mt<4; mt++)
                #pragma unroll
                for (int g=0; g<3; g++)
                    #pragma unroll
                    for (int jt=0; jt<2; jt++)
                        mma_tf32(acc[mt][g][jt][0], acc[mt][g][jt][1],
                                 acc[mt][g][jt][2], acc[mt][g][jt][3],
                                 a[mt][0], a[mt][1], a[mt][2], a[mt][3],
                                 b[g][jt][0], b[g][jt][1]);
        }
    }

    // epilogue: bias + LSTM nonlinearity, store CE
    const float* B1t = g_B1 + t*384 + dir*192;
    #pragma unroll
    for (int mt=0; mt<4; mt++) {
        #pragma unroll
        for (int jt=0; jt<2; jt++) {
            int j = wj*16 + jt*8 + lc*2;
            float bi0 = B1t[j],     bi1 = B1t[j+1];
            float bg0 = B1t[64+j],  bg1 = B1t[64+j+1];
            float bo0 = B1t[128+j], bo1 = B1t[128+j+1];
            int r0 = m0 + wm*64 + mt*16 + lr;
            int r1 = r0 + 8;
            // rows r0: regs 0,1; rows r1: regs 2,3
            if (r0 < N_NODES) {
                float cc0 = sigmoid_f(acc[mt][0][jt][0]+bi0) * tanh_f(acc[mt][1][jt][0]+bg0);
                float cc1 = sigmoid_f(acc[mt][0][jt][1]+bi1) * tanh_f(acc[mt][1][jt][1]+bg1);
                float2 v;
                v.x = sigmoid_f(acc[mt][2][jt][0]+bo0) * tanh_f(cc0);
                v.y = sigmoid_f(acc[mt][2][jt][1]+bo1) * tanh_f(cc1);
                *(float2*)(g_CE + (size_t)r0*128 + dir*64 + j) = v;
            }
            if (r1 < N_NODES) {
                float cc0 = sigmoid_f(acc[mt][0][jt][2]+bi0) * tanh_f(acc[mt][1][jt][2]+bg0);
                float cc1 = sigmoid_f(acc[mt][0][jt][3]+bi1) * tanh_f(acc[mt][1][jt][3]+bg1);
                float2 v;
                v.x = sigmoid_f(acc[mt][2][jt][2]+bo0) * tanh_f(cc0);
                v.y = sigmoid_f(acc[mt][2][jt][3]+bo1) * tanh_f(cc1);
                *(float2*)(g_CE + (size_t)r1*128 + dir*64 + j) = v;
            }
        }
    }
}

// ---------------- self embed: gather type-0 CE rows ----------------
__global__ void self_gather_kernel(const int* __restrict__ id_batch)
{
    int b = blockIdx.x;
    int tid = threadIdx.x;                 // 32 threads, one float4 each
    int id = id_batch[b];
    float4 v = *(const float4*)(g_CE + (size_t)id*128 + tid*4);
    *(float4*)(g_SELF + (size_t)b*128 + tid*4) = v;
}

// ---------------- stage B1: dense per-node seq-LSTM input projection (tf32 tensor cores) ----------------
// grid (391, 4); block 256 (8 warps); block tile 128(M) x 128(N); warp tile 64 x 32
__global__ __launch_bounds__(256) void ig_kernel(int t)
{
    extern __shared__ float sm[];
    float* As = sm;             // [128][132]  row-major, tf32-rounded
    float* Ws = sm + 128*132;   // [32][136]   k-chunk of weights

    int nt = blockIdx.y;        // 0..3 : 128-col chunk of 512
    int m0 = blockIdx.x*128;
    int tid = threadIdx.x;
    int warp = tid >> 5, lane = tid & 31;
    int wm = warp >> 2;         // 0..1
    int wn = warp & 3;          // 0..3 : 32-col slice
    int lr = lane >> 2;
    int lc = lane & 3;

    {   // stage CE tile row-major with tf32 rounding
        int rl = tid >> 5, c4 = tid & 31;
        #pragma unroll
        for (int it=0; it<16; it++) {
            int r = rl + it*8;
            int row = m0 + r; if (row >= N_NODES) row = N_NODES-1;
            float4 v = *(const float4*)(g_CE + (size_t)row*128 + c4*4);
            float4 o; o.x=f2tf32(v.x); o.y=f2tf32(v.y); o.z=f2tf32(v.z); o.w=f2tf32(v.w);
            *(float4*)&As[r*132 + c4*4] = o;
        }
    }

    float acc[4][4][4];   // [mtile][ntile][c-regs]
    #pragma unroll
    for (int mt=0;mt<4;mt++)
        #pragma unroll
        for (int n8=0;n8<4;n8++)
            #pragma unroll
            for (int r=0;r<4;r++) acc[mt][n8][r]=0.f;

    const float* W2t = g_W2 + (size_t)t*128*512 + nt*128;

    for (int kc=0; kc<4; kc++) {
        __syncthreads();
        for (int it=0; it<4; it++) {     // 32x32 float4 = 1024
            int idx = tid + it*256;
            int kk = idx >> 5, c4 = idx & 31;
            float4 v = *(const float4*)(W2t + (size_t)(kc*32+kk)*512 + c4*4);
            *(float4*)&Ws[kk*136 + c4*4] = v;    // already tf32-rounded
        }
        __syncthreads();
        #pragma unroll
        for (int k8=0; k8<4; k8++) {
            int kb = k8*8;
            uint32_t a[4][4];
            #pragma unroll
            for (int mt=0; mt<4; mt++) {
                const float* Ab = As + (wm*64 + mt*16)*132 + kc*32 + kb;
                a[mt][0] = __float_as_uint(Ab[lr*132 + lc]);
                a[mt][1] = __float_as_uint(Ab[(lr+8)*132 + lc]);
                a[mt][2] = __float_as_uint(Ab[lr*132 + lc+4]);
                a[mt][3] = __float_as_uint(Ab[(lr+8)*132 + lc+4]);
            }
            uint32_t b[4][2];
            #pragma unroll
            for (int n8=0; n8<4; n8++) {
                const float* Bb = Ws + kb*136 + wn*32 + n8*8;
                b[n8][0] = __float_as_uint(Bb[lc*136 + lr]);
                b[n8][1] = __float_as_uint(Bb[(lc+4)*136 + lr]);
            }
            #pragma unroll
            for (int mt=0; mt<4; mt++)
                #pragma unroll
                for (int n8=0; n8<4; n8++)
                    mma_tf32(acc[mt][n8][0], acc[mt][n8][1], acc[mt][n8][2], acc[mt][n8][3],
                             a[mt][0], a[mt][1], a[mt][2], a[mt][3],
                             b[n8][0], b[n8][1]);
        }
    }

    const float* B2t = g_B2 + t*512;
    #pragma unroll
    for (int mt=0; mt<4; mt++) {
        #pragma unroll
        for (int n8=0; n8<4; n8++) {
            int ncol = nt*128 + wn*32 + n8*8 + lc*2;
            float b0 = B2t[ncol], b1 = B2t[ncol+1];
            int r0 = m0 + wm*64 + mt*16 + lr;
            int r1 = r0 + 8;
            if (r0 < N_NODES) {
                float2 v; v.x = acc[mt][n8][0]+b0; v.y = acc[mt][n8][1]+b1;
                *(float2*)(g_IG + (size_t)r0*512 + ncol) = v;
            }
            if (r1 < N_NODES) {
                float2 v; v.x = acc[mt][n8][2]+b0; v.y = acc[mt][n8][3]+b1;
                *(float2*)(g_IG + (size_t)r1*512 + ncol) = v;
            }
        }
    }
}

// ---------------- stage B2: LSTM recurrence over K=10 (gathers IG by node id, prefetched) ----------------
// grid (256, 2); block 256 thr, 64 batch rows; Whh in smem; h double-buffered transposed
__global__ __launch_bounds__(256) void recur_kernel(const int* __restrict__ neigh_ids, int t)
{
    extern __shared__ float sm[];
    float* Whh_s = sm;             // [64][260]
    float* hT0 = sm + 64*260;      // [64][68]
    float* hT1 = hT0 + 64*68;
    int*   ids_s = (int*)(hT1 + 64*68);  // [64][10]

    int dir = blockIdx.y;
    int b0 = blockIdx.x*64;
    int tid = threadIdx.x;
    int tx = tid & 15, ty = tid >> 4;

    const float* Wsrc = g_Whh + ((size_t)t*2 + dir)*64*256;
    for (int it=0; it<16; it++) {        // 64x64 float4 = 4096
        int idx = tid + it*256;
        int hh = idx / 64, c4 = idx % 64;
        float4 v = *(const float4*)(Wsrc + (size_t)hh*256 + c4*4);
        *(float4*)&Whh_s[hh*260 + c4*4] = v;
    }
    for (int idx = tid; idx < 64*68; idx += 256) hT0[idx] = 0.f;
    {   // stage neighbor ids for this block's 64 rows
        const int* nsrc = neigh_ids + ((size_t)t*B_ + b0)*K_;
        for (int idx = tid; idx < 64*K_; idx += 256) ids_s[idx] = nsrc[idx];
    }
    __syncthreads();

    float c[4][4], hs[4][4];
    #pragma unroll
    for (int i=0;i<4;i++)
        #pragma unroll
        for (int jj=0;jj<4;jj++){ c[i][jj]=0.f; hs[i][jj]=0.f; }

    float* cur = hT0; float* nxt = hT1;

    // prefetch step 0
    float4 pre[16];
    {
        int k0 = dir ? (K_-1) : 0;
        #pragma unroll
        for (int i=0;i<4;i++) {
            int id = ids_s[(ty*4+i)*K_ + k0];
            const float* igrow = g_IG + (size_t)id*512 + dir*256;
            #pragma unroll
            for (int g=0; g<4; g++)
                pre[i*4+g] = *(const float4*)(igrow + g*64 + tx*4);
        }
    }

    for (int step=0; step<K_; step++) {
        float acc[4][4][4];    // [row][gate][jj]
        #pragma unroll
        for (int i=0;i<4;i++)
            #pragma unroll
            for (int g=0; g<4; g++) {
                float4 v = pre[i*4+g];
                acc[i][g][0]=v.x; acc[i][g][1]=v.y; acc[i][g][2]=v.z; acc[i][g][3]=v.w;
            }
        if (step+1 < K_) {     // prefetch next step's gather; consumed next iteration
            int kn = dir ? (K_-2-step) : (step+1);
            #pragma unroll
            for (int i=0;i<4;i++) {
                int id = ids_s[(ty*4+i)*K_ + kn];
                const float* igrow = g_IG + (size_t)id*512 + dir*256;
                #pragma unroll
                for (int g=0; g<4; g++)
                    pre[i*4+g] = *(const float4*)(igrow + g*64 + tx*4);
            }
        }
        #pragma unroll 4
        for (int hh=0; hh<64; hh++) {
            float4 a  = *(float4*)&cur[hh*68 + ty*4];
            float4 w0 = *(float4*)&Whh_s[hh*260 +   0 + tx*4];
            float4 w1 = *(float4*)&Whh_s[hh*260 +  64 + tx*4];
            float4 w2 = *(float4*)&Whh_s[hh*260 + 128 + tx*4];
            float4 w3 = *(float4*)&Whh_s[hh*260 + 192 + tx*4];
            float av[4] = {a.x,a.y,a.z,a.w};
            float wv[4][4] = {{w0.x,w0.y,w0.z,w0.w},{w1.x,w1.y,w1.z,w1.w},
                              {w2.x,w2.y,w2.z,w2.w},{w3.x,w3.y,w3.z,w3.w}};
            #pragma unroll
            for (int i=0;i<4;i++)
                #pragma unroll
                for (int g=0;g<4;g++)
                    #pragma unroll
                    for (int jj=0;jj<4;jj++)
                        acc[i][g][jj] += av[i]*wv[g][jj];
        }
        #pragma unroll
        for (int i=0;i<4;i++)
            #pragma unroll
            for (int jj=0;jj<4;jj++) {
                float ii = sigmoid_f(acc[i][0][jj]);
                float ff = sigmoid_f(acc[i][1][jj]);
                float gg = tanh_f   (acc[i][2][jj]);
                float oo = sigmoid_f(acc[i][3][jj]);
                c[i][jj] = ff*c[i][jj] + ii*gg;
                float h = oo*tanh_f(c[i][jj]);
                hs[i][jj] += h;
                nxt[(tx*4+jj)*68 + ty*4 + i] = h;
            }
        __syncthreads();
        float* tmp = cur; cur = nxt; nxt = tmp;
    }

    #pragma unroll
    for (int i=0;i<4;i++) {
        int b = b0 + ty*4 + i;
        #pragma unroll
        for (int jj=0;jj<4;jj++)
            g_AGG[((size_t)t*B_ + b)*128 + dir*64 + tx*4 + jj] = hs[i][jj] * (1.0f/K_);
    }
}

// ---------------- stage C: attention combine ----------------
__global__ __launch_bounds__(256) void attn_kernel(const float* __restrict__ att,
                                                   float* __restrict__ out)
{
    int warp = threadIdx.x >> 5;
    int lane = threadIdx.x & 31;
    int b = blockIdx.x*8 + warp;

    float e[12][4], a0[4], a1[4];
    #pragma unroll
    for (int i=0;i<4;i++) {
        int d = i*32 + lane;
        a0[i] = att[d];
        a1[i] = att[128+d];
        e[0][i] = g_SELF[(size_t)b*128 + d];
    }
    #pragma unroll
    for (int t=0;t<T_;t++)
        #pragma unroll
        for (int i=0;i<4;i++)
            e[1+t][i] = g_AGG[((size_t)t*B_ + b)*128 + i*32 + lane];

    float pself = 0.f;
    #pragma unroll
    for (int i=0;i<4;i++) pself += e[0][i]*a0[i];
    float sc[12];
    #pragma unroll
    for (int j=0;j<12;j++) {
        float p = 0.f;
        #pragma unroll
        for (int i=0;i<4;i++) p += e[j][i]*a1[i];
        sc[j] = p;
    }
    #pragma unroll
    for (int off=16; off>0; off>>=1) {
        pself += __shfl_xor_sync(0xffffffff, pself, off);
        #pragma unroll
        for (int j=0;j<12;j++) sc[j] += __shfl_xor_sync(0xffffffff, sc[j], off);
    }
    float mx = -1e30f;
    #pragma unroll
    for (int j=0;j<12;j++) {
        float s = pself + sc[j];
        s = (s > 0.f) ? s : 0.01f*s;    // leaky_relu(0.01)
        sc[j] = s;
        mx = fmaxf(mx, s);
    }
    float sum = 0.f;
    #pragma unroll
    for (int j=0;j<12;j++) { sc[j] = expf(sc[j]-mx); sum += sc[j]; }
    float inv = 1.f/sum;
    #pragma unroll
    for (int i=0;i<4;i++) {
        float o = 0.f;
        #pragma unroll
        for (int j=0;j<12;j++) o += sc[j]*e[j][i];
        out[(size_t)b*128 + i*32 + lane] = o*inv;
    }
}

// ---------------- launch ----------------
extern "C" void kernel_launch(void* const* d_in, const int* in_sizes, int n_in,
                              void* d_out, int out_size)
{
    const float* features = (const float*)d_in[0];
    const int*   id_batch = (const int*)d_in[1];
    const int*   neigh_ids= (const int*)d_in[2];
    const float* cWih_f   = (const float*)d_in[3];
    // d_in[4] = cWhh_f : unused (zero-state content LSTM)
    const float* cb_f     = (const float*)d_in[5];
    const float* cWih_b   = (const float*)d_in[6];
    // d_in[7] = cWhh_b : unused
    const float* cb_b     = (const float*)d_in[8];
    const float* nWih_f   = (const float*)d_in[9];
    const float* nWhh_f   = (const float*)d_in[10];
    const float* nb_f     = (const float*)d_in[11];
    const float* nWih_b   = (const float*)d_in[12];
    const float* nWhh_b   = (const float*)d_in[13];
    const float* nb_b     = (const float*)d_in[14];
    const float* att      = (const float*)d_in[15];
    float* out = (float*)d_out;

    const int SMEM_CONTENT = (128*132 + 32*200) * 4;            // 93184
    const int SMEM_IG      = (128*132 + 32*136) * 4;            // 84992
    const int SMEM_RECUR   = (64*260 + 2*64*68 + 64*K_) * 4;    // 103936
    cudaFuncSetAttribute(content_kernel, cudaFuncAttributeMaxDynamicSharedMemorySize, SMEM_CONTENT);
    cudaFuncSetAttribute(ig_kernel,      cudaFuncAttributeMaxDynamicSharedMemorySize, SMEM_IG);
    cudaFuncSetAttribute(recur_kernel,   cudaFuncAttributeMaxDynamicSharedMemorySize, SMEM_RECUR);

    pack_kernel<<<512, 256>>>(cWih_f, cb_f, cWih_b, cb_b,
                              nWih_f, nb_f, nWih_b, nb_b, nWhh_f, nWhh_b);

    for (int t = 0; t < T_; t++) {
        dim3 gc(NROW_BLKS, 2);
        content_kernel<<<gc, 256, SMEM_CONTENT>>>(features, t);
        if (t == 0)
            self_gather_kernel<<<B_, 32>>>(id_batch);   // c_self = CE0[id_batch]
        dim3 gi(NROW_BLKS, 4);
        ig_kernel<<<gi, 256, SMEM_IG>>>(t);
        dim3 gr(B_/64, 2);
        recur_kernel<<<gr, 256, SMEM_RECUR>>>(neigh_ids, t);
    }

    attn_kernel<<<B_/8, 256>>>(att, out);
}

// round 10
// speedup vs baseline: 5.3045x; 1.5241x over previous
#include <cuda_runtime.h>
#include <stdint.h>
#include <stddef.h>
#include <math.h>

#define T_ 11
#define N_NODES 50000
#define D_ 128
#define H_ 64
#define B_ 16384
#define K_ 10
#define NROW_BLKS 391    // ceil(50000/128)

// ---------------- scratch (device globals; ~250 MB total) ----------------
__device__ float g_W1[(size_t)T_*128*384];     // packed content Wih (gates i,g,o x 2 dirs), tf32-rounded
__device__ float g_B1[T_*384];
__device__ float g_W2[(size_t)T_*128*512];     // packed seq Wih (4 gates x 2 dirs), tf32-rounded
__device__ float g_B2[T_*512];
__device__ float g_Whh[(size_t)T_*2*64*256];   // [t][dir][k=64][n=256] k-major mma-B layout, tf32-rounded
__device__ float g_CE[(size_t)N_NODES*128];    // per-node content encodings, ONE type
__device__ float g_IG[(size_t)N_NODES*512];    // per-node seq-LSTM preacts (incl. bias), ONE type
__device__ float g_SELF[(size_t)B_*128];
__device__ float g_AGG[(size_t)T_*B_*128];

__device__ __forceinline__ float sigmoid_f(float x){
    return __fdividef(1.0f, 1.0f + __expf(-x));
}
__device__ __forceinline__ float tanh_f(float x){
    return 1.0f - __fdividef(2.0f, 1.0f + __expf(2.0f*x));
}
__device__ __forceinline__ float f2tf32(float x){
    uint32_t r;
    asm("cvt.rna.tf32.f32 %0, %1;" : "=r"(r) : "f"(x));
    return __uint_as_float(r);
}
__device__ __forceinline__ void mma_tf32(float& c0, float& c1, float& c2, float& c3,
                                         uint32_t a0, uint32_t a1, uint32_t a2, uint32_t a3,
                                         uint32_t b0, uint32_t b1){
    asm volatile("mma.sync.aligned.m16n8k8.row.col.f32.tf32.tf32.f32 "
                 "{%0,%1,%2,%3},{%4,%5,%6,%7},{%8,%9},{%0,%1,%2,%3};"
                 : "+f"(c0), "+f"(c1), "+f"(c2), "+f"(c3)
                 : "r"(a0), "r"(a1), "r"(a2), "r"(a3), "r"(b0), "r"(b1));
}

// ---------------- weight packing ----------------
__global__ void pack_kernel(const float* __restrict__ cWih_f, const float* __restrict__ cb_f,
                            const float* __restrict__ cWih_b, const float* __restrict__ cb_b,
                            const float* __restrict__ nWih_f, const float* __restrict__ nb_f,
                            const float* __restrict__ nWih_b, const float* __restrict__ nb_b,
                            const float* __restrict__ nWhh_f, const float* __restrict__ nWhh_b)
{
    int stride = gridDim.x*blockDim.x;
    int tid0 = blockIdx.x*blockDim.x + threadIdx.x;

    // W1: [t][kk][n], n = dir*192 + gate*64 + j, gate 0:i 1:g 2:o (f-gate dead: zero state)
    for (size_t idx = tid0; idx < (size_t)T_*128*384; idx += stride) {
        int n = (int)(idx % 384); size_t rest = idx / 384;
        int kk = (int)(rest % 128); int t = (int)(rest / 128);
        int dir = n/192, rem = n%192, g = rem/64, j = rem%64;
        int row = (g==0) ? j : (g==1) ? 128+j : 192+j;
        const float* W = dir ? cWih_b : cWih_f;
        g_W1[idx] = f2tf32(W[((size_t)t*256 + row)*128 + kk]);
    }
    for (int idx = tid0; idx < T_*384; idx += stride) {
        int n = idx % 384; int t = idx / 384;
        int dir = n/192, rem = n%192, g = rem/64, j = rem%64;
        int row = (g==0) ? j : (g==1) ? 128+j : 192+j;
        g_B1[idx] = (dir ? cb_b : cb_f)[t*256 + row];
    }
    // W2: [t][kk][n], n = dir*256 + r  (natural gate rows i,f,g,o)
    for (size_t idx = tid0; idx < (size_t)T_*128*512; idx += stride) {
        int n = (int)(idx % 512); size_t rest = idx/512;
        int kk = (int)(rest % 128); int t = (int)(rest/128);
        int dir = n/256, r = n%256;
        const float* W = dir ? nWih_b : nWih_f;
        g_W2[idx] = f2tf32(W[((size_t)t*256 + r)*128 + kk]);
    }
    for (int idx = tid0; idx < T_*512; idx += stride) {
        int n = idx % 512; int t = idx/512;
        int dir = n/256, r = n%256;
        g_B2[idx] = (dir ? nb_b : nb_f)[t*256 + r];
    }
    // Whh mma-B layout: [t][dir][k][n], tf32-rounded (source nWhh[t][n=256][k=64])
    for (size_t idx = tid0; idx < (size_t)T_*2*64*256; idx += stride) {
        int n = (int)(idx % 256); size_t rest = idx/256;
        int k = (int)(rest % 64); rest /= 64;
        int dir = (int)(rest % 2); int t = (int)(rest/2);
        const float* W = dir ? nWhh_b : nWhh_f;
        g_Whh[idx] = f2tf32(W[((size_t)t*256 + n)*64 + k]);
    }
}

// ---------------- stage A: dense per-node content encode (tf32 tensor cores) ----------------
// grid (391, 2 dirs); block 256 (8 warps); block tile 128(M) x 192(N: 3 gates x 64)
__global__ __launch_bounds__(256) void content_kernel(
    const float* __restrict__ features, int t)
{
    extern __shared__ float sm[];
    float* As  = sm;             // [128][132]  row-major, tf32-rounded
    float* W1s = sm + 128*132;   // [32][200]   k-chunk of weights

    const float* feat = features + (size_t)t*N_NODES*128;
    int dir = blockIdx.y;
    int m0 = blockIdx.x*128;
    int tid = threadIdx.x;
    int warp = tid >> 5, lane = tid & 31;
    int wm = warp >> 2;          // 0..1 : 64-row half
    int wj = warp & 3;           // 0..3 : 16-j slice
    int lr = lane >> 2;          // 0..7
    int lc = lane & 3;           // 0..3

    {   // stage A row-major with tf32 rounding; clamp tail rows
        int rl = tid >> 5, c4 = tid & 31;
        #pragma unroll
        for (int it = 0; it < 16; it++) {
            int r = rl + it*8;
            int row = m0 + r; if (row >= N_NODES) row = N_NODES-1;
            float4 v = *(const float4*)(feat + (size_t)row*128 + c4*4);
            float4 o; o.x=f2tf32(v.x); o.y=f2tf32(v.y); o.z=f2tf32(v.z); o.w=f2tf32(v.w);
            *(float4*)&As[r*132 + c4*4] = o;
        }
    }

    float acc[4][3][2][4];   // [mtile][gate][jtile][c-regs]
    #pragma unroll
    for (int mt=0;mt<4;mt++)
        #pragma unroll
        for (int g=0;g<3;g++)
            #pragma unroll
            for (int jt=0;jt<2;jt++)
                #pragma unroll
                for (int r=0;r<4;r++) acc[mt][g][jt][r]=0.f;

    const float* W1t = g_W1 + (size_t)t*128*384 + dir*192;

    for (int kc = 0; kc < 4; kc++) {
        __syncthreads();
        for (int it = 0; it < 6; it++) {          // 32x48 float4 = 1536
            int idx = tid + it*256;
            int kk = idx / 48, c4 = idx % 48;
            float4 v = *(const float4*)(W1t + (size_t)(kc*32+kk)*384 + c4*4);
            *(float4*)&W1s[kk*200 + c4*4] = v;    // already tf32-rounded in pack
        }
        __syncthreads();
        #pragma unroll
        for (int k8 = 0; k8 < 4; k8++) {
            int kb = k8*8;
            uint32_t a[4][4];
            #pragma unroll
            for (int mt=0; mt<4; mt++) {
                const float* Ab = As + (wm*64 + mt*16)*132 + kc*32 + kb;
                a[mt][0] = __float_as_uint(Ab[lr*132 + lc]);
                a[mt][1] = __float_as_uint(Ab[(lr+8)*132 + lc]);
                a[mt][2] = __float_as_uint(Ab[lr*132 + lc+4]);
                a[mt][3] = __float_as_uint(Ab[(lr+8)*132 + lc+4]);
            }
            uint32_t b[3][2][2];
            #pragma unroll
            for (int g=0; g<3; g++)
                #pragma unroll
                for (int jt=0; jt<2; jt++) {
                    const float* Bb = W1s + kb*200 + g*64 + wj*16 + jt*8;
                    b[g][jt][0] = __float_as_uint(Bb[lc*200 + lr]);
                    b[g][jt][1] = __float_as_uint(Bb[(lc+4)*200 + lr]);
                }
            #pragma unroll
            for (int mt=0; mt<4; mt++)
                #pragma unroll
                for (int g=0; g<3; g++)
                    #pragma unroll
                    for (int jt=0; jt<2; jt++)
                        mma_tf32(acc[mt][g][jt][0], acc[mt][g][jt][1],
                                 acc[mt][g][jt][2], acc[mt][g][jt][3],
                                 a[mt][0], a[mt][1], a[mt][2], a[mt][3],
                                 b[g][jt][0], b[g][jt][1]);
        }
    }

    // epilogue: bias + LSTM nonlinearity, store CE
    const float* B1t = g_B1 + t*384 + dir*192;
    #pragma unroll
    for (int mt=0; mt<4; mt++) {
        #pragma unroll
        for (int jt=0; jt<2; jt++) {
            int j = wj*16 + jt*8 + lc*2;
            float bi0 = B1t[j],     bi1 = B1t[j+1];
            float bg0 = B1t[64+j],  bg1 = B1t[64+j+1];
            float bo0 = B1t[128+j], bo1 = B1t[128+j+1];
            int r0 = m0 + wm*64 + mt*16 + lr;
            int r1 = r0 + 8;
            if (r0 < N_NODES) {
                float cc0 = sigmoid_f(acc[mt][0][jt][0]+bi0) * tanh_f(acc[mt][1][jt][0]+bg0);
                float cc1 = sigmoid_f(acc[mt][0][jt][1]+bi1) * tanh_f(acc[mt][1][jt][1]+bg1);
                float2 v;
                v.x = sigmoid_f(acc[mt][2][jt][0]+bo0) * tanh_f(cc0);
                v.y = sigmoid_f(acc[mt][2][jt][1]+bo1) * tanh_f(cc1);
                *(float2*)(g_CE + (size_t)r0*128 + dir*64 + j) = v;
            }
            if (r1 < N_NODES) {
                float cc0 = sigmoid_f(acc[mt][0][jt][2]+bi0) * tanh_f(acc[mt][1][jt][2]+bg0);
                float cc1 = sigmoid_f(acc[mt][0][jt][3]+bi1) * tanh_f(acc[mt][1][jt][3]+bg1);
                float2 v;
                v.x = sigmoid_f(acc[mt][2][jt][2]+bo0) * tanh_f(cc0);
                v.y = sigmoid_f(acc[mt][2][jt][3]+bo1) * tanh_f(cc1);
                *(float2*)(g_CE + (size_t)r1*128 + dir*64 + j) = v;
            }
        }
    }
}

// ---------------- self embed: gather type-0 CE rows ----------------
__global__ void self_gather_kernel(const int* __restrict__ id_batch)
{
    int b = blockIdx.x;
    int tid = threadIdx.x;                 // 32 threads, one float4 each
    int id = id_batch[b];
    float4 v = *(const float4*)(g_CE + (size_t)id*128 + tid*4);
    *(float4*)(g_SELF + (size_t)b*128 + tid*4) = v;
}

// ---------------- stage B1: dense per-node seq-LSTM input projection (tf32) ----------------
// grid (391, 4); block 256 (8 warps); block tile 128(M) x 128(N)
__global__ __launch_bounds__(256) void ig_kernel(int t)
{
    extern __shared__ float sm[];
    float* As = sm;             // [128][132]
    float* Ws = sm + 128*132;   // [32][136]

    int nt = blockIdx.y;        // 0..3 : 128-col chunk of 512
    int m0 = blockIdx.x*128;
    int tid = threadIdx.x;
    int warp = tid >> 5, lane = tid & 31;
    int wm = warp >> 2;         // 0..1
    int wn = warp & 3;          // 0..3 : 32-col slice
    int lr = lane >> 2;
    int lc = lane & 3;

    {   // stage CE tile row-major with tf32 rounding
        int rl = tid >> 5, c4 = tid & 31;
        #pragma unroll
        for (int it=0; it<16; it++) {
            int r = rl + it*8;
            int row = m0 + r; if (row >= N_NODES) row = N_NODES-1;
            float4 v = *(const float4*)(g_CE + (size_t)row*128 + c4*4);
            float4 o; o.x=f2tf32(v.x); o.y=f2tf32(v.y); o.z=f2tf32(v.z); o.w=f2tf32(v.w);
            *(float4*)&As[r*132 + c4*4] = o;
        }
    }

    float acc[4][4][4];
    #pragma unroll
    for (int mt=0;mt<4;mt++)
        #pragma unroll
        for (int n8=0;n8<4;n8++)
            #pragma unroll
            for (int r=0;r<4;r++) acc[mt][n8][r]=0.f;

    const float* W2t = g_W2 + (size_t)t*128*512 + nt*128;

    for (int kc=0; kc<4; kc++) {
        __syncthreads();
        for (int it=0; it<4; it++) {     // 32x32 float4 = 1024
            int idx = tid + it*256;
            int kk = idx >> 5, c4 = idx & 31;
            float4 v = *(const float4*)(W2t + (size_t)(kc*32+kk)*512 + c4*4);
            *(float4*)&Ws[kk*136 + c4*4] = v;
        }
        __syncthreads();
        #pragma unroll
        for (int k8=0; k8<4; k8++) {
            int kb = k8*8;
            uint32_t a[4][4];
            #pragma unroll
            for (int mt=0; mt<4; mt++) {
                const float* Ab = As + (wm*64 + mt*16)*132 + kc*32 + kb;
                a[mt][0] = __float_as_uint(Ab[lr*132 + lc]);
                a[mt][1] = __float_as_uint(Ab[(lr+8)*132 + lc]);
                a[mt][2] = __float_as_uint(Ab[lr*132 + lc+4]);
                a[mt][3] = __float_as_uint(Ab[(lr+8)*132 + lc+4]);
            }
            uint32_t b[4][2];
            #pragma unroll
            for (int n8=0; n8<4; n8++) {
                const float* Bb = Ws + kb*136 + wn*32 + n8*8;
                b[n8][0] = __float_as_uint(Bb[lc*136 + lr]);
                b[n8][1] = __float_as_uint(Bb[(lc+4)*136 + lr]);
            }
            #pragma unroll
            for (int mt=0; mt<4; mt++)
                #pragma unroll
                for (int n8=0; n8<4; n8++)
                    mma_tf32(acc[mt][n8][0], acc[mt][n8][1], acc[mt][n8][2], acc[mt][n8][3],
                             a[mt][0], a[mt][1], a[mt][2], a[mt][3],
                             b[n8][0], b[n8][1]);
        }
    }

    const float* B2t = g_B2 + t*512;
    #pragma unroll
    for (int mt=0; mt<4; mt++) {
        #pragma unroll
        for (int n8=0; n8<4; n8++) {
            int ncol = nt*128 + wn*32 + n8*8 + lc*2;
            float b0 = B2t[ncol], b1 = B2t[ncol+1];
            int r0 = m0 + wm*64 + mt*16 + lr;
            int r1 = r0 + 8;
            if (r0 < N_NODES) {
                float2 v; v.x = acc[mt][n8][0]+b0; v.y = acc[mt][n8][1]+b1;
                *(float2*)(g_IG + (size_t)r0*512 + ncol) = v;
            }
            if (r1 < N_NODES) {
                float2 v; v.x = acc[mt][n8][2]+b0; v.y = acc[mt][n8][3]+b1;
                *(float2*)(g_IG + (size_t)r1*512 + ncol) = v;
            }
        }
    }
}

// ---------------- stage B2: tensor-core LSTM recurrence over K=10 ----------------
// grid (512, 2 dirs); block 256 (8 warps); 32 batch rows/block
// per step: g[32x256] = IG(gather) + h[32x64] @ WhhT via tf32 mma; c/hs in fp32 regs
// warp layout: wm (0..1) = 16-row m-tile; wj (0..3) = 16-j slice (all 4 gates, 2 jt of 8)
__global__ __launch_bounds__(256) void recur_kernel(const int* __restrict__ neigh_ids, int t)
{
    extern __shared__ float sm[];
    float* Whh_s = sm;             // [64][264]  k-major, pad 264 (conflict-free frag loads)
    float* hA0 = sm + 64*264;      // [32][68]   h tile (tf32 values)
    float* hA1 = hA0 + 32*68;
    int*   ids_s = (int*)(hA1 + 32*68);  // [32][10]

    int dir = blockIdx.y;
    int b0 = blockIdx.x*32;
    int tid = threadIdx.x;
    int warp = tid >> 5, lane = tid & 31;
    int wm = warp >> 2;            // 0..1
    int wj = warp & 3;             // 0..3
    int lr = lane >> 2, lc = lane & 3;

    // stage Whh [64][256] -> smem [64][264]
    const float* Wsrc = g_Whh + ((size_t)t*2 + dir)*64*256;
    #pragma unroll
    for (int it=0; it<16; it++) {          // 4096 float4
        int idx = tid + it*256;
        int kk = idx >> 6, c4 = idx & 63;
        float4 v = *(const float4*)(Wsrc + (size_t)kk*256 + c4*4);
        *(float4*)&Whh_s[kk*264 + c4*4] = v;
    }
    for (int idx = tid; idx < 32*68; idx += 256) hA0[idx] = 0.f;
    {
        const int* nsrc = neigh_ids + ((size_t)t*B_ + b0)*K_;
        for (int idx = tid; idx < 32*K_; idx += 256) ids_s[idx] = nsrc[idx];
    }
    __syncthreads();

    const float* ig = g_IG + dir*256;
    int row_lo = wm*16 + lr;               // block-local rows: row_lo, row_lo+8

    float c[2][4], hs[2][4];               // [jt][0:lo/j0 1:lo/j1 2:hi/j0 3:hi/j1]
    #pragma unroll
    for (int jt=0;jt<2;jt++)
        #pragma unroll
        for (int e=0;e<4;e++){ c[jt][e]=0.f; hs[jt][e]=0.f; }

    float* cur = hA0; float* nxt = hA1;

    for (int step=0; step<K_; step++) {
        int k = dir ? (K_-1-step) : step;

        // issue IG gathers early (consumed in epilogue; latency hidden by mma stream)
        int id_lo = ids_s[row_lo*K_ + k];
        int id_hi = ids_s[(row_lo+8)*K_ + k];
        const float* ig_lo = ig + (size_t)id_lo*512;
        const float* ig_hi = ig + (size_t)id_hi*512;
        float2 igv[2][4][2];               // [jt][gate][lo/hi]
        #pragma unroll
        for (int jt=0; jt<2; jt++) {
            int jb = wj*16 + jt*8 + lc*2;
            #pragma unroll
            for (int g=0; g<4; g++) {
                igv[jt][g][0] = *(const float2*)(ig_lo + g*64 + jb);
                igv[jt][g][1] = *(const float2*)(ig_hi + g*64 + jb);
            }
        }

        // acc = h_prev @ WhhT  (tf32 mma)
        float acc[4][2][4];                // [gate][jt][c-regs]
        #pragma unroll
        for (int g=0;g<4;g++)
            #pragma unroll
            for (int jt=0;jt<2;jt++)
                #pragma unroll
                for (int r=0;r<4;r++) acc[g][jt][r]=0.f;

        #pragma unroll
        for (int k8=0; k8<8; k8++) {
            int kb = k8*8;
            uint32_t a0 = __float_as_uint(cur[row_lo*68 + kb + lc]);
            uint32_t a1 = __float_as_uint(cur[(row_lo+8)*68 + kb + lc]);
            uint32_t a2 = __float_as_uint(cur[row_lo*68 + kb + lc + 4]);
            uint32_t a3 = __float_as_uint(cur[(row_lo+8)*68 + kb + lc + 4]);
            #pragma unroll
            for (int g=0; g<4; g++)
                #pragma unroll
                for (int jt=0; jt<2; jt++) {
                    int nb = g*64 + wj*16 + jt*8;
                    uint32_t bb0 = __float_as_uint(Whh_s[(kb+lc)*264 + nb + lr]);
                    uint32_t bb1 = __float_as_uint(Whh_s[(kb+lc+4)*264 + nb + lr]);
                    mma_tf32(acc[g][jt][0], acc[g][jt][1], acc[g][jt][2], acc[g][jt][3],
                             a0, a1, a2, a3, bb0, bb1);
                }
        }
        __syncthreads();   // all reads of cur complete before nxt writes alias next round

        // epilogue: gates, state update, h -> nxt (tf32-rounded)
        #pragma unroll
        for (int jt=0; jt<2; jt++) {
            int jb = wj*16 + jt*8 + lc*2;
            // row lo, cols jb, jb+1 (regs 0,1)
            {
                float pi0 = acc[0][jt][0] + igv[jt][0][0].x;
                float pf0 = acc[1][jt][0] + igv[jt][1][0].x;
                float pg0 = acc[2][jt][0] + igv[jt][2][0].x;
                float po0 = acc[3][jt][0] + igv[jt][3][0].x;
                float pi1 = acc[0][jt][1] + igv[jt][0][0].y;
                float pf1 = acc[1][jt][1] + igv[jt][1][0].y;
                float pg1 = acc[2][jt][1] + igv[jt][2][0].y;
                float po1 = acc[3][jt][1] + igv[jt][3][0].y;
                c[jt][0] = sigmoid_f(pf0)*c[jt][0] + sigmoid_f(pi0)*tanh_f(pg0);
                c[jt][1] = sigmoid_f(pf1)*c[jt][1] + sigmoid_f(pi1)*tanh_f(pg1);
                float h0 = sigmoid_f(po0)*tanh_f(c[jt][0]);
                float h1 = sigmoid_f(po1)*tanh_f(c[jt][1]);
                hs[jt][0] += h0; hs[jt][1] += h1;
                float2 v; v.x = f2tf32(h0); v.y = f2tf32(h1);
                *(float2*)&nxt[row_lo*68 + jb] = v;
            }
            // row hi (regs 2,3)
            {
                float pi0 = acc[0][jt][2] + igv[jt][0][1].x;
                float pf0 = acc[1][jt][2] + igv[jt][1][1].x;
                float pg0 = acc[2][jt][2] + igv[jt][2][1].x;
                float po0 = acc[3][jt][2] + igv[jt][3][1].x;
                float pi1 = acc[0][jt][3] + igv[jt][0][1].y;
                float pf1 = acc[1][jt][3] + igv[jt][1][1].y;
                float pg1 = acc[2][jt][3] + igv[jt][2][1].y;
                float po1 = acc[3][jt][3] + igv[jt][3][1].y;
                c[jt][2] = sigmoid_f(pf0)*c[jt][2] + sigmoid_f(pi0)*tanh_f(pg0);
                c[jt][3] = sigmoid_f(pf1)*c[jt][3] + sigmoid_f(pi1)*tanh_f(pg1);
                float h0 = sigmoid_f(po0)*tanh_f(c[jt][2]);
                float h1 = sigmoid_f(po1)*tanh_f(c[jt][3]);
                hs[jt][2] += h0; hs[jt][3] += h1;
                float2 v; v.x = f2tf32(h0); v.y = f2tf32(h1);
                *(float2*)&nxt[(row_lo+8)*68 + jb] = v;
            }
        }
        __syncthreads();   // nxt complete before it becomes cur
        float* tmp = cur; cur = nxt; nxt = tmp;
    }

    // mean over K, store
    #pragma unroll
    for (int jt=0; jt<2; jt++) {
        int jb = wj*16 + jt*8 + lc*2;
        int blo = b0 + row_lo, bhi = blo + 8;
        float2 v0; v0.x = hs[jt][0]*(1.0f/K_); v0.y = hs[jt][1]*(1.0f/K_);
        float2 v1; v1.x = hs[jt][2]*(1.0f/K_); v1.y = hs[jt][3]*(1.0f/K_);
        *(float2*)(g_AGG + ((size_t)t*B_ + blo)*128 + dir*64 + jb) = v0;
        *(float2*)(g_AGG + ((size_t)t*B_ + bhi)*128 + dir*64 + jb) = v1;
    }
}

// ---------------- stage C: attention combine ----------------
__global__ __launch_bounds__(256) void attn_kernel(const float* __restrict__ att,
                                                   float* __restrict__ out)
{
    int warp = threadIdx.x >> 5;
    int lane = threadIdx.x & 31;
    int b = blockIdx.x*8 + warp;

    float e[12][4], a0[4], a1[4];
    #pragma unroll
    for (int i=0;i<4;i++) {
        int d = i*32 + lane;
        a0[i] = att[d];
        a1[i] = att[128+d];
        e[0][i] = g_SELF[(size_t)b*128 + d];
    }
    #pragma unroll
    for (int t=0;t<T_;t++)
        #pragma unroll
        for (int i=0;i<4;i++)
            e[1+t][i] = g_AGG[((size_t)t*B_ + b)*128 + i*32 + lane];

    float pself = 0.f;
    #pragma unroll
    for (int i=0;i<4;i++) pself += e[0][i]*a0[i];
    float sc[12];
    #pragma unroll
    for (int j=0;j<12;j++) {
        float p = 0.f;
        #pragma unroll
        for (int i=0;i<4;i++) p += e[j][i]*a1[i];
        sc[j] = p;
    }
    #pragma unroll
    for (int off=16; off>0; off>>=1) {
        pself += __shfl_xor_sync(0xffffffff, pself, off);
        #pragma unroll
        for (int j=0;j<12;j++) sc[j] += __shfl_xor_sync(0xffffffff, sc[j], off);
    }
    float mx = -1e30f;
    #pragma unroll
    for (int j=0;j<12;j++) {
        float s = pself + sc[j];
        s = (s > 0.f) ? s : 0.01f*s;    // leaky_relu(0.01)
        sc[j] = s;
        mx = fmaxf(mx, s);
    }
    float sum = 0.f;
    #pragma unroll
    for (int j=0;j<12;j++) { sc[j] = expf(sc[j]-mx); sum += sc[j]; }
    float inv = 1.f/sum;
    #pragma unroll
    for (int i=0;i<4;i++) {
        float o = 0.f;
        #pragma unroll
        for (int j=0;j<12;j++) o += sc[j]*e[j][i];
        out[(size_t)b*128 + i*32 + lane] = o*inv;
    }
}

// ---------------- launch (single stream) ----------------
extern "C" void kernel_launch(void* const* d_in, const int* in_sizes, int n_in,
                              void* d_out, int out_size)
{
    const float* features = (const float*)d_in[0];
    const int*   id_batch = (const int*)d_in[1];
    const int*   neigh_ids= (const int*)d_in[2];
    const float* cWih_f   = (const float*)d_in[3];
    const float* cb_f     = (const float*)d_in[5];
    const float* cWih_b   = (const float*)d_in[6];
    const float* cb_b     = (const float*)d_in[8];
    const float* nWih_f   = (const float*)d_in[9];
    const float* nWhh_f   = (const float*)d_in[10];
    const float* nb_f     = (const float*)d_in[11];
    const float* nWih_b   = (const float*)d_in[12];
    const float* nWhh_b   = (const float*)d_in[13];
    const float* nb_b     = (const float*)d_in[14];
    const float* att      = (const float*)d_in[15];
    float* out = (float*)d_out;

    const int SMEM_CONTENT = (128*132 + 32*200) * 4;            // 93184
    const int SMEM_IG      = (128*132 + 32*136) * 4;            // 84992
    const int SMEM_RECUR   = (64*264 + 2*32*68 + 32*K_) * 4;    // 86272
    cudaFuncSetAttribute(content_kernel, cudaFuncAttributeMaxDynamicSharedMemorySize, SMEM_CONTENT);
    cudaFuncSetAttribute(ig_kernel,      cudaFuncAttributeMaxDynamicSharedMemorySize, SMEM_IG);
    cudaFuncSetAttribute(recur_kernel,   cudaFuncAttributeMaxDynamicSharedMemorySize, SMEM_RECUR);

    pack_kernel<<<512, 256>>>(cWih_f, cb_f, cWih_b, cb_b,
                              nWih_f, nb_f, nWih_b, nb_b, nWhh_f, nWhh_b);

    for (int t = 0; t < T_; t++) {
        dim3 gc(NROW_BLKS, 2);
        content_kernel<<<gc, 256, SMEM_CONTENT>>>(features, t);
        if (t == 0)
            self_gather_kernel<<<B_, 32>>>(id_batch);   // c_self = CE0[id_batch]
        dim3 gi(NROW_BLKS, 4);
        ig_kernel<<<gi, 256, SMEM_IG>>>(t);
        dim3 gr(B_/32, 2);
        recur_kernel<<<gr, 256, SMEM_RECUR>>>(neigh_ids, t);
    }

    attn_kernel<<<B_/8, 256>>>(att, out);
}

// round 11
// speedup vs baseline: 6.1610x; 1.1615x over previous
#include <cuda_runtime.h>
#include <stdint.h>
#include <stddef.h>
#include <math.h>

#define T_ 11
#define N_NODES 50000
#define D_ 128
#define H_ 64
#define B_ 16384
#define K_ 10
#define MROW_BLKS 782    // ceil(50000/64)

// ---------------- scratch (device globals; ~1.43 GB total, < 2GB reloc limit) ----------------
__device__ float g_W1[(size_t)T_*128*384];     // packed content Wih (gates i,g,o x 2 dirs), tf32-rounded
__device__ float g_B1[T_*384];
__device__ float g_W2[(size_t)T_*128*512];     // packed seq Wih (4 gates x 2 dirs), tf32-rounded
__device__ float g_B2[T_*512];
__device__ float g_Whh[(size_t)T_*2*64*256];   // [t][dir][k=64][n=256] k-major mma-B layout, tf32-rounded
__device__ float g_CE[(size_t)T_*N_NODES*128]; // per-node content encodings, ALL types (282 MB)
__device__ float g_IG[(size_t)T_*N_NODES*512]; // per-node seq-LSTM preacts, ALL types (1.13 GB)
__device__ float g_AGG[(size_t)T_*B_*128];

__device__ __forceinline__ float sigmoid_f(float x){
    return __fdividef(1.0f, 1.0f + __expf(-x));
}
__device__ __forceinline__ float tanh_f(float x){
    return 1.0f - __fdividef(2.0f, 1.0f + __expf(2.0f*x));
}
__device__ __forceinline__ float f2tf32(float x){
    uint32_t r;
    asm("cvt.rna.tf32.f32 %0, %1;" : "=r"(r) : "f"(x));
    return __uint_as_float(r);
}
__device__ __forceinline__ void mma_tf32(float& c0, float& c1, float& c2, float& c3,
                                         uint32_t a0, uint32_t a1, uint32_t a2, uint32_t a3,
                                         uint32_t b0, uint32_t b1){
    asm volatile("mma.sync.aligned.m16n8k8.row.col.f32.tf32.tf32.f32 "
                 "{%0,%1,%2,%3},{%4,%5,%6,%7},{%8,%9},{%0,%1,%2,%3};"
                 : "+f"(c0), "+f"(c1), "+f"(c2), "+f"(c3)
                 : "r"(a0), "r"(a1), "r"(a2), "r"(a3), "r"(b0), "r"(b1));
}

// ---------------- weight packing ----------------
__global__ void pack_kernel(const float* __restrict__ cWih_f, const float* __restrict__ cb_f,
                            const float* __restrict__ cWih_b, const float* __restrict__ cb_b,
                            const float* __restrict__ nWih_f, const float* __restrict__ nb_f,
                            const float* __restrict__ nWih_b, const float* __restrict__ nb_b,
                            const float* __restrict__ nWhh_f, const float* __restrict__ nWhh_b)
{
    int stride = gridDim.x*blockDim.x;
    int tid0 = blockIdx.x*blockDim.x + threadIdx.x;

    // W1: [t][kk][n], n = dir*192 + gate*64 + j, gate 0:i 1:g 2:o (f-gate dead: zero state)
    for (size_t idx = tid0; idx < (size_t)T_*128*384; idx += stride) {
        int n = (int)(idx % 384); size_t rest = idx / 384;
        int kk = (int)(rest % 128); int t = (int)(rest / 128);
        int dir = n/192, rem = n%192, g = rem/64, j = rem%64;
        int row = (g==0) ? j : (g==1) ? 128+j : 192+j;
        const float* W = dir ? cWih_b : cWih_f;
        g_W1[idx] = f2tf32(W[((size_t)t*256 + row)*128 + kk]);
    }
    for (int idx = tid0; idx < T_*384; idx += stride) {
        int n = idx % 384; int t = idx / 384;
        int dir = n/192, rem = n%192, g = rem/64, j = rem%64;
        int row = (g==0) ? j : (g==1) ? 128+j : 192+j;
        g_B1[idx] = (dir ? cb_b : cb_f)[t*256 + row];
    }
    // W2: [t][kk][n], n = dir*256 + r  (natural gate rows i,f,g,o)
    for (size_t idx = tid0; idx < (size_t)T_*128*512; idx += stride) {
        int n = (int)(idx % 512); size_t rest = idx/512;
        int kk = (int)(rest % 128); int t = (int)(rest/128);
        int dir = n/256, r = n%256;
        const float* W = dir ? nWih_b : nWih_f;
        g_W2[idx] = f2tf32(W[((size_t)t*256 + r)*128 + kk]);
    }
    for (int idx = tid0; idx < T_*512; idx += stride) {
        int n = idx % 512; int t = idx/512;
        int dir = n/256, r = n%256;
        g_B2[idx] = (dir ? nb_b : nb_f)[t*256 + r];
    }
    // Whh mma-B layout: [t][dir][k][n], tf32-rounded (source nWhh[t][n=256][k=64])
    for (size_t idx = tid0; idx < (size_t)T_*2*64*256; idx += stride) {
        int n = (int)(idx % 256); size_t rest = idx/256;
        int k = (int)(rest % 64); rest /= 64;
        int dir = (int)(rest % 2); int t = (int)(rest/2);
        const float* W = dir ? nWhh_b : nWhh_f;
        g_Whh[idx] = f2tf32(W[((size_t)t*256 + n)*64 + k]);
    }
}

// ---------------- stage A: dense per-node content encode, ALL types ----------------
// grid (782, 2 dirs, 11 types); block 256 (8 warps); block tile 64(M) x 192(N); smem ~46.6 KB
__global__ __launch_bounds__(256) void content_kernel(const float* __restrict__ features)
{
    extern __shared__ float sm[];
    float* As  = sm;             // [64][132]  row-major, tf32-rounded
    float* W1s = sm + 64*132;    // [16][200]  k-chunk of weights

    int t = blockIdx.z;
    const float* feat = features + (size_t)t*N_NODES*128;
    float* ce = g_CE + (size_t)t*N_NODES*128;
    int dir = blockIdx.y;
    int m0 = blockIdx.x*64;
    int tid = threadIdx.x;
    int warp = tid >> 5, lane = tid & 31;
    int wm = warp >> 2;          // 0..1 : 32-row half
    int wj = warp & 3;           // 0..3 : 16-j slice
    int lr = lane >> 2;          // 0..7
    int lc = lane & 3;           // 0..3

    {   // stage A (64x128) row-major with tf32 rounding; clamp tail rows
        int rl = tid >> 5, c4 = tid & 31;
        #pragma unroll
        for (int it = 0; it < 8; it++) {
            int r = rl + it*8;
            int row = m0 + r; if (row >= N_NODES) row = N_NODES-1;
            float4 v = *(const float4*)(feat + (size_t)row*128 + c4*4);
            float4 o; o.x=f2tf32(v.x); o.y=f2tf32(v.y); o.z=f2tf32(v.z); o.w=f2tf32(v.w);
            *(float4*)&As[r*132 + c4*4] = o;
        }
    }

    float acc[2][3][2][4];   // [mtile][gate][jtile][c-regs]
    #pragma unroll
    for (int mt=0;mt<2;mt++)
        #pragma unroll
        for (int g=0;g<3;g++)
            #pragma unroll
            for (int jt=0;jt<2;jt++)
                #pragma unroll
                for (int r=0;r<4;r++) acc[mt][g][jt][r]=0.f;

    const float* W1t = g_W1 + (size_t)t*128*384 + dir*192;

    for (int kc = 0; kc < 8; kc++) {     // 16 k-rows per chunk
        __syncthreads();
        for (int it = 0; it < 3; it++) {          // 16x48 float4 = 768
            int idx = tid + it*256;
            int kk = idx / 48, c4 = idx % 48;
            float4 v = *(const float4*)(W1t + (size_t)(kc*16+kk)*384 + c4*4);
            *(float4*)&W1s[kk*200 + c4*4] = v;    // already tf32-rounded in pack
        }
        __syncthreads();
        #pragma unroll
        for (int k8 = 0; k8 < 2; k8++) {
            int kb = k8*8;
            uint32_t a[2][4];
            #pragma unroll
            for (int mt=0; mt<2; mt++) {
                const float* Ab = As + (wm*32 + mt*16)*132 + kc*16 + kb;
                a[mt][0] = __float_as_uint(Ab[lr*132 + lc]);
                a[mt][1] = __float_as_uint(Ab[(lr+8)*132 + lc]);
                a[mt][2] = __float_as_uint(Ab[lr*132 + lc+4]);
                a[mt][3] = __float_as_uint(Ab[(lr+8)*132 + lc+4]);
            }
            uint32_t b[3][2][2];
            #pragma unroll
            for (int g=0; g<3; g++)
                #pragma unroll
                for (int jt=0; jt<2; jt++) {
                    const float* Bb = W1s + kb*200 + g*64 + wj*16 + jt*8;
                    b[g][jt][0] = __float_as_uint(Bb[lc*200 + lr]);
                    b[g][jt][1] = __float_as_uint(Bb[(lc+4)*200 + lr]);
                }
            #pragma unroll
            for (int mt=0; mt<2; mt++)
                #pragma unroll
                for (int g=0; g<3; g++)
                    #pragma unroll
                    for (int jt=0; jt<2; jt++)
                        mma_tf32(acc[mt][g][jt][0], acc[mt][g][jt][1],
                                 acc[mt][g][jt][2], acc[mt][g][jt][3],
                                 a[mt][0], a[mt][1], a[mt][2], a[mt][3],
                                 b[g][jt][0], b[g][jt][1]);
        }
    }

    // epilogue: bias + LSTM nonlinearity, store CE
    const float* B1t = g_B1 + t*384 + dir*192;
    #pragma unroll
    for (int mt=0; mt<2; mt++) {
        #pragma unroll
        for (int jt=0; jt<2; jt++) {
            int j = wj*16 + jt*8 + lc*2;
            float bi0 = B1t[j],     bi1 = B1t[j+1];
            float bg0 = B1t[64+j],  bg1 = B1t[64+j+1];
            float bo0 = B1t[128+j], bo1 = B1t[128+j+1];
            int r0 = m0 + wm*32 + mt*16 + lr;
            int r1 = r0 + 8;
            if (r0 < N_NODES) {
                float cc0 = sigmoid_f(acc[mt][0][jt][0]+bi0) * tanh_f(acc[mt][1][jt][0]+bg0);
                float cc1 = sigmoid_f(acc[mt][0][jt][1]+bi1) * tanh_f(acc[mt][1][jt][1]+bg1);
                float2 v;
                v.x = sigmoid_f(acc[mt][2][jt][0]+bo0) * tanh_f(cc0);
                v.y = sigmoid_f(acc[mt][2][jt][1]+bo1) * tanh_f(cc1);
                *(float2*)(ce + (size_t)r0*128 + dir*64 + j) = v;
            }
            if (r1 < N_NODES) {
                float cc0 = sigmoid_f(acc[mt][0][jt][2]+bi0) * tanh_f(acc[mt][1][jt][2]+bg0);
                float cc1 = sigmoid_f(acc[mt][0][jt][3]+bi1) * tanh_f(acc[mt][1][jt][3]+bg1);
                float2 v;
                v.x = sigmoid_f(acc[mt][2][jt][2]+bo0) * tanh_f(cc0);
                v.y = sigmoid_f(acc[mt][2][jt][3]+bo1) * tanh_f(cc1);
                *(float2*)(ce + (size_t)r1*128 + dir*64 + j) = v;
            }
        }
    }
}

// ---------------- stage B1: per-node seq-LSTM input projection, ALL types ----------------
// grid (782, 4, 11); block 256 (8 warps); block tile 64(M) x 128(N); smem ~42.5 KB
__global__ __launch_bounds__(256) void ig_kernel()
{
    extern __shared__ float sm[];
    float* As = sm;             // [64][132]
    float* Ws = sm + 64*132;    // [16][136]

    int t = blockIdx.z;
    const float* ce = g_CE + (size_t)t*N_NODES*128;
    float* igb = g_IG + (size_t)t*N_NODES*512;
    int nt = blockIdx.y;        // 0..3 : 128-col chunk of 512
    int m0 = blockIdx.x*64;
    int tid = threadIdx.x;
    int warp = tid >> 5, lane = tid & 31;
    int wm = warp >> 2;         // 0..1 : 32-row half
    int wn = warp & 3;          // 0..3 : 32-col slice
    int lr = lane >> 2;
    int lc = lane & 3;

    {   // stage CE tile (64x128) row-major with tf32 rounding
        int rl = tid >> 5, c4 = tid & 31;
        #pragma unroll
        for (int it=0; it<8; it++) {
            int r = rl + it*8;
            int row = m0 + r; if (row >= N_NODES) row = N_NODES-1;
            float4 v = *(const float4*)(ce + (size_t)row*128 + c4*4);
            float4 o; o.x=f2tf32(v.x); o.y=f2tf32(v.y); o.z=f2tf32(v.z); o.w=f2tf32(v.w);
            *(float4*)&As[r*132 + c4*4] = o;
        }
    }

    float acc[2][4][4];   // [mtile][ntile][c-regs]
    #pragma unroll
    for (int mt=0;mt<2;mt++)
        #pragma unroll
        for (int n8=0;n8<4;n8++)
            #pragma unroll
            for (int r=0;r<4;r++) acc[mt][n8][r]=0.f;

    const float* W2t = g_W2 + (size_t)t*128*512 + nt*128;

    for (int kc=0; kc<8; kc++) {        // 16 k-rows per chunk
        __syncthreads();
        for (int it=0; it<2; it++) {     // 16x32 float4 = 512
            int idx = tid + it*256;
            int kk = idx >> 5, c4 = idx & 31;
            float4 v = *(const float4*)(W2t + (size_t)(kc*16+kk)*512 + c4*4);
            *(float4*)&Ws[kk*136 + c4*4] = v;
        }
        __syncthreads();
        #pragma unroll
        for (int k8=0; k8<2; k8++) {
            int kb = k8*8;
            uint32_t a[2][4];
            #pragma unroll
            for (int mt=0; mt<2; mt++) {
                const float* Ab = As + (wm*32 + mt*16)*132 + kc*16 + kb;
                a[mt][0] = __float_as_uint(Ab[lr*132 + lc]);
                a[mt][1] = __float_as_uint(Ab[(lr+8)*132 + lc]);
                a[mt][2] = __float_as_uint(Ab[lr*132 + lc+4]);
                a[mt][3] = __float_as_uint(Ab[(lr+8)*132 + lc+4]);
            }
            uint32_t b[4][2];
            #pragma unroll
            for (int n8=0; n8<4; n8++) {
                const float* Bb = Ws + kb*136 + wn*32 + n8*8;
                b[n8][0] = __float_as_uint(Bb[lc*136 + lr]);
                b[n8][1] = __float_as_uint(Bb[(lc+4)*136 + lr]);
            }
            #pragma unroll
            for (int mt=0; mt<2; mt++)
                #pragma unroll
                for (int n8=0; n8<4; n8++)
                    mma_tf32(acc[mt][n8][0], acc[mt][n8][1], acc[mt][n8][2], acc[mt][n8][3],
                             a[mt][0], a[mt][1], a[mt][2], a[mt][3],
                             b[n8][0], b[n8][1]);
        }
    }

    const float* B2t = g_B2 + t*512;
    #pragma unroll
    for (int mt=0; mt<2; mt++) {
        #pragma unroll
        for (int n8=0; n8<4; n8++) {
            int ncol = nt*128 + wn*32 + n8*8 + lc*2;
            float b0 = B2t[ncol], b1 = B2t[ncol+1];
            int r0 = m0 + wm*32 + mt*16 + lr;
            int r1 = r0 + 8;
            if (r0 < N_NODES) {
                float2 v; v.x = acc[mt][n8][0]+b0; v.y = acc[mt][n8][1]+b1;
                *(float2*)(igb + (size_t)r0*512 + ncol) = v;
            }
            if (r1 < N_NODES) {
                float2 v; v.x = acc[mt][n8][2]+b0; v.y = acc[mt][n8][3]+b1;
                *(float2*)(igb + (size_t)r1*512 + ncol) = v;
            }
        }
    }
}

// ---------------- stage B2: tensor-core LSTM recurrence over K=10, ALL types ----------------
// grid (512, 2 dirs, 11 types); block 256 (8 warps); 32 batch rows/block
__global__ __launch_bounds__(256) void recur_kernel(const int* __restrict__ neigh_ids)
{
    extern __shared__ float sm[];
    float* Whh_s = sm;             // [64][264]  k-major, pad 264
    float* hA0 = sm + 64*264;      // [32][68]   h tile (tf32 values)
    float* hA1 = hA0 + 32*68;
    int*   ids_s = (int*)(hA1 + 32*68);  // [32][10]

    int t = blockIdx.z;
    int dir = blockIdx.y;
    int b0 = blockIdx.x*32;
    int tid = threadIdx.x;
    int warp = tid >> 5, lane = tid & 31;
    int wm = warp >> 2;            // 0..1
    int wj = warp & 3;             // 0..3
    int lr = lane >> 2, lc = lane & 3;

    // stage Whh [64][256] -> smem [64][264]
    const float* Wsrc = g_Whh + ((size_t)t*2 + dir)*64*256;
    #pragma unroll
    for (int it=0; it<16; it++) {          // 4096 float4
        int idx = tid + it*256;
        int kk = idx >> 6, c4 = idx & 63;
        float4 v = *(const float4*)(Wsrc + (size_t)kk*256 + c4*4);
        *(float4*)&Whh_s[kk*264 + c4*4] = v;
    }
    for (int idx = tid; idx < 32*68; idx += 256) hA0[idx] = 0.f;
    {
        const int* nsrc = neigh_ids + ((size_t)t*B_ + b0)*K_;
        for (int idx = tid; idx < 32*K_; idx += 256) ids_s[idx] = nsrc[idx];
    }
    __syncthreads();

    const float* ig = g_IG + (size_t)t*N_NODES*512 + dir*256;
    int row_lo = wm*16 + lr;               // block-local rows: row_lo, row_lo+8

    float c[2][4], hs[2][4];               // [jt][0:lo/j0 1:lo/j1 2:hi/j0 3:hi/j1]
    #pragma unroll
    for (int jt=0;jt<2;jt++)
        #pragma unroll
        for (int e=0;e<4;e++){ c[jt][e]=0.f; hs[jt][e]=0.f; }

    float* cur = hA0; float* nxt = hA1;

    for (int step=0; step<K_; step++) {
        int k = dir ? (K_-1-step) : step;

        // issue IG gathers early (consumed in epilogue; latency hidden by mma stream)
        int id_lo = ids_s[row_lo*K_ + k];
        int id_hi = ids_s[(row_lo+8)*K_ + k];
        const float* ig_lo = ig + (size_t)id_lo*512;
        const float* ig_hi = ig + (size_t)id_hi*512;
        float2 igv[2][4][2];               // [jt][gate][lo/hi]
        #pragma unroll
        for (int jt=0; jt<2; jt++) {
            int jb = wj*16 + jt*8 + lc*2;
            #pragma unroll
            for (int g=0; g<4; g++) {
                igv[jt][g][0] = *(const float2*)(ig_lo + g*64 + jb);
                igv[jt][g][1] = *(const float2*)(ig_hi + g*64 + jb);
            }
        }

        // acc = h_prev @ WhhT  (tf32 mma)
        float acc[4][2][4];                // [gate][jt][c-regs]
        #pragma unroll
        for (int g=0;g<4;g++)
            #pragma unroll
            for (int jt=0;jt<2;jt++)
                #pragma unroll
                for (int r=0;r<4;r++) acc[g][jt][r]=0.f;

        #pragma unroll
        for (int k8=0; k8<8; k8++) {
            int kb = k8*8;
            uint32_t a0 = __float_as_uint(cur[row_lo*68 + kb + lc]);
            uint32_t a1 = __float_as_uint(cur[(row_lo+8)*68 + kb + lc]);
            uint32_t a2 = __float_as_uint(cur[row_lo*68 + kb + lc + 4]);
            uint32_t a3 = __float_as_uint(cur[(row_lo+8)*68 + kb + lc + 4]);
            #pragma unroll
            for (int g=0; g<4; g++)
                #pragma unroll
                for (int jt=0; jt<2; jt++) {
                    int nb = g*64 + wj*16 + jt*8;
                    uint32_t bb0 = __float_as_uint(Whh_s[(kb+lc)*264 + nb + lr]);
                    uint32_t bb1 = __float_as_uint(Whh_s[(kb+lc+4)*264 + nb + lr]);
                    mma_tf32(acc[g][jt][0], acc[g][jt][1], acc[g][jt][2], acc[g][jt][3],
                             a0, a1, a2, a3, bb0, bb1);
                }
        }
        __syncthreads();   // all reads of cur complete before nxt writes alias next round

        // epilogue: gates, state update, h -> nxt (tf32-rounded)
        #pragma unroll
        for (int jt=0; jt<2; jt++) {
            int jb = wj*16 + jt*8 + lc*2;
            // row lo, cols jb, jb+1 (regs 0,1)
            {
                float pi0 = acc[0][jt][0] + igv[jt][0][0].x;
                float pf0 = acc[1][jt][0] + igv[jt][1][0].x;
                float pg0 = acc[2][jt][0] + igv[jt][2][0].x;
                float po0 = acc[3][jt][0] + igv[jt][3][0].x;
                float pi1 = acc[0][jt][1] + igv[jt][0][0].y;
                float pf1 = acc[1][jt][1] + igv[jt][1][0].y;
                float pg1 = acc[2][jt][1] + igv[jt][2][0].y;
                float po1 = acc[3][jt][1] + igv[jt][3][0].y;
                c[jt][0] = sigmoid_f(pf0)*c[jt][0] + sigmoid_f(pi0)*tanh_f(pg0);
                c[jt][1] = sigmoid_f(pf1)*c[jt][1] + sigmoid_f(pi1)*tanh_f(pg1);
                float h0 = sigmoid_f(po0)*tanh_f(c[jt][0]);
                float h1 = sigmoid_f(po1)*tanh_f(c[jt][1]);
                hs[jt][0] += h0; hs[jt][1] += h1;
                float2 v; v.x = f2tf32(h0); v.y = f2tf32(h1);
                *(float2*)&nxt[row_lo*68 + jb] = v;
            }
            // row hi (regs 2,3)
            {
                float pi0 = acc[0][jt][2] + igv[jt][0][1].x;
                float pf0 = acc[1][jt][2] + igv[jt][1][1].x;
                float pg0 = acc[2][jt][2] + igv[jt][2][1].x;
                float po0 = acc[3][jt][2] + igv[jt][3][1].x;
                float pi1 = acc[0][jt][3] + igv[jt][0][1].y;
                float pf1 = acc[1][jt][3] + igv[jt][1][1].y;
                float pg1 = acc[2][jt][3] + igv[jt][2][1].y;
                float po1 = acc[3][jt][3] + igv[jt][3][1].y;
                c[jt][2] = sigmoid_f(pf0)*c[jt][2] + sigmoid_f(pi0)*tanh_f(pg0);
                c[jt][3] = sigmoid_f(pf1)*c[jt][3] + sigmoid_f(pi1)*tanh_f(pg1);
                float h0 = sigmoid_f(po0)*tanh_f(c[jt][2]);
                float h1 = sigmoid_f(po1)*tanh_f(c[jt][3]);
                hs[jt][2] += h0; hs[jt][3] += h1;
                float2 v; v.x = f2tf32(h0); v.y = f2tf32(h1);
                *(float2*)&nxt[(row_lo+8)*68 + jb] = v;
            }
        }
        __syncthreads();   // nxt complete before it becomes cur
        float* tmp = cur; cur = nxt; nxt = tmp;
    }

    // mean over K, store
    #pragma unroll
    for (int jt=0; jt<2; jt++) {
        int jb = wj*16 + jt*8 + lc*2;
        int blo = b0 + row_lo, bhi = blo + 8;
        float2 v0; v0.x = hs[jt][0]*(1.0f/K_); v0.y = hs[jt][1]*(1.0f/K_);
        float2 v1; v1.x = hs[jt][2]*(1.0f/K_); v1.y = hs[jt][3]*(1.0f/K_);
        *(float2*)(g_AGG + ((size_t)t*B_ + blo)*128 + dir*64 + jb) = v0;
        *(float2*)(g_AGG + ((size_t)t*B_ + bhi)*128 + dir*64 + jb) = v1;
    }
}

// ---------------- stage C: attention combine (self embed gathered from CE type 0) ----------------
__global__ __launch_bounds__(256) void attn_kernel(const int* __restrict__ id_batch,
                                                   const float* __restrict__ att,
                                                   float* __restrict__ out)
{
    int warp = threadIdx.x >> 5;
    int lane = threadIdx.x & 31;
    int b = blockIdx.x*8 + warp;
    int id = id_batch[b];

    float e[12][4], a0[4], a1[4];
    #pragma unroll
    for (int i=0;i<4;i++) {
        int d = i*32 + lane;
        a0[i] = att[d];
        a1[i] = att[128+d];
        e[0][i] = g_CE[(size_t)id*128 + d];    // c_self = CE type-0 row
    }
    #pragma unroll
    for (int t=0;t<T_;t++)
        #pragma unroll
        for (int i=0;i<4;i++)
            e[1+t][i] = g_AGG[((size_t)t*B_ + b)*128 + i*32 + lane];

    float pself = 0.f;
    #pragma unroll
    for (int i=0;i<4;i++) pself += e[0][i]*a0[i];
    float sc[12];
    #pragma unroll
    for (int j=0;j<12;j++) {
        float p = 0.f;
        #pragma unroll
        for (int i=0;i<4;i++) p += e[j][i]*a1[i];
        sc[j] = p;
    }
    #pragma unroll
    for (int off=16; off>0; off>>=1) {
        pself += __shfl_xor_sync(0xffffffff, pself, off);
        #pragma unroll
        for (int j=0;j<12;j++) sc[j] += __shfl_xor_sync(0xffffffff, sc[j], off);
    }
    float mx = -1e30f;
    #pragma unroll
    for (int j=0;j<12;j++) {
        float s = pself + sc[j];
        s = (s > 0.f) ? s : 0.01f*s;    // leaky_relu(0.01)
        sc[j] = s;
        mx = fmaxf(mx, s);
    }
    float sum = 0.f;
    #pragma unroll
    for (int j=0;j<12;j++) { sc[j] = expf(sc[j]-mx); sum += sc[j]; }
    float inv = 1.f/sum;
    #pragma unroll
    for (int i=0;i<4;i++) {
        float o = 0.f;
        #pragma unroll
        for (int j=0;j<12;j++) o += sc[j]*e[j][i];
        out[(size_t)b*128 + i*32 + lane] = o*inv;
    }
}

// ---------------- launch (single stream, 5 launches) ----------------
extern "C" void kernel_launch(void* const* d_in, const int* in_sizes, int n_in,
                              void* d_out, int out_size)
{
    const float* features = (const float*)d_in[0];
    const int*   id_batch = (const int*)d_in[1];
    const int*   neigh_ids= (const int*)d_in[2];
    const float* cWih_f   = (const float*)d_in[3];
    const float* cb_f     = (const float*)d_in[5];
    const float* cWih_b   = (const float*)d_in[6];
    const float* cb_b     = (const float*)d_in[8];
    const float* nWih_f   = (const float*)d_in[9];
    const float* nWhh_f   = (const float*)d_in[10];
    const float* nb_f     = (const float*)d_in[11];
    const float* nWih_b   = (const float*)d_in[12];
    const float* nWhh_b   = (const float*)d_in[13];
    const float* nb_b     = (const float*)d_in[14];
    const float* att      = (const float*)d_in[15];
    float* out = (float*)d_out;

    const int SMEM_CONTENT = (64*132 + 16*200) * 4;             // 46592
    const int SMEM_IG      = (64*132 + 16*136) * 4;             // 42496
    const int SMEM_RECUR   = (64*264 + 2*32*68 + 32*K_) * 4;    // 86272
    cudaFuncSetAttribute(content_kernel, cudaFuncAttributeMaxDynamicSharedMemorySize, SMEM_CONTENT);
    cudaFuncSetAttribute(ig_kernel,      cudaFuncAttributeMaxDynamicSharedMemorySize, SMEM_IG);
    cudaFuncSetAttribute(recur_kernel,   cudaFuncAttributeMaxDynamicSharedMemorySize, SMEM_RECUR);

    pack_kernel<<<512, 256>>>(cWih_f, cb_f, cWih_b, cb_b,
                              nWih_f, nb_f, nWih_b, nb_b, nWhh_f, nWhh_b);

    {   // content encode, all types
        dim3 g(MROW_BLKS, 2, T_);
        content_kernel<<<g, 256, SMEM_CONTENT>>>(features);
    }
    {   // seq-LSTM input projections, all types
        dim3 g(MROW_BLKS, 4, T_);
        ig_kernel<<<g, 256, SMEM_IG>>>();
    }
    {   // recurrence, all types
        dim3 g(B_/32, 2, T_);
        recur_kernel<<<g, 256, SMEM_RECUR>>>(neigh_ids);
    }
    attn_kernel<<<B_/8, 256>>>(id_batch, att, out);
}

// round 12
// speedup vs baseline: 6.9403x; 1.1265x over previous
#include <cuda_runtime.h>
#include <stdint.h>
#include <stddef.h>
#include <math.h>

#define T_ 11
#define N_NODES 50000
#define D_ 128
#define H_ 64
#define B_ 16384
#define K_ 10
#define MROW_BLKS 782    // ceil(50000/64)

// ---------------- scratch (device globals; ~1.43 GB total, < 2GB reloc limit) ----------------
__device__ float g_W1[(size_t)T_*128*384];     // packed content Wih (gates i,g,o x 2 dirs), tf32-rounded
__device__ float g_B1[T_*384];
__device__ float g_W2[(size_t)T_*128*512];     // packed seq Wih (4 gates x 2 dirs), tf32-rounded
__device__ float g_B2[T_*512];
__device__ float g_Whh[(size_t)T_*2*64*256];   // [t][dir][k=64][n=256] k-major mma-B layout, tf32-rounded
__device__ float g_CE[(size_t)T_*N_NODES*128]; // per-node content encodings, ALL types (282 MB)
__device__ float g_IG[(size_t)T_*N_NODES*512]; // per-node seq-LSTM preacts, ALL types (1.13 GB)
__device__ float g_AGG[(size_t)T_*B_*128];

// HW tanh (MUFU.TANH, sm_75+): 1 MUFU op vs 2 (EX2+RCP) for the exp-based forms.
__device__ __forceinline__ float tanh_f(float x){
    float r; asm("tanh.approx.f32 %0, %1;" : "=f"(r) : "f"(x)); return r;
}
__device__ __forceinline__ float sigmoid_f(float x){
    float r; asm("tanh.approx.f32 %0, %1;" : "=f"(r) : "f"(0.5f*x));
    return fmaf(0.5f, r, 0.5f);
}
__device__ __forceinline__ float f2tf32(float x){
    uint32_t r;
    asm("cvt.rna.tf32.f32 %0, %1;" : "=r"(r) : "f"(x));
    return __uint_as_float(r);
}
__device__ __forceinline__ void mma_tf32(float& c0, float& c1, float& c2, float& c3,
                                         uint32_t a0, uint32_t a1, uint32_t a2, uint32_t a3,
                                         uint32_t b0, uint32_t b1){
    asm volatile("mma.sync.aligned.m16n8k8.row.col.f32.tf32.tf32.f32 "
                 "{%0,%1,%2,%3},{%4,%5,%6,%7},{%8,%9},{%0,%1,%2,%3};"
                 : "+f"(c0), "+f"(c1), "+f"(c2), "+f"(c3)
                 : "r"(a0), "r"(a1), "r"(a2), "r"(a3), "r"(b0), "r"(b1));
}

// ---------------- weight packing ----------------
__global__ void pack_kernel(const float* __restrict__ cWih_f, const float* __restrict__ cb_f,
                            const float* __restrict__ cWih_b, const float* __restrict__ cb_b,
                            const float* __restrict__ nWih_f, const float* __restrict__ nb_f,
                            const float* __restrict__ nWih_b, const float* __restrict__ nb_b,
                            const float* __restrict__ nWhh_f, const float* __restrict__ nWhh_b)
{
    int stride = gridDim.x*blockDim.x;
    int tid0 = blockIdx.x*blockDim.x + threadIdx.x;

    // W1: [t][kk][n], n = dir*192 + gate*64 + j, gate 0:i 1:g 2:o (f-gate dead: zero state)
    for (size_t idx = tid0; idx < (size_t)T_*128*384; idx += stride) {
        int n = (int)(idx % 384); size_t rest = idx / 384;
        int kk = (int)(rest % 128); int t = (int)(rest / 128);
        int dir = n/192, rem = n%192, g = rem/64, j = rem%64;
        int row = (g==0) ? j : (g==1) ? 128+j : 192+j;
        const float* W = dir ? cWih_b : cWih_f;
        g_W1[idx] = f2tf32(W[((size_t)t*256 + row)*128 + kk]);
    }
    for (int idx = tid0; idx < T_*384; idx += stride) {
        int n = idx % 384; int t = idx / 384;
        int dir = n/192, rem = n%192, g = rem/64, j = rem%64;
        int row = (g==0) ? j : (g==1) ? 128+j : 192+j;
        g_B1[idx] = (dir ? cb_b : cb_f)[t*256 + row];
    }
    // W2: [t][kk][n], n = dir*256 + r  (natural gate rows i,f,g,o)
    for (size_t idx = tid0; idx < (size_t)T_*128*512; idx += stride) {
        int n = (int)(idx % 512); size_t rest = idx/512;
        int kk = (int)(rest % 128); int t = (int)(rest/128);
        int dir = n/256, r = n%256;
        const float* W = dir ? nWih_b : nWih_f;
        g_W2[idx] = f2tf32(W[((size_t)t*256 + r)*128 + kk]);
    }
    for (int idx = tid0; idx < T_*512; idx += stride) {
        int n = idx % 512; int t = idx/512;
        int dir = n/256, r = n%256;
        g_B2[idx] = (dir ? nb_b : nb_f)[t*256 + r];
    }
    // Whh mma-B layout: [t][dir][k][n], tf32-rounded (source nWhh[t][n=256][k=64])
    for (size_t idx = tid0; idx < (size_t)T_*2*64*256; idx += stride) {
        int n = (int)(idx % 256); size_t rest = idx/256;
        int k = (int)(rest % 64); rest /= 64;
        int dir = (int)(rest % 2); int t = (int)(rest/2);
        const float* W = dir ? nWhh_b : nWhh_f;
        g_Whh[idx] = f2tf32(W[((size_t)t*256 + n)*64 + k]);
    }
}

// ---------------- stage A: dense per-node content encode, ALL types ----------------
// grid (782, 2 dirs, 11 types); block 256 (8 warps); block tile 64(M) x 192(N); smem ~46.6 KB
__global__ __launch_bounds__(256) void content_kernel(const float* __restrict__ features)
{
    extern __shared__ float sm[];
    float* As  = sm;             // [64][132]  row-major, tf32-rounded
    float* W1s = sm + 64*132;    // [16][200]  k-chunk of weights

    int t = blockIdx.z;
    const float* feat = features + (size_t)t*N_NODES*128;
    float* ce = g_CE + (size_t)t*N_NODES*128;
    int dir = blockIdx.y;
    int m0 = blockIdx.x*64;
    int tid = threadIdx.x;
    int warp = tid >> 5, lane = tid & 31;
    int wm = warp >> 2;          // 0..1 : 32-row half
    int wj = warp & 3;           // 0..3 : 16-j slice
    int lr = lane >> 2;          // 0..7
    int lc = lane & 3;           // 0..3

    {   // stage A (64x128) row-major with tf32 rounding; clamp tail rows
        int rl = tid >> 5, c4 = tid & 31;
        #pragma unroll
        for (int it = 0; it < 8; it++) {
            int r = rl + it*8;
            int row = m0 + r; if (row >= N_NODES) row = N_NODES-1;
            float4 v = *(const float4*)(feat + (size_t)row*128 + c4*4);
            float4 o; o.x=f2tf32(v.x); o.y=f2tf32(v.y); o.z=f2tf32(v.z); o.w=f2tf32(v.w);
            *(float4*)&As[r*132 + c4*4] = o;
        }
    }

    float acc[2][3][2][4];   // [mtile][gate][jtile][c-regs]
    #pragma unroll
    for (int mt=0;mt<2;mt++)
        #pragma unroll
        for (int g=0;g<3;g++)
            #pragma unroll
            for (int jt=0;jt<2;jt++)
                #pragma unroll
                for (int r=0;r<4;r++) acc[mt][g][jt][r]=0.f;

    const float* W1t = g_W1 + (size_t)t*128*384 + dir*192;

    for (int kc = 0; kc < 8; kc++) {     // 16 k-rows per chunk
        __syncthreads();
        for (int it = 0; it < 3; it++) {          // 16x48 float4 = 768
            int idx = tid + it*256;
            int kk = idx / 48, c4 = idx % 48;
            float4 v = *(const float4*)(W1t + (size_t)(kc*16+kk)*384 + c4*4);
            *(float4*)&W1s[kk*200 + c4*4] = v;    // already tf32-rounded in pack
        }
        __syncthreads();
        #pragma unroll
        for (int k8 = 0; k8 < 2; k8++) {
            int kb = k8*8;
            uint32_t a[2][4];
            #pragma unroll
            for (int mt=0; mt<2; mt++) {
                const float* Ab = As + (wm*32 + mt*16)*132 + kc*16 + kb;
                a[mt][0] = __float_as_uint(Ab[lr*132 + lc]);
                a[mt][1] = __float_as_uint(Ab[(lr+8)*132 + lc]);
                a[mt][2] = __float_as_uint(Ab[lr*132 + lc+4]);
                a[mt][3] = __float_as_uint(Ab[(lr+8)*132 + lc+4]);
            }
            uint32_t b[3][2][2];
            #pragma unroll
            for (int g=0; g<3; g++)
                #pragma unroll
                for (int jt=0; jt<2; jt++) {
                    const float* Bb = W1s + kb*200 + g*64 + wj*16 + jt*8;
                    b[g][jt][0] = __float_as_uint(Bb[lc*200 + lr]);
                    b[g][jt][1] = __float_as_uint(Bb[(lc+4)*200 + lr]);
                }
            #pragma unroll
            for (int mt=0; mt<2; mt++)
                #pragma unroll
                for (int g=0; g<3; g++)
                    #pragma unroll
                    for (int jt=0; jt<2; jt++)
                        mma_tf32(acc[mt][g][jt][0], acc[mt][g][jt][1],
                                 acc[mt][g][jt][2], acc[mt][g][jt][3],
                                 a[mt][0], a[mt][1], a[mt][2], a[mt][3],
                                 b[g][jt][0], b[g][jt][1]);
        }
    }

    // epilogue: bias + LSTM nonlinearity, store CE
    const float* B1t = g_B1 + t*384 + dir*192;
    #pragma unroll
    for (int mt=0; mt<2; mt++) {
        #pragma unroll
        for (int jt=0; jt<2; jt++) {
            int j = wj*16 + jt*8 + lc*2;
            float bi0 = B1t[j],     bi1 = B1t[j+1];
            float bg0 = B1t[64+j],  bg1 = B1t[64+j+1];
            float bo0 = B1t[128+j], bo1 = B1t[128+j+1];
            int r0 = m0 + wm*32 + mt*16 + lr;
            int r1 = r0 + 8;
            if (r0 < N_NODES) {
                float cc0 = sigmoid_f(acc[mt][0][jt][0]+bi0) * tanh_f(acc[mt][1][jt][0]+bg0);
                float cc1 = sigmoid_f(acc[mt][0][jt][1]+bi1) * tanh_f(acc[mt][1][jt][1]+bg1);
                float2 v;
                v.x = sigmoid_f(acc[mt][2][jt][0]+bo0) * tanh_f(cc0);
                v.y = sigmoid_f(acc[mt][2][jt][1]+bo1) * tanh_f(cc1);
                *(float2*)(ce + (size_t)r0*128 + dir*64 + j) = v;
            }
            if (r1 < N_NODES) {
                float cc0 = sigmoid_f(acc[mt][0][jt][2]+bi0) * tanh_f(acc[mt][1][jt][2]+bg0);
                float cc1 = sigmoid_f(acc[mt][0][jt][3]+bi1) * tanh_f(acc[mt][1][jt][3]+bg1);
                float2 v;
                v.x = sigmoid_f(acc[mt][2][jt][2]+bo0) * tanh_f(cc0);
                v.y = sigmoid_f(acc[mt][2][jt][3]+bo1) * tanh_f(cc1);
                *(float2*)(ce + (size_t)r1*128 + dir*64 + j) = v;
            }
        }
    }
}

// ---------------- stage B1: per-node seq-LSTM input projection, ALL types ----------------
// grid (782, 4, 11); block 256 (8 warps); block tile 64(M) x 128(N); smem ~42.5 KB
__global__ __launch_bounds__(256) void ig_kernel()
{
    extern __shared__ float sm[];
    float* As = sm;             // [64][132]
    float* Ws = sm + 64*132;    // [16][136]

    int t = blockIdx.z;
    const float* ce = g_CE + (size_t)t*N_NODES*128;
    float* igb = g_IG + (size_t)t*N_NODES*512;
    int nt = blockIdx.y;        // 0..3 : 128-col chunk of 512
    int m0 = blockIdx.x*64;
    int tid = threadIdx.x;
    int warp = tid >> 5, lane = tid & 31;
    int wm = warp >> 2;         // 0..1 : 32-row half
    int wn = warp & 3;          // 0..3 : 32-col slice
    int lr = lane >> 2;
    int lc = lane & 3;

    {   // stage CE tile (64x128) row-major with tf32 rounding
        int rl = tid >> 5, c4 = tid & 31;
        #pragma unroll
        for (int it=0; it<8; it++) {
            int r = rl + it*8;
            int row = m0 + r; if (row >= N_NODES) row = N_NODES-1;
            float4 v = *(const float4*)(ce + (size_t)row*128 + c4*4);
            float4 o; o.x=f2tf32(v.x); o.y=f2tf32(v.y); o.z=f2tf32(v.z); o.w=f2tf32(v.w);
            *(float4*)&As[r*132 + c4*4] = o;
        }
    }

    float acc[2][4][4];   // [mtile][ntile][c-regs]
    #pragma unroll
    for (int mt=0;mt<2;mt++)
        #pragma unroll
        for (int n8=0;n8<4;n8++)
            #pragma unroll
            for (int r=0;r<4;r++) acc[mt][n8][r]=0.f;

    const float* W2t = g_W2 + (size_t)t*128*512 + nt*128;

    for (int kc=0; kc<8; kc++) {        // 16 k-rows per chunk
        __syncthreads();
        for (int it=0; it<2; it++) {     // 16x32 float4 = 512
            int idx = tid + it*256;
            int kk = idx >> 5, c4 = idx & 31;
            float4 v = *(const float4*)(W2t + (size_t)(kc*16+kk)*512 + c4*4);
            *(float4*)&Ws[kk*136 + c4*4] = v;
        }
        __syncthreads();
        #pragma unroll
        for (int k8=0; k8<2; k8++) {
            int kb = k8*8;
            uint32_t a[2][4];
            #pragma unroll
            for (int mt=0; mt<2; mt++) {
                const float* Ab = As + (wm*32 + mt*16)*132 + kc*16 + kb;
                a[mt][0] = __float_as_uint(Ab[lr*132 + lc]);
                a[mt][1] = __float_as_uint(Ab[(lr+8)*132 + lc]);
                a[mt][2] = __float_as_uint(Ab[lr*132 + lc+4]);
                a[mt][3] = __float_as_uint(Ab[(lr+8)*132 + lc+4]);
            }
            uint32_t b[4][2];
            #pragma unroll
            for (int n8=0; n8<4; n8++) {
                const float* Bb = Ws + kb*136 + wn*32 + n8*8;
                b[n8][0] = __float_as_uint(Bb[lc*136 + lr]);
                b[n8][1] = __float_as_uint(Bb[(lc+4)*136 + lr]);
            }
            #pragma unroll
            for (int mt=0; mt<2; mt++)
                #pragma unroll
                for (int n8=0; n8<4; n8++)
                    mma_tf32(acc[mt][n8][0], acc[mt][n8][1], acc[mt][n8][2], acc[mt][n8][3],
                             a[mt][0], a[mt][1], a[mt][2], a[mt][3],
                             b[n8][0], b[n8][1]);
        }
    }

    const float* B2t = g_B2 + t*512;
    #pragma unroll
    for (int mt=0; mt<2; mt++) {
        #pragma unroll
        for (int n8=0; n8<4; n8++) {
            int ncol = nt*128 + wn*32 + n8*8 + lc*2;
            float b0 = B2t[ncol], b1 = B2t[ncol+1];
            int r0 = m0 + wm*32 + mt*16 + lr;
            int r1 = r0 + 8;
            if (r0 < N_NODES) {
                float2 v; v.x = acc[mt][n8][0]+b0; v.y = acc[mt][n8][1]+b1;
                *(float2*)(igb + (size_t)r0*512 + ncol) = v;
            }
            if (r1 < N_NODES) {
                float2 v; v.x = acc[mt][n8][2]+b0; v.y = acc[mt][n8][3]+b1;
                *(float2*)(igb + (size_t)r1*512 + ncol) = v;
            }
        }
    }
}

// ---------------- stage B2: tensor-core LSTM recurrence over K=10, ALL types ----------------
// grid (512, 2 dirs, 11 types); block 256 (8 warps); 32 batch rows/block
__global__ __launch_bounds__(256) void recur_kernel(const int* __restrict__ neigh_ids)
{
    extern __shared__ float sm[];
    float* Whh_s = sm;             // [64][264]  k-major, pad 264
    float* hA0 = sm + 64*264;      // [32][68]   h tile (tf32 values)
    float* hA1 = hA0 + 32*68;
    int*   ids_s = (int*)(hA1 + 32*68);  // [32][10]

    int t = blockIdx.z;
    int dir = blockIdx.y;
    int b0 = blockIdx.x*32;
    int tid = threadIdx.x;
    int warp = tid >> 5, lane = tid & 31;
    int wm = warp >> 2;            // 0..1
    int wj = warp & 3;             // 0..3
    int lr = lane >> 2, lc = lane & 3;

    // stage Whh [64][256] -> smem [64][264]
    const float* Wsrc = g_Whh + ((size_t)t*2 + dir)*64*256;
    #pragma unroll
    for (int it=0; it<16; it++) {          // 4096 float4
        int idx = tid + it*256;
        int kk = idx >> 6, c4 = idx & 63;
        float4 v = *(const float4*)(Wsrc + (size_t)kk*256 + c4*4);
        *(float4*)&Whh_s[kk*264 + c4*4] = v;
    }
    for (int idx = tid; idx < 32*68; idx += 256) hA0[idx] = 0.f;
    {
        const int* nsrc = neigh_ids + ((size_t)t*B_ + b0)*K_;
        for (int idx = tid; idx < 32*K_; idx += 256) ids_s[idx] = nsrc[idx];
    }
    __syncthreads();

    const float* ig = g_IG + (size_t)t*N_NODES*512 + dir*256;
    int row_lo = wm*16 + lr;               // block-local rows: row_lo, row_lo+8

    float c[2][4], hs[2][4];               // [jt][0:lo/j0 1:lo/j1 2:hi/j0 3:hi/j1]
    #pragma unroll
    for (int jt=0;jt<2;jt++)
        #pragma unroll
        for (int e=0;e<4;e++){ c[jt][e]=0.f; hs[jt][e]=0.f; }

    float* cur = hA0; float* nxt = hA1;

    for (int step=0; step<K_; step++) {
        int k = dir ? (K_-1-step) : step;

        // issue IG gathers early (consumed in epilogue; latency hidden by mma stream)
        int id_lo = ids_s[row_lo*K_ + k];
        int id_hi = ids_s[(row_lo+8)*K_ + k];
        const float* ig_lo = ig + (size_t)id_lo*512;
        const float* ig_hi = ig + (size_t)id_hi*512;
        float2 igv[2][4][2];               // [jt][gate][lo/hi]
        #pragma unroll
        for (int jt=0; jt<2; jt++) {
            int jb = wj*16 + jt*8 + lc*2;
            #pragma unroll
            for (int g=0; g<4; g++) {
                igv[jt][g][0] = *(const float2*)(ig_lo + g*64 + jb);
                igv[jt][g][1] = *(const float2*)(ig_hi + g*64 + jb);
            }
        }

        // acc = h_prev @ WhhT  (tf32 mma)
        float acc[4][2][4];                // [gate][jt][c-regs]
        #pragma unroll
        for (int g=0;g<4;g++)
            #pragma unroll
            for (int jt=0;jt<2;jt++)
                #pragma unroll
                for (int r=0;r<4;r++) acc[g][jt][r]=0.f;

        #pragma unroll
        for (int k8=0; k8<8; k8++) {
            int kb = k8*8;
            uint32_t a0 = __float_as_uint(cur[row_lo*68 + kb + lc]);
            uint32_t a1 = __float_as_uint(cur[(row_lo+8)*68 + kb + lc]);
            uint32_t a2 = __float_as_uint(cur[row_lo*68 + kb + lc + 4]);
            uint32_t a3 = __float_as_uint(cur[(row_lo+8)*68 + kb + lc + 4]);
            #pragma unroll
            for (int g=0; g<4; g++)
                #pragma unroll
                for (int jt=0; jt<2; jt++) {
                    int nb = g*64 + wj*16 + jt*8;
                    uint32_t bb0 = __float_as_uint(Whh_s[(kb+lc)*264 + nb + lr]);
                    uint32_t bb1 = __float_as_uint(Whh_s[(kb+lc+4)*264 + nb + lr]);
                    mma_tf32(acc[g][jt][0], acc[g][jt][1], acc[g][jt][2], acc[g][jt][3],
                             a0, a1, a2, a3, bb0, bb1);
                }
        }
        __syncthreads();   // all reads of cur complete before nxt writes alias next round

        // epilogue: gates, state update, h -> nxt (tf32-rounded)
        #pragma unroll
        for (int jt=0; jt<2; jt++) {
            int jb = wj*16 + jt*8 + lc*2;
            // row lo, cols jb, jb+1 (regs 0,1)
            {
                float pi0 = acc[0][jt][0] + igv[jt][0][0].x;
                float pf0 = acc[1][jt][0] + igv[jt][1][0].x;
                float pg0 = acc[2][jt][0] + igv[jt][2][0].x;
                float po0 = acc[3][jt][0] + igv[jt][3][0].x;
                float pi1 = acc[0][jt][1] + igv[jt][0][0].y;
                float pf1 = acc[1][jt][1] + igv[jt][1][0].y;
                float pg1 = acc[2][jt][1] + igv[jt][2][0].y;
                float po1 = acc[3][jt][1] + igv[jt][3][0].y;
                c[jt][0] = sigmoid_f(pf0)*c[jt][0] + sigmoid_f(pi0)*tanh_f(pg0);
                c[jt][1] = sigmoid_f(pf1)*c[jt][1] + sigmoid_f(pi1)*tanh_f(pg1);
                float h0 = sigmoid_f(po0)*tanh_f(c[jt][0]);
                float h1 = sigmoid_f(po1)*tanh_f(c[jt][1]);
                hs[jt][0] += h0; hs[jt][1] += h1;
                float2 v; v.x = f2tf32(h0); v.y = f2tf32(h1);
                *(float2*)&nxt[row_lo*68 + jb] = v;
            }
            // row hi (regs 2,3)
            {
                float pi0 = acc[0][jt][2] + igv[jt][0][1].x;
                float pf0 = acc[1][jt][2] + igv[jt][1][1].x;
                float pg0 = acc[2][jt][2] + igv[jt][2][1].x;
                float po0 = acc[3][jt][2] + igv[jt][3][1].x;
                float pi1 = acc[0][jt][3] + igv[jt][0][1].y;
                float pf1 = acc[1][jt][3] + igv[jt][1][1].y;
                float pg1 = acc[2][jt][3] + igv[jt][2][1].y;
                float po1 = acc[3][jt][3] + igv[jt][3][1].y;
                c[jt][2] = sigmoid_f(pf0)*c[jt][2] + sigmoid_f(pi0)*tanh_f(pg0);
                c[jt][3] = sigmoid_f(pf1)*c[jt][3] + sigmoid_f(pi1)*tanh_f(pg1);
                float h0 = sigmoid_f(po0)*tanh_f(c[jt][2]);
                float h1 = sigmoid_f(po1)*tanh_f(c[jt][3]);
                hs[jt][2] += h0; hs[jt][3] += h1;
                float2 v; v.x = f2tf32(h0); v.y = f2tf32(h1);
                *(float2*)&nxt[(row_lo+8)*68 + jb] = v;
            }
        }
        __syncthreads();   // nxt complete before it becomes cur
        float* tmp = cur; cur = nxt; nxt = tmp;
    }

    // mean over K, store
    #pragma unroll
    for (int jt=0; jt<2; jt++) {
        int jb = wj*16 + jt*8 + lc*2;
        int blo = b0 + row_lo, bhi = blo + 8;
        float2 v0; v0.x = hs[jt][0]*(1.0f/K_); v0.y = hs[jt][1]*(1.0f/K_);
        float2 v1; v1.x = hs[jt][2]*(1.0f/K_); v1.y = hs[jt][3]*(1.0f/K_);
        *(float2*)(g_AGG + ((size_t)t*B_ + blo)*128 + dir*64 + jb) = v0;
        *(float2*)(g_AGG + ((size_t)t*B_ + bhi)*128 + dir*64 + jb) = v1;
    }
}

// ---------------- stage C: attention combine (self embed gathered from CE type 0) ----------------
__global__ __launch_bounds__(256) void attn_kernel(const int* __restrict__ id_batch,
                                                   const float* __restrict__ att,
                                                   float* __restrict__ out)
{
    int warp = threadIdx.x >> 5;
    int lane = threadIdx.x & 31;
    int b = blockIdx.x*8 + warp;
    int id = id_batch[b];

    float e[12][4], a0[4], a1[4];
    #pragma unroll
    for (int i=0;i<4;i++) {
        int d = i*32 + lane;
        a0[i] = att[d];
        a1[i] = att[128+d];
        e[0][i] = g_CE[(size_t)id*128 + d];    // c_self = CE type-0 row
    }
    #pragma unroll
    for (int t=0;t<T_;t++)
        #pragma unroll
        for (int i=0;i<4;i++)
            e[1+t][i] = g_AGG[((size_t)t*B_ + b)*128 + i*32 + lane];

    float pself = 0.f;
    #pragma unroll
    for (int i=0;i<4;i++) pself += e[0][i]*a0[i];
    float sc[12];
    #pragma unroll
    for (int j=0;j<12;j++) {
        float p = 0.f;
        #pragma unroll
        for (int i=0;i<4;i++) p += e[j][i]*a1[i];
        sc[j] = p;
    }
    #pragma unroll
    for (int off=16; off>0; off>>=1) {
        pself += __shfl_xor_sync(0xffffffff, pself, off);
        #pragma unroll
        for (int j=0;j<12;j++) sc[j] += __shfl_xor_sync(0xffffffff, sc[j], off);
    }
    float mx = -1e30f;
    #pragma unroll
    for (int j=0;j<12;j++) {
        float s = pself + sc[j];
        s = (s > 0.f) ? s : 0.01f*s;    // leaky_relu(0.01)
        sc[j] = s;
        mx = fmaxf(mx, s);
    }
    float sum = 0.f;
    #pragma unroll
    for (int j=0;j<12;j++) { sc[j] = expf(sc[j]-mx); sum += sc[j]; }
    float inv = 1.f/sum;
    #pragma unroll
    for (int i=0;i<4;i++) {
        float o = 0.f;
        #pragma unroll
        for (int j=0;j<12;j++) o += sc[j]*e[j][i];
        out[(size_t)b*128 + i*32 + lane] = o*inv;
    }
}

// ---------------- launch (single stream, 5 launches) ----------------
extern "C" void kernel_launch(void* const* d_in, const int* in_sizes, int n_in,
                              void* d_out, int out_size)
{
    const float* features = (const float*)d_in[0];
    const int*   id_batch = (const int*)d_in[1];
    const int*   neigh_ids= (const int*)d_in[2];
    const float* cWih_f   = (const float*)d_in[3];
    const float* cb_f     = (const float*)d_in[5];
    const float* cWih_b   = (const float*)d_in[6];
    const float* cb_b     = (const float*)d_in[8];
    const float* nWih_f   = (const float*)d_in[9];
    const float* nWhh_f   = (const float*)d_in[10];
    const float* nb_f     = (const float*)d_in[11];
    const float* nWih_b   = (const float*)d_in[12];
    const float* nWhh_b   = (const float*)d_in[13];
    const float* nb_b     = (const float*)d_in[14];
    const float* att      = (const float*)d_in[15];
    float* out = (float*)d_out;

    const int SMEM_CONTENT = (64*132 + 16*200) * 4;             // 46592
    const int SMEM_IG      = (64*132 + 16*136) * 4;             // 42496
    const int SMEM_RECUR   = (64*264 + 2*32*68 + 32*K_) * 4;    // 86272
    cudaFuncSetAttribute(content_kernel, cudaFuncAttributeMaxDynamicSharedMemorySize, SMEM_CONTENT);
    cudaFuncSetAttribute(ig_kernel,      cudaFuncAttributeMaxDynamicSharedMemorySize, SMEM_IG);
    cudaFuncSetAttribute(recur_kernel,   cudaFuncAttributeMaxDynamicSharedMemorySize, SMEM_RECUR);

    pack_kernel<<<512, 256>>>(cWih_f, cb_f, cWih_b, cb_b,
                              nWih_f, nb_f, nWih_b, nb_b, nWhh_f, nWhh_b);

    {   // content encode, all types
        dim3 g(MROW_BLKS, 2, T_);
        content_kernel<<<g, 256, SMEM_CONTENT>>>(features);
    }
    {   // seq-LSTM input projections, all types
        dim3 g(MROW_BLKS, 4, T_);
        ig_kernel<<<g, 256, SMEM_IG>>>();
    }
    {   // recurrence, all types
        dim3 g(B_/32, 2, T_);
        recur_kernel<<<g, 256, SMEM_RECUR>>>(neigh_ids);
    }
    attn_kernel<<<B_/8, 256>>>(id_batch, att, out);
}

// round 13
// speedup vs baseline: 8.5638x; 1.2339x over previous
#include <cuda_runtime.h>
#include <cuda_fp16.h>
#include <stdint.h>
#include <stddef.h>
#include <math.h>

#define T_ 11
#define N_NODES 50000
#define D_ 128
#define H_ 64
#define B_ 16384
#define K_ 10
#define MROW_BLKS 782    // ceil(50000/64)

// ---------------- scratch (device globals; ~1.43 GB total, < 2GB reloc limit) ----------------
__device__ float g_W1[(size_t)T_*128*384];     // packed content Wih (gates i,g,o x 2 dirs), tf32-rounded
__device__ float g_B1[T_*384];
__device__ float g_W2[(size_t)T_*128*512];     // packed seq Wih (4 gates x 2 dirs), tf32-rounded
__device__ float g_B2[T_*512];
__device__ uint32_t g_WhhH[(size_t)T_*2*32*256]; // [t][dir][k2=32][n=256] half2 (k-pairs), mma-B layout
__device__ float g_CE[(size_t)T_*N_NODES*128]; // per-node content encodings, ALL types (282 MB)
__device__ float g_IG[(size_t)T_*N_NODES*512]; // per-node seq-LSTM preacts, ALL types (1.13 GB)
__device__ float g_AGG[(size_t)T_*B_*128];

// HW tanh (MUFU.TANH, sm_75+)
__device__ __forceinline__ float tanh_f(float x){
    float r; asm("tanh.approx.f32 %0, %1;" : "=f"(r) : "f"(x)); return r;
}
__device__ __forceinline__ float sigmoid_f(float x){
    float r; asm("tanh.approx.f32 %0, %1;" : "=f"(r) : "f"(0.5f*x));
    return fmaf(0.5f, r, 0.5f);
}
__device__ __forceinline__ float f2tf32(float x){
    uint32_t r;
    asm("cvt.rna.tf32.f32 %0, %1;" : "=r"(r) : "f"(x));
    return __uint_as_float(r);
}
__device__ __forceinline__ void mma_tf32(float& c0, float& c1, float& c2, float& c3,
                                         uint32_t a0, uint32_t a1, uint32_t a2, uint32_t a3,
                                         uint32_t b0, uint32_t b1){
    asm volatile("mma.sync.aligned.m16n8k8.row.col.f32.tf32.tf32.f32 "
                 "{%0,%1,%2,%3},{%4,%5,%6,%7},{%8,%9},{%0,%1,%2,%3};"
                 : "+f"(c0), "+f"(c1), "+f"(c2), "+f"(c3)
                 : "r"(a0), "r"(a1), "r"(a2), "r"(a3), "r"(b0), "r"(b1));
}
__device__ __forceinline__ void mma_f16(float& c0, float& c1, float& c2, float& c3,
                                        uint32_t a0, uint32_t a1, uint32_t a2, uint32_t a3,
                                        uint32_t b0, uint32_t b1){
    asm volatile("mma.sync.aligned.m16n8k16.row.col.f32.f16.f16.f32 "
                 "{%0,%1,%2,%3},{%4,%5,%6,%7},{%8,%9},{%0,%1,%2,%3};"
                 : "+f"(c0), "+f"(c1), "+f"(c2), "+f"(c3)
                 : "r"(a0), "r"(a1), "r"(a2), "r"(a3), "r"(b0), "r"(b1));
}
__device__ __forceinline__ uint32_t pack_h2(float a, float b){
    __half2 p = __floats2half2_rn(a, b);
    return *reinterpret_cast<uint32_t*>(&p);
}

// ---------------- weight packing ----------------
__global__ void pack_kernel(const float* __restrict__ cWih_f, const float* __restrict__ cb_f,
                            const float* __restrict__ cWih_b, const float* __restrict__ cb_b,
                            const float* __restrict__ nWih_f, const float* __restrict__ nb_f,
                            const float* __restrict__ nWih_b, const float* __restrict__ nb_b,
                            const float* __restrict__ nWhh_f, const float* __restrict__ nWhh_b)
{
    int stride = gridDim.x*blockDim.x;
    int tid0 = blockIdx.x*blockDim.x + threadIdx.x;

    // W1: [t][kk][n], n = dir*192 + gate*64 + j, gate 0:i 1:g 2:o (f-gate dead: zero state)
    for (size_t idx = tid0; idx < (size_t)T_*128*384; idx += stride) {
        int n = (int)(idx % 384); size_t rest = idx / 384;
        int kk = (int)(rest % 128); int t = (int)(rest / 128);
        int dir = n/192, rem = n%192, g = rem/64, j = rem%64;
        int row = (g==0) ? j : (g==1) ? 128+j : 192+j;
        const float* W = dir ? cWih_b : cWih_f;
        g_W1[idx] = f2tf32(W[((size_t)t*256 + row)*128 + kk]);
    }
    for (int idx = tid0; idx < T_*384; idx += stride) {
        int n = idx % 384; int t = idx / 384;
        int dir = n/192, rem = n%192, g = rem/64, j = rem%64;
        int row = (g==0) ? j : (g==1) ? 128+j : 192+j;
        g_B1[idx] = (dir ? cb_b : cb_f)[t*256 + row];
    }
    // W2: [t][kk][n], n = dir*256 + r  (natural gate rows i,f,g,o)
    for (size_t idx = tid0; idx < (size_t)T_*128*512; idx += stride) {
        int n = (int)(idx % 512); size_t rest = idx/512;
        int kk = (int)(rest % 128); int t = (int)(rest/128);
        int dir = n/256, r = n%256;
        const float* W = dir ? nWih_b : nWih_f;
        g_W2[idx] = f2tf32(W[((size_t)t*256 + r)*128 + kk]);
    }
    for (int idx = tid0; idx < T_*512; idx += stride) {
        int n = idx % 512; int t = idx/512;
        int dir = n/256, r = n%256;
        g_B2[idx] = (dir ? nb_b : nb_f)[t*256 + r];
    }
    // Whh half2 mma-B layout: word(k2,n) = half2(W[n][2k2], W[n][2k2+1])
    for (size_t idx = tid0; idx < (size_t)T_*2*32*256; idx += stride) {
        int n = (int)(idx % 256); size_t rest = idx/256;
        int k2 = (int)(rest % 32); rest /= 32;
        int dir = (int)(rest % 2); int t = (int)(rest/2);
        const float* W = dir ? nWhh_b : nWhh_f;
        float w0 = W[((size_t)t*256 + n)*64 + 2*k2];
        float w1 = W[((size_t)t*256 + n)*64 + 2*k2 + 1];
        g_WhhH[idx] = pack_h2(w0, w1);
    }
}

// ---------------- stage A: dense per-node content encode, ALL types ----------------
// grid (782, 2 dirs, 11 types); block 256 (8 warps); block tile 64(M) x 192(N); smem ~46.6 KB
__global__ __launch_bounds__(256) void content_kernel(const float* __restrict__ features)
{
    extern __shared__ float sm[];
    float* As  = sm;             // [64][132]  row-major, tf32-rounded
    float* W1s = sm + 64*132;    // [16][200]  k-chunk of weights

    int t = blockIdx.z;
    const float* feat = features + (size_t)t*N_NODES*128;
    float* ce = g_CE + (size_t)t*N_NODES*128;
    int dir = blockIdx.y;
    int m0 = blockIdx.x*64;
    int tid = threadIdx.x;
    int warp = tid >> 5, lane = tid & 31;
    int wm = warp >> 2;          // 0..1 : 32-row half
    int wj = warp & 3;           // 0..3 : 16-j slice
    int lr = lane >> 2;          // 0..7
    int lc = lane & 3;           // 0..3

    {   // stage A (64x128) row-major with tf32 rounding; clamp tail rows
        int rl = tid >> 5, c4 = tid & 31;
        #pragma unroll
        for (int it = 0; it < 8; it++) {
            int r = rl + it*8;
            int row = m0 + r; if (row >= N_NODES) row = N_NODES-1;
            float4 v = *(const float4*)(feat + (size_t)row*128 + c4*4);
            float4 o; o.x=f2tf32(v.x); o.y=f2tf32(v.y); o.z=f2tf32(v.z); o.w=f2tf32(v.w);
            *(float4*)&As[r*132 + c4*4] = o;
        }
    }

    float acc[2][3][2][4];   // [mtile][gate][jtile][c-regs]
    #pragma unroll
    for (int mt=0;mt<2;mt++)
        #pragma unroll
        for (int g=0;g<3;g++)
            #pragma unroll
            for (int jt=0;jt<2;jt++)
                #pragma unroll
                for (int r=0;r<4;r++) acc[mt][g][jt][r]=0.f;

    const float* W1t = g_W1 + (size_t)t*128*384 + dir*192;

    for (int kc = 0; kc < 8; kc++) {     // 16 k-rows per chunk
        __syncthreads();
        for (int it = 0; it < 3; it++) {          // 16x48 float4 = 768
            int idx = tid + it*256;
            int kk = idx / 48, c4 = idx % 48;
            float4 v = *(const float4*)(W1t + (size_t)(kc*16+kk)*384 + c4*4);
            *(float4*)&W1s[kk*200 + c4*4] = v;    // already tf32-rounded in pack
        }
        __syncthreads();
        #pragma unroll
        for (int k8 = 0; k8 < 2; k8++) {
            int kb = k8*8;
            uint32_t a[2][4];
            #pragma unroll
            for (int mt=0; mt<2; mt++) {
                const float* Ab = As + (wm*32 + mt*16)*132 + kc*16 + kb;
                a[mt][0] = __float_as_uint(Ab[lr*132 + lc]);
                a[mt][1] = __float_as_uint(Ab[(lr+8)*132 + lc]);
                a[mt][2] = __float_as_uint(Ab[lr*132 + lc+4]);
                a[mt][3] = __float_as_uint(Ab[(lr+8)*132 + lc+4]);
            }
            uint32_t b[3][2][2];
            #pragma unroll
            for (int g=0; g<3; g++)
                #pragma unroll
                for (int jt=0; jt<2; jt++) {
                    const float* Bb = W1s + kb*200 + g*64 + wj*16 + jt*8;
                    b[g][jt][0] = __float_as_uint(Bb[lc*200 + lr]);
                    b[g][jt][1] = __float_as_uint(Bb[(lc+4)*200 + lr]);
                }
            #pragma unroll
            for (int mt=0; mt<2; mt++)
                #pragma unroll
                for (int g=0; g<3; g++)
                    #pragma unroll
                    for (int jt=0; jt<2; jt++)
                        mma_tf32(acc[mt][g][jt][0], acc[mt][g][jt][1],
                                 acc[mt][g][jt][2], acc[mt][g][jt][3],
                                 a[mt][0], a[mt][1], a[mt][2], a[mt][3],
                                 b[g][jt][0], b[g][jt][1]);
        }
    }

    // epilogue: bias + LSTM nonlinearity, store CE
    const float* B1t = g_B1 + t*384 + dir*192;
    #pragma unroll
    for (int mt=0; mt<2; mt++) {
        #pragma unroll
        for (int jt=0; jt<2; jt++) {
            int j = wj*16 + jt*8 + lc*2;
            float bi0 = B1t[j],     bi1 = B1t[j+1];
            float bg0 = B1t[64+j],  bg1 = B1t[64+j+1];
            float bo0 = B1t[128+j], bo1 = B1t[128+j+1];
            int r0 = m0 + wm*32 + mt*16 + lr;
            int r1 = r0 + 8;
            if (r0 < N_NODES) {
                float cc0 = sigmoid_f(acc[mt][0][jt][0]+bi0) * tanh_f(acc[mt][1][jt][0]+bg0);
                float cc1 = sigmoid_f(acc[mt][0][jt][1]+bi1) * tanh_f(acc[mt][1][jt][1]+bg1);
                float2 v;
                v.x = sigmoid_f(acc[mt][2][jt][0]+bo0) * tanh_f(cc0);
                v.y = sigmoid_f(acc[mt][2][jt][1]+bo1) * tanh_f(cc1);
                *(float2*)(ce + (size_t)r0*128 + dir*64 + j) = v;
            }
            if (r1 < N_NODES) {
                float cc0 = sigmoid_f(acc[mt][0][jt][2]+bi0) * tanh_f(acc[mt][1][jt][2]+bg0);
                float cc1 = sigmoid_f(acc[mt][0][jt][3]+bi1) * tanh_f(acc[mt][1][jt][3]+bg1);
                float2 v;
                v.x = sigmoid_f(acc[mt][2][jt][2]+bo0) * tanh_f(cc0);
                v.y = sigmoid_f(acc[mt][2][jt][3]+bo1) * tanh_f(cc1);
                *(float2*)(ce + (size_t)r1*128 + dir*64 + j) = v;
            }
        }
    }
}

// ---------------- stage B1: per-node seq-LSTM input projection, ALL types ----------------
// grid (782, 4, 11); block 256 (8 warps); block tile 64(M) x 128(N); smem ~42.5 KB
__global__ __launch_bounds__(256) void ig_kernel()
{
    extern __shared__ float sm[];
    float* As = sm;             // [64][132]
    float* Ws = sm + 64*132;    // [16][136]

    int t = blockIdx.z;
    const float* ce = g_CE + (size_t)t*N_NODES*128;
    float* igb = g_IG + (size_t)t*N_NODES*512;
    int nt = blockIdx.y;        // 0..3 : 128-col chunk of 512
    int m0 = blockIdx.x*64;
    int tid = threadIdx.x;
    int warp = tid >> 5, lane = tid & 31;
    int wm = warp >> 2;         // 0..1 : 32-row half
    int wn = warp & 3;          // 0..3 : 32-col slice
    int lr = lane >> 2;
    int lc = lane & 3;

    {   // stage CE tile (64x128) row-major with tf32 rounding
        int rl = tid >> 5, c4 = tid & 31;
        #pragma unroll
        for (int it=0; it<8; it++) {
            int r = rl + it*8;
            int row = m0 + r; if (row >= N_NODES) row = N_NODES-1;
            float4 v = *(const float4*)(ce + (size_t)row*128 + c4*4);
            float4 o; o.x=f2tf32(v.x); o.y=f2tf32(v.y); o.z=f2tf32(v.z); o.w=f2tf32(v.w);
            *(float4*)&As[r*132 + c4*4] = o;
        }
    }

    float acc[2][4][4];   // [mtile][ntile][c-regs]
    #pragma unroll
    for (int mt=0;mt<2;mt++)
        #pragma unroll
        for (int n8=0;n8<4;n8++)
            #pragma unroll
            for (int r=0;r<4;r++) acc[mt][n8][r]=0.f;

    const float* W2t = g_W2 + (size_t)t*128*512 + nt*128;

    for (int kc=0; kc<8; kc++) {        // 16 k-rows per chunk
        __syncthreads();
        for (int it=0; it<2; it++) {     // 16x32 float4 = 512
            int idx = tid + it*256;
            int kk = idx >> 5, c4 = idx & 31;
            float4 v = *(const float4*)(W2t + (size_t)(kc*16+kk)*512 + c4*4);
            *(float4*)&Ws[kk*136 + c4*4] = v;
        }
        __syncthreads();
        #pragma unroll
        for (int k8=0; k8<2; k8++) {
            int kb = k8*8;
            uint32_t a[2][4];
            #pragma unroll
            for (int mt=0; mt<2; mt++) {
                const float* Ab = As + (wm*32 + mt*16)*132 + kc*16 + kb;
                a[mt][0] = __float_as_uint(Ab[lr*132 + lc]);
                a[mt][1] = __float_as_uint(Ab[(lr+8)*132 + lc]);
                a[mt][2] = __float_as_uint(Ab[lr*132 + lc+4]);
                a[mt][3] = __float_as_uint(Ab[(lr+8)*132 + lc+4]);
            }
            uint32_t b[4][2];
            #pragma unroll
            for (int n8=0; n8<4; n8++) {
                const float* Bb = Ws + kb*136 + wn*32 + n8*8;
                b[n8][0] = __float_as_uint(Bb[lc*136 + lr]);
                b[n8][1] = __float_as_uint(Bb[(lc+4)*136 + lr]);
            }
            #pragma unroll
            for (int mt=0; mt<2; mt++)
                #pragma unroll
                for (int n8=0; n8<4; n8++)
                    mma_tf32(acc[mt][n8][0], acc[mt][n8][1], acc[mt][n8][2], acc[mt][n8][3],
                             a[mt][0], a[mt][1], a[mt][2], a[mt][3],
                             b[n8][0], b[n8][1]);
        }
    }

    const float* B2t = g_B2 + t*512;
    #pragma unroll
    for (int mt=0; mt<2; mt++) {
        #pragma unroll
        for (int n8=0; n8<4; n8++) {
            int ncol = nt*128 + wn*32 + n8*8 + lc*2;
            float b0 = B2t[ncol], b1 = B2t[ncol+1];
            int r0 = m0 + wm*32 + mt*16 + lr;
            int r1 = r0 + 8;
            if (r0 < N_NODES) {
                float2 v; v.x = acc[mt][n8][0]+b0; v.y = acc[mt][n8][1]+b1;
                *(float2*)(igb + (size_t)r0*512 + ncol) = v;
            }
            if (r1 < N_NODES) {
                float2 v; v.x = acc[mt][n8][2]+b0; v.y = acc[mt][n8][3]+b1;
                *(float2*)(igb + (size_t)r1*512 + ncol) = v;
            }
        }
    }
}

// ---------------- stage B2: fp16 tensor-core LSTM recurrence over K=10, ALL types ----------------
// grid (512, 2 dirs, 11 types); block 256 (8 warps); 32 batch rows/block; smem ~44.3 KB
// per step: g = IG(gather) + h @ WhhT via m16n8k16 f16 mma; c/hs fp32 regs; h stored half2
__global__ __launch_bounds__(256, 3) void recur_kernel(const int* __restrict__ neigh_ids)
{
    extern __shared__ float sm[];
    uint32_t* smw = (uint32_t*)sm;
    uint32_t* Whh_s = smw;               // [32 k2][264] half2 words (pad 264: 8lc+lr banks)
    uint32_t* hA0 = smw + 32*264;        // [32 rows][36] half2 words (pad 36: 4lr+lc banks)
    uint32_t* hA1 = hA0 + 32*36;
    int* ids_s = (int*)(hA1 + 32*36);    // [32][10]

    int t = blockIdx.z;
    int dir = blockIdx.y;
    int b0 = blockIdx.x*32;
    int tid = threadIdx.x;
    int warp = tid >> 5, lane = tid & 31;
    int wm = warp >> 2;            // 0..1
    int wj = warp & 3;             // 0..3
    int lr = lane >> 2, lc = lane & 3;

    // stage Whh half2 [32][256] -> smem [32][264]
    const uint32_t* Wsrc = g_WhhH + ((size_t)t*2 + dir)*32*256;
    #pragma unroll
    for (int it=0; it<8; it++) {          // 2048 uint4
        int idx = tid + it*256;
        int k2 = idx >> 6, c4 = idx & 63;
        uint4 v = *(const uint4*)(Wsrc + (size_t)k2*256 + c4*4);
        *(uint4*)&Whh_s[k2*264 + c4*4] = v;
    }
    for (int idx = tid; idx < 32*36; idx += 256) hA0[idx] = 0u;   // h=0 (half2 zero)
    {
        const int* nsrc = neigh_ids + ((size_t)t*B_ + b0)*K_;
        for (int idx = tid; idx < 32*K_; idx += 256) ids_s[idx] = nsrc[idx];
    }
    __syncthreads();

    const float* ig = g_IG + (size_t)t*N_NODES*512 + dir*256;
    int row_lo = wm*16 + lr;               // block-local rows: row_lo, row_lo+8

    float c[2][4], hs[2][4];               // [jt][0:lo/j0 1:lo/j1 2:hi/j0 3:hi/j1]
    #pragma unroll
    for (int jt=0;jt<2;jt++)
        #pragma unroll
        for (int e=0;e<4;e++){ c[jt][e]=0.f; hs[jt][e]=0.f; }

    uint32_t* cur = hA0; uint32_t* nxt = hA1;

    for (int step=0; step<K_; step++) {
        int k = dir ? (K_-1-step) : step;
        int id_lo = ids_s[row_lo*K_ + k];
        int id_hi = ids_s[(row_lo+8)*K_ + k];
        const float* ig_lo = ig + (size_t)id_lo*512;
        const float* ig_hi = ig + (size_t)id_hi*512;

        // prefetch jt=0 IG preacts (latency hidden under mma stream)
        float2 igv0[4][2];
        {
            int jb = wj*16 + lc*2;
            #pragma unroll
            for (int g=0; g<4; g++) {
                igv0[g][0] = *(const float2*)(ig_lo + g*64 + jb);
                igv0[g][1] = *(const float2*)(ig_hi + g*64 + jb);
            }
        }

        // acc = h_prev @ WhhT  (f16 m16n8k16 mma)
        float acc[4][2][4];                // [gate][jt][c-regs]
        #pragma unroll
        for (int g=0;g<4;g++)
            #pragma unroll
            for (int jt=0;jt<2;jt++)
                #pragma unroll
                for (int r=0;r<4;r++) acc[g][jt][r]=0.f;

        #pragma unroll
        for (int kit=0; kit<4; kit++) {
            int kb2 = kit*8;               // word offset (16 halves per mma = 8 words)
            uint32_t a0 = cur[row_lo*36 + kb2 + lc];
            uint32_t a1 = cur[(row_lo+8)*36 + kb2 + lc];
            uint32_t a2 = cur[row_lo*36 + kb2 + lc + 4];
            uint32_t a3 = cur[(row_lo+8)*36 + kb2 + lc + 4];
            #pragma unroll
            for (int g=0; g<4; g++)
                #pragma unroll
                for (int jt=0; jt<2; jt++) {
                    int nb = g*64 + wj*16 + jt*8;
                    uint32_t bb0 = Whh_s[(kb2+lc)*264 + nb + lr];
                    uint32_t bb1 = Whh_s[(kb2+lc+4)*264 + nb + lr];
                    mma_f16(acc[g][jt][0], acc[g][jt][1], acc[g][jt][2], acc[g][jt][3],
                            a0, a1, a2, a3, bb0, bb1);
                }
        }

        // load jt=1 IG preacts (overlaps jt=0 epilogue compute)
        float2 igv1[4][2];
        {
            int jb = wj*16 + 8 + lc*2;
            #pragma unroll
            for (int g=0; g<4; g++) {
                igv1[g][0] = *(const float2*)(ig_lo + g*64 + jb);
                igv1[g][1] = *(const float2*)(ig_hi + g*64 + jb);
            }
        }

        // epilogue: gates, state update, h -> nxt (half2)
        #pragma unroll
        for (int jt=0; jt<2; jt++) {
            float2 (*igv)[2] = jt ? igv1 : igv0;
            int jw = wj*8 + jt*4 + lc;     // half2 word index of cols (jb, jb+1)
            // row lo (regs 0,1)
            {
                float pi0 = acc[0][jt][0] + igv[0][0].x;
                float pf0 = acc[1][jt][0] + igv[1][0].x;
                float pg0 = acc[2][jt][0] + igv[2][0].x;
                float po0 = acc[3][jt][0] + igv[3][0].x;
                float pi1 = acc[0][jt][1] + igv[0][0].y;
                float pf1 = acc[1][jt][1] + igv[1][0].y;
                float pg1 = acc[2][jt][1] + igv[2][0].y;
                float po1 = acc[3][jt][1] + igv[3][0].y;
                c[jt][0] = sigmoid_f(pf0)*c[jt][0] + sigmoid_f(pi0)*tanh_f(pg0);
                c[jt][1] = sigmoid_f(pf1)*c[jt][1] + sigmoid_f(pi1)*tanh_f(pg1);
                float h0 = sigmoid_f(po0)*tanh_f(c[jt][0]);
                float h1 = sigmoid_f(po1)*tanh_f(c[jt][1]);
                hs[jt][0] += h0; hs[jt][1] += h1;
                nxt[row_lo*36 + jw] = pack_h2(h0, h1);
            }
            // row hi (regs 2,3)
            {
                float pi0 = acc[0][jt][2] + igv[0][1].x;
                float pf0 = acc[1][jt][2] + igv[1][1].x;
                float pg0 = acc[2][jt][2] + igv[2][1].x;
                float po0 = acc[3][jt][2] + igv[3][1].x;
                float pi1 = acc[0][jt][3] + igv[0][1].y;
                float pf1 = acc[1][jt][3] + igv[1][1].y;
                float pg1 = acc[2][jt][3] + igv[2][1].y;
                float po1 = acc[3][jt][3] + igv[3][1].y;
                c[jt][2] = sigmoid_f(pf0)*c[jt][2] + sigmoid_f(pi0)*tanh_f(pg0);
                c[jt][3] = sigmoid_f(pf1)*c[jt][3] + sigmoid_f(pi1)*tanh_f(pg1);
                float h0 = sigmoid_f(po0)*tanh_f(c[jt][2]);
                float h1 = sigmoid_f(po1)*tanh_f(c[jt][3]);
                hs[jt][2] += h0; hs[jt][3] += h1;
                nxt[(row_lo+8)*36 + jw] = pack_h2(h0, h1);
            }
        }
        __syncthreads();   // nxt complete before it becomes cur (single barrier per step)
        uint32_t* tmp = cur; cur = nxt; nxt = tmp;
    }

    // mean over K, store
    #pragma unroll
    for (int jt=0; jt<2; jt++) {
        int jb = wj*16 + jt*8 + lc*2;
        int blo = b0 + row_lo, bhi = blo + 8;
        float2 v0; v0.x = hs[jt][0]*(1.0f/K_); v0.y = hs[jt][1]*(1.0f/K_);
        float2 v1; v1.x = hs[jt][2]*(1.0f/K_); v1.y = hs[jt][3]*(1.0f/K_);
        *(float2*)(g_AGG + ((size_t)t*B_ + blo)*128 + dir*64 + jb) = v0;
        *(float2*)(g_AGG + ((size_t)t*B_ + bhi)*128 + dir*64 + jb) = v1;
    }
}

// ---------------- stage C: attention combine (self embed gathered from CE type 0) ----------------
__global__ __launch_bounds__(256) void attn_kernel(const int* __restrict__ id_batch,
                                                   const float* __restrict__ att,
                                                   float* __restrict__ out)
{
    int warp = threadIdx.x >> 5;
    int lane = threadIdx.x & 31;
    int b = blockIdx.x*8 + warp;
    int id = id_batch[b];

    float e[12][4], a0[4], a1[4];
    #pragma unroll
    for (int i=0;i<4;i++) {
        int d = i*32 + lane;
        a0[i] = att[d];
        a1[i] = att[128+d];
        e[0][i] = g_CE[(size_t)id*128 + d];    // c_self = CE type-0 row
    }
    #pragma unroll
    for (int t=0;t<T_;t++)
        #pragma unroll
        for (int i=0;i<4;i++)
            e[1+t][i] = g_AGG[((size_t)t*B_ + b)*128 + i*32 + lane];

    float pself = 0.f;
    #pragma unroll
    for (int i=0;i<4;i++) pself += e[0][i]*a0[i];
    float sc[12];
    #pragma unroll
    for (int j=0;j<12;j++) {
        float p = 0.f;
        #pragma unroll
        for (int i=0;i<4;i++) p += e[j][i]*a1[i];
        sc[j] = p;
    }
    #pragma unroll
    for (int off=16; off>0; off>>=1) {
        pself += __shfl_xor_sync(0xffffffff, pself, off);
        #pragma unroll
        for (int j=0;j<12;j++) sc[j] += __shfl_xor_sync(0xffffffff, sc[j], off);
    }
    float mx = -1e30f;
    #pragma unroll
    for (int j=0;j<12;j++) {
        float s = pself + sc[j];
        s = (s > 0.f) ? s : 0.01f*s;    // leaky_relu(0.01)
        sc[j] = s;
        mx = fmaxf(mx, s);
    }
    float sum = 0.f;
    #pragma unroll
    for (int j=0;j<12;j++) { sc[j] = expf(sc[j]-mx); sum += sc[j]; }
    float inv = 1.f/sum;
    #pragma unroll
    for (int i=0;i<4;i++) {
        float o = 0.f;
        #pragma unroll
        for (int j=0;j<12;j++) o += sc[j]*e[j][i];
        out[(size_t)b*128 + i*32 + lane] = o*inv;
    }
}

// ---------------- launch (single stream, 5 launches) ----------------
extern "C" void kernel_launch(void* const* d_in, const int* in_sizes, int n_in,
                              void* d_out, int out_size)
{
    const float* features = (const float*)d_in[0];
    const int*   id_batch = (const int*)d_in[1];
    const int*   neigh_ids= (const int*)d_in[2];
    const float* cWih_f   = (const float*)d_in[3];
    const float* cb_f     = (const float*)d_in[5];
    const float* cWih_b   = (const float*)d_in[6];
    const float* cb_b     = (const float*)d_in[8];
    const float* nWih_f   = (const float*)d_in[9];
    const float* nWhh_f   = (const float*)d_in[10];
    const float* nb_f     = (const float*)d_in[11];
    const float* nWih_b   = (const float*)d_in[12];
    const float* nWhh_b   = (const float*)d_in[13];
    const float* nb_b     = (const float*)d_in[14];
    const float* att      = (const float*)d_in[15];
    float* out = (float*)d_out;

    const int SMEM_CONTENT = (64*132 + 16*200) * 4;             // 46592
    const int SMEM_IG      = (64*132 + 16*136) * 4;             // 42496
    const int SMEM_RECUR   = (32*264 + 2*32*36 + 32*K_) * 4;    // 44288
    cudaFuncSetAttribute(content_kernel, cudaFuncAttributeMaxDynamicSharedMemorySize, SMEM_CONTENT);
    cudaFuncSetAttribute(ig_kernel,      cudaFuncAttributeMaxDynamicSharedMemorySize, SMEM_IG);
    cudaFuncSetAttribute(recur_kernel,   cudaFuncAttributeMaxDynamicSharedMemorySize, SMEM_RECUR);

    pack_kernel<<<512, 256>>>(cWih_f, cb_f, cWih_b, cb_b,
                              nWih_f, nb_f, nWih_b, nb_b, nWhh_f, nWhh_b);

    {   // content encode, all types
        dim3 g(MROW_BLKS, 2, T_);
        content_kernel<<<g, 256, SMEM_CONTENT>>>(features);
    }
    {   // seq-LSTM input projections, all types
        dim3 g(MROW_BLKS, 4, T_);
        ig_kernel<<<g, 256, SMEM_IG>>>();
    }
    {   // recurrence, all types
        dim3 g(B_/32, 2, T_);
        recur_kernel<<<g, 256, SMEM_RECUR>>>(neigh_ids);
    }
    attn_kernel<<<B_/8, 256>>>(id_batch, att, out);
}

// round 14
// speedup vs baseline: 10.5837x; 1.2359x over previous
#include <cuda_runtime.h>
#include <cuda_fp16.h>
#include <stdint.h>
#include <stddef.h>
#include <math.h>

#define T_ 11
#define N_NODES 50000
#define D_ 128
#define H_ 64
#define B_ 16384
#define K_ 10
#define MROW_BLKS 782    // ceil(50000/64)

// ---------------- scratch (device globals; ~1.43 GB total, < 2GB reloc limit) ----------------
__device__ uint32_t g_W1H[(size_t)T_*64*384];  // content Wih half2 k-pairs: [t][k2][n], n = dir*192+gate*64+j
__device__ float    g_B1[T_*384];
__device__ uint32_t g_W2H[(size_t)T_*64*512];  // seq Wih half2 k-pairs: [t][k2][n], n = dir*256+r
__device__ float    g_B2[T_*512];
__device__ uint32_t g_WhhH[(size_t)T_*2*32*256]; // [t][dir][k2][n=256] half2 (k-pairs), mma-B layout
__device__ float g_CE[(size_t)T_*N_NODES*128]; // per-node content encodings, ALL types (282 MB) — fp32
__device__ float g_IG[(size_t)T_*N_NODES*512]; // per-node seq-LSTM preacts, ALL types (1.13 GB)
__device__ float g_AGG[(size_t)T_*B_*128];

// HW tanh (MUFU.TANH, sm_75+)
__device__ __forceinline__ float tanh_f(float x){
    float r; asm("tanh.approx.f32 %0, %1;" : "=f"(r) : "f"(x)); return r;
}
__device__ __forceinline__ float sigmoid_f(float x){
    float r; asm("tanh.approx.f32 %0, %1;" : "=f"(r) : "f"(0.5f*x));
    return fmaf(0.5f, r, 0.5f);
}
__device__ __forceinline__ void mma_f16(float& c0, float& c1, float& c2, float& c3,
                                        uint32_t a0, uint32_t a1, uint32_t a2, uint32_t a3,
                                        uint32_t b0, uint32_t b1){
    asm volatile("mma.sync.aligned.m16n8k16.row.col.f32.f16.f16.f32 "
                 "{%0,%1,%2,%3},{%4,%5,%6,%7},{%8,%9},{%0,%1,%2,%3};"
                 : "+f"(c0), "+f"(c1), "+f"(c2), "+f"(c3)
                 : "r"(a0), "r"(a1), "r"(a2), "r"(a3), "r"(b0), "r"(b1));
}
__device__ __forceinline__ uint32_t pack_h2(float a, float b){
    __half2 p = __floats2half2_rn(a, b);
    return *reinterpret_cast<uint32_t*>(&p);
}

// ---------------- weight packing (all mma operands half2 k-pair packed) ----------------
__global__ void pack_kernel(const float* __restrict__ cWih_f, const float* __restrict__ cb_f,
                            const float* __restrict__ cWih_b, const float* __restrict__ cb_b,
                            const float* __restrict__ nWih_f, const float* __restrict__ nb_f,
                            const float* __restrict__ nWih_b, const float* __restrict__ nb_b,
                            const float* __restrict__ nWhh_f, const float* __restrict__ nWhh_b)
{
    int stride = gridDim.x*blockDim.x;
    int tid0 = blockIdx.x*blockDim.x + threadIdx.x;

    // W1H: [t][k2][n], n = dir*192 + gate*64 + j, gate 0:i 1:g 2:o (f-gate dead: zero state)
    for (size_t idx = tid0; idx < (size_t)T_*64*384; idx += stride) {
        int n = (int)(idx % 384); size_t rest = idx / 384;
        int k2 = (int)(rest % 64); int t = (int)(rest / 64);
        int dir = n/192, rem = n%192, g = rem/64, j = rem%64;
        int row = (g==0) ? j : (g==1) ? 128+j : 192+j;
        const float* W = dir ? cWih_b : cWih_f;
        float w0 = W[((size_t)t*256 + row)*128 + 2*k2];
        float w1 = W[((size_t)t*256 + row)*128 + 2*k2 + 1];
        g_W1H[idx] = pack_h2(w0, w1);
    }
    for (int idx = tid0; idx < T_*384; idx += stride) {
        int n = idx % 384; int t = idx / 384;
        int dir = n/192, rem = n%192, g = rem/64, j = rem%64;
        int row = (g==0) ? j : (g==1) ? 128+j : 192+j;
        g_B1[idx] = (dir ? cb_b : cb_f)[t*256 + row];
    }
    // W2H: [t][k2][n], n = dir*256 + r  (natural gate rows i,f,g,o)
    for (size_t idx = tid0; idx < (size_t)T_*64*512; idx += stride) {
        int n = (int)(idx % 512); size_t rest = idx/512;
        int k2 = (int)(rest % 64); int t = (int)(rest/64);
        int dir = n/256, r = n%256;
        const float* W = dir ? nWih_b : nWih_f;
        float w0 = W[((size_t)t*256 + r)*128 + 2*k2];
        float w1 = W[((size_t)t*256 + r)*128 + 2*k2 + 1];
        g_W2H[idx] = pack_h2(w0, w1);
    }
    for (int idx = tid0; idx < T_*512; idx += stride) {
        int n = idx % 512; int t = idx/512;
        int dir = n/256, r = n%256;
        g_B2[idx] = (dir ? nb_b : nb_f)[t*256 + r];
    }
    // Whh half2 mma-B layout: word(k2,n) = half2(W[n][2k2], W[n][2k2+1])
    for (size_t idx = tid0; idx < (size_t)T_*2*32*256; idx += stride) {
        int n = (int)(idx % 256); size_t rest = idx/256;
        int k2 = (int)(rest % 32); rest /= 32;
        int dir = (int)(rest % 2); int t = (int)(rest/2);
        const float* W = dir ? nWhh_b : nWhh_f;
        float w0 = W[((size_t)t*256 + n)*64 + 2*k2];
        float w1 = W[((size_t)t*256 + n)*64 + 2*k2 + 1];
        g_WhhH[idx] = pack_h2(w0, w1);
    }
}

// ---------------- stage A: dense per-node content encode, ALL types (fp16 mma) ----------------
// grid (782, 2 dirs, 11 types); block 256 (8 warps); tile 64(M) x 192(N); smem ~30.2 KB
__global__ __launch_bounds__(256) void content_kernel(const float* __restrict__ features)
{
    extern __shared__ float sm[];
    uint32_t* As  = (uint32_t*)sm;      // [64 rows][68] half2 words (64 used)
    uint32_t* W1s = As + 64*68;         // [16 k2][200] half2 words (192 used)

    int t = blockIdx.z;
    const float* feat = features + (size_t)t*N_NODES*128;
    float* ce = g_CE + (size_t)t*N_NODES*128;
    int dir = blockIdx.y;
    int m0 = blockIdx.x*64;
    int tid = threadIdx.x;
    int warp = tid >> 5, lane = tid & 31;
    int wm = warp >> 2;          // 0..1 : 32-row half
    int wj = warp & 3;           // 0..3 : 16-j slice
    int lr = lane >> 2;          // 0..7
    int lc = lane & 3;           // 0..3

    {   // stage A (64x128) as half2 words; clamp tail rows
        int rl = tid >> 5, c4 = tid & 31;
        #pragma unroll
        for (int it = 0; it < 8; it++) {
            int r = rl + it*8;
            int row = m0 + r; if (row >= N_NODES) row = N_NODES-1;
            float4 v = *(const float4*)(feat + (size_t)row*128 + c4*4);
            As[r*68 + 2*c4]     = pack_h2(v.x, v.y);
            As[r*68 + 2*c4 + 1] = pack_h2(v.z, v.w);
        }
    }

    float acc[2][3][2][4];   // [mtile][gate][jtile][c-regs]
    #pragma unroll
    for (int mt=0;mt<2;mt++)
        #pragma unroll
        for (int g=0;g<3;g++)
            #pragma unroll
            for (int jt=0;jt<2;jt++)
                #pragma unroll
                for (int r=0;r<4;r++) acc[mt][g][jt][r]=0.f;

    const uint32_t* W1t = g_W1H + (size_t)t*64*384 + dir*192;

    for (int kc = 0; kc < 4; kc++) {     // 16 k2-words per chunk (k=32)
        __syncthreads();
        for (int it = 0; it < 3; it++) {          // 16x48 uint4 = 768
            int idx = tid + it*256;
            int k2l = idx / 48, c4w = idx % 48;
            uint4 v = *(const uint4*)(W1t + (size_t)(kc*16+k2l)*384 + c4w*4);
            *(uint4*)&W1s[k2l*200 + c4w*4] = v;
        }
        __syncthreads();
        #pragma unroll
        for (int kit = 0; kit < 2; kit++) {
            int base = kit*8;
            uint32_t a[2][4];
            #pragma unroll
            for (int mt=0; mt<2; mt++) {
                const uint32_t* Ab = As + (wm*32 + mt*16 + lr)*68 + kc*16 + base;
                const uint32_t* Ab8 = Ab + 8*68;
                a[mt][0] = Ab[lc];
                a[mt][1] = Ab8[lc];
                a[mt][2] = Ab[lc+4];
                a[mt][3] = Ab8[lc+4];
            }
            uint32_t b[3][2][2];
            #pragma unroll
            for (int g=0; g<3; g++)
                #pragma unroll
                for (int jt=0; jt<2; jt++) {
                    int nb = g*64 + wj*16 + jt*8;
                    b[g][jt][0] = W1s[(base+lc)*200 + nb + lr];
                    b[g][jt][1] = W1s[(base+lc+4)*200 + nb + lr];
                }
            #pragma unroll
            for (int mt=0; mt<2; mt++)
                #pragma unroll
                for (int g=0; g<3; g++)
                    #pragma unroll
                    for (int jt=0; jt<2; jt++)
                        mma_f16(acc[mt][g][jt][0], acc[mt][g][jt][1],
                                acc[mt][g][jt][2], acc[mt][g][jt][3],
                                a[mt][0], a[mt][1], a[mt][2], a[mt][3],
                                b[g][jt][0], b[g][jt][1]);
        }
    }

    // epilogue: bias + LSTM nonlinearity, store CE (fp32)
    const float* B1t = g_B1 + t*384 + dir*192;
    #pragma unroll
    for (int mt=0; mt<2; mt++) {
        #pragma unroll
        for (int jt=0; jt<2; jt++) {
            int j = wj*16 + jt*8 + lc*2;
            float bi0 = B1t[j],     bi1 = B1t[j+1];
            float bg0 = B1t[64+j],  bg1 = B1t[64+j+1];
            float bo0 = B1t[128+j], bo1 = B1t[128+j+1];
            int r0 = m0 + wm*32 + mt*16 + lr;
            int r1 = r0 + 8;
            if (r0 < N_NODES) {
                float cc0 = sigmoid_f(acc[mt][0][jt][0]+bi0) * tanh_f(acc[mt][1][jt][0]+bg0);
                float cc1 = sigmoid_f(acc[mt][0][jt][1]+bi1) * tanh_f(acc[mt][1][jt][1]+bg1);
                float2 v;
                v.x = sigmoid_f(acc[mt][2][jt][0]+bo0) * tanh_f(cc0);
                v.y = sigmoid_f(acc[mt][2][jt][1]+bo1) * tanh_f(cc1);
                *(float2*)(ce + (size_t)r0*128 + dir*64 + j) = v;
            }
            if (r1 < N_NODES) {
                float cc0 = sigmoid_f(acc[mt][0][jt][2]+bi0) * tanh_f(acc[mt][1][jt][2]+bg0);
                float cc1 = sigmoid_f(acc[mt][0][jt][3]+bi1) * tanh_f(acc[mt][1][jt][3]+bg1);
                float2 v;
                v.x = sigmoid_f(acc[mt][2][jt][2]+bo0) * tanh_f(cc0);
                v.y = sigmoid_f(acc[mt][2][jt][3]+bo1) * tanh_f(cc1);
                *(float2*)(ce + (size_t)r1*128 + dir*64 + j) = v;
            }
        }
    }
}

// ---------------- stage B1: per-node seq-LSTM input projection, ALL types (fp16 mma) ----------------
// grid (782, 4, 11); block 256 (8 warps); tile 64(M) x 128(N); smem ~26.1 KB
__global__ __launch_bounds__(256) void ig_kernel()
{
    extern __shared__ float sm[];
    uint32_t* As = (uint32_t*)sm;       // [64 rows][68] half2 words
    uint32_t* Ws = As + 64*68;          // [16 k2][136] half2 words (128 used)

    int t = blockIdx.z;
    const float* ce = g_CE + (size_t)t*N_NODES*128;
    float* igb = g_IG + (size_t)t*N_NODES*512;
    int nt = blockIdx.y;        // 0..3 : 128-col chunk of 512
    int m0 = blockIdx.x*64;
    int tid = threadIdx.x;
    int warp = tid >> 5, lane = tid & 31;
    int wm = warp >> 2;         // 0..1 : 32-row half
    int wn = warp & 3;          // 0..3 : 32-col slice
    int lr = lane >> 2;
    int lc = lane & 3;

    {   // stage CE tile (64x128) as half2 words
        int rl = tid >> 5, c4 = tid & 31;
        #pragma unroll
        for (int it=0; it<8; it++) {
            int r = rl + it*8;
            int row = m0 + r; if (row >= N_NODES) row = N_NODES-1;
            float4 v = *(const float4*)(ce + (size_t)row*128 + c4*4);
            As[r*68 + 2*c4]     = pack_h2(v.x, v.y);
            As[r*68 + 2*c4 + 1] = pack_h2(v.z, v.w);
        }
    }

    float acc[2][4][4];   // [mtile][ntile][c-regs]
    #pragma unroll
    for (int mt=0;mt<2;mt++)
        #pragma unroll
        for (int n8=0;n8<4;n8++)
            #pragma unroll
            for (int r=0;r<4;r++) acc[mt][n8][r]=0.f;

    const uint32_t* W2t = g_W2H + (size_t)t*64*512 + nt*128;

    for (int kc=0; kc<4; kc++) {        // 16 k2-words per chunk
        __syncthreads();
        for (int it=0; it<2; it++) {     // 16x32 uint4 = 512
            int idx = tid + it*256;
            int k2l = idx >> 5, c4w = idx & 31;
            uint4 v = *(const uint4*)(W2t + (size_t)(kc*16+k2l)*512 + c4w*4);
            *(uint4*)&Ws[k2l*136 + c4w*4] = v;
        }
        __syncthreads();
        #pragma unroll
        for (int kit=0; kit<2; kit++) {
            int base = kit*8;
            uint32_t a[2][4];
            #pragma unroll
            for (int mt=0; mt<2; mt++) {
                const uint32_t* Ab = As + (wm*32 + mt*16 + lr)*68 + kc*16 + base;
                const uint32_t* Ab8 = Ab + 8*68;
                a[mt][0] = Ab[lc];
                a[mt][1] = Ab8[lc];
                a[mt][2] = Ab[lc+4];
                a[mt][3] = Ab8[lc+4];
            }
            uint32_t b[4][2];
            #pragma unroll
            for (int n8=0; n8<4; n8++) {
                int nb = wn*32 + n8*8;
                b[n8][0] = Ws[(base+lc)*136 + nb + lr];
                b[n8][1] = Ws[(base+lc+4)*136 + nb + lr];
            }
            #pragma unroll
            for (int mt=0; mt<2; mt++)
                #pragma unroll
                for (int n8=0; n8<4; n8++)
                    mma_f16(acc[mt][n8][0], acc[mt][n8][1], acc[mt][n8][2], acc[mt][n8][3],
                            a[mt][0], a[mt][1], a[mt][2], a[mt][3],
                            b[n8][0], b[n8][1]);
        }
    }

    const float* B2t = g_B2 + t*512;
    #pragma unroll
    for (int mt=0; mt<2; mt++) {
        #pragma unroll
        for (int n8=0; n8<4; n8++) {
            int ncol = nt*128 + wn*32 + n8*8 + lc*2;
            float b0 = B2t[ncol], b1 = B2t[ncol+1];
            int r0 = m0 + wm*32 + mt*16 + lr;
            int r1 = r0 + 8;
            if (r0 < N_NODES) {
                float2 v; v.x = acc[mt][n8][0]+b0; v.y = acc[mt][n8][1]+b1;
                *(float2*)(igb + (size_t)r0*512 + ncol) = v;
            }
            if (r1 < N_NODES) {
                float2 v; v.x = acc[mt][n8][2]+b0; v.y = acc[mt][n8][3]+b1;
                *(float2*)(igb + (size_t)r1*512 + ncol) = v;
            }
        }
    }
}

// ---------------- stage B2: fp16 recurrence, Whh fragments register-resident ----------------
// grid (512, 2 dirs, 11 types); block 256 (8 warps); 32 batch rows/block; smem ~44.3 KB
// warp layout: warp (0..7) = 8-j-col slice; each warp covers ALL 32 rows x 8 cols x 4 gates.
// Whh B-fragments (32 words/thread) hoisted into registers across the K loop.
__global__ __launch_bounds__(256, 2) void recur_kernel(const int* __restrict__ neigh_ids)
{
    extern __shared__ float sm[];
    uint32_t* smw = (uint32_t*)sm;
    uint32_t* Whh_s = smw;               // [32 k2][264] half2 words
    uint32_t* hA0 = smw + 32*264;        // [32 rows][36] half2 words
    uint32_t* hA1 = hA0 + 32*36;
    int* ids_s = (int*)(hA1 + 32*36);    // [32][10]

    int t = blockIdx.z;
    int dir = blockIdx.y;
    int b0 = blockIdx.x*32;
    int tid = threadIdx.x;
    int warp = tid >> 5, lane = tid & 31;
    int lr = lane >> 2, lc = lane & 3;

    // stage Whh half2 [32][256] -> smem [32][264]
    const uint32_t* Wsrc = g_WhhH + ((size_t)t*2 + dir)*32*256;
    #pragma unroll
    for (int it=0; it<8; it++) {          // 2048 uint4
        int idx = tid + it*256;
        int k2 = idx >> 6, c4 = idx & 63;
        uint4 v = *(const uint4*)(Wsrc + (size_t)k2*256 + c4*4);
        *(uint4*)&Whh_s[k2*264 + c4*4] = v;
    }
    for (int idx = tid; idx < 32*36; idx += 256) hA0[idx] = 0u;
    {
        const int* nsrc = neigh_ids + ((size_t)t*B_ + b0)*K_;
        for (int idx = tid; idx < 32*K_; idx += 256) ids_s[idx] = nsrc[idx];
    }
    __syncthreads();

    // hoist Whh B-fragments: [kit][gate][2], loop-invariant across all K steps
    uint32_t Breg[4][4][2];
    #pragma unroll
    for (int kit=0; kit<4; kit++) {
        int kb2 = kit*8;
        #pragma unroll
        for (int g=0; g<4; g++) {
            int nb = g*64 + warp*8;
            Breg[kit][g][0] = Whh_s[(kb2+lc)*264 + nb + lr];
            Breg[kit][g][1] = Whh_s[(kb2+lc+4)*264 + nb + lr];
        }
    }

    const float* ig = g_IG + (size_t)t*N_NODES*512 + dir*256;
    int jb = warp*8 + lc*2;              // thread's two preact cols
    int jw = warp*4 + lc;                // half2 word index of those cols

    float c[2][4], hs[2][4];             // [mt][0:lo.x 1:lo.y 2:hi.x 3:hi.y]
    #pragma unroll
    for (int mt=0;mt<2;mt++)
        #pragma unroll
        for (int e=0;e<4;e++){ c[mt][e]=0.f; hs[mt][e]=0.f; }

    uint32_t* cur = hA0; uint32_t* nxt = hA1;

    for (int step=0; step<K_; step++) {
        int k = dir ? (K_-1-step) : step;

        // prefetch mt=0 IG preacts (rows lr, lr+8); latency hidden under mma stream
        float2 igv0[4][2];
        {
            const float* ig_lo = ig + (size_t)ids_s[lr*K_ + k]*512;
            const float* ig_hi = ig + (size_t)ids_s[(lr+8)*K_ + k]*512;
            #pragma unroll
            for (int g=0; g<4; g++) {
                igv0[g][0] = *(const float2*)(ig_lo + g*64 + jb);
                igv0[g][1] = *(const float2*)(ig_hi + g*64 + jb);
            }
        }

        // acc = h_prev @ WhhT  (f16 mma, B from registers)
        float acc[2][4][4];              // [mt][gate][c-regs]
        #pragma unroll
        for (int mt=0;mt<2;mt++)
            #pragma unroll
            for (int g=0;g<4;g++)
                #pragma unroll
                for (int r=0;r<4;r++) acc[mt][g][r]=0.f;

        #pragma unroll
        for (int kit=0; kit<4; kit++) {
            int kb2 = kit*8;
            #pragma unroll
            for (int mt=0; mt<2; mt++) {
                const uint32_t* Cb = cur + (mt*16 + lr)*36 + kb2;
                const uint32_t* Cb8 = Cb + 8*36;
                uint32_t a0 = Cb[lc];
                uint32_t a1 = Cb8[lc];
                uint32_t a2 = Cb[lc+4];
                uint32_t a3 = Cb8[lc+4];
                #pragma unroll
                for (int g=0; g<4; g++)
                    mma_f16(acc[mt][g][0], acc[mt][g][1], acc[mt][g][2], acc[mt][g][3],
                            a0, a1, a2, a3, Breg[kit][g][0], Breg[kit][g][1]);
            }
        }

        // load mt=1 IG preacts (rows 16+lr, 24+lr); overlaps mt=0 epilogue
        float2 igv1[4][2];
        {
            const float* ig_lo = ig + (size_t)ids_s[(16+lr)*K_ + k]*512;
            const float* ig_hi = ig + (size_t)ids_s[(24+lr)*K_ + k]*512;
            #pragma unroll
            for (int g=0; g<4; g++) {
                igv1[g][0] = *(const float2*)(ig_lo + g*64 + jb);
                igv1[g][1] = *(const float2*)(ig_hi + g*64 + jb);
            }
        }

        // epilogue: gates, state update, h -> nxt (half2)
        #pragma unroll
        for (int mt=0; mt<2; mt++) {
            float2 (*iv)[2] = mt ? igv1 : igv0;
            int rlo = mt*16 + lr, rhi = rlo + 8;
            // row lo (regs 0,1)
            {
                float pi0 = acc[mt][0][0] + iv[0][0].x;
                float pf0 = acc[mt][1][0] + iv[1][0].x;
                float pg0 = acc[mt][2][0] + iv[2][0].x;
                float po0 = acc[mt][3][0] + iv[3][0].x;
                float pi1 = acc[mt][0][1] + iv[0][0].y;
                float pf1 = acc[mt][1][1] + iv[1][0].y;
                float pg1 = acc[mt][2][1] + iv[2][0].y;
                float po1 = acc[mt][3][1] + iv[3][0].y;
                c[mt][0] = sigmoid_f(pf0)*c[mt][0] + sigmoid_f(pi0)*tanh_f(pg0);
                c[mt][1] = sigmoid_f(pf1)*c[mt][1] + sigmoid_f(pi1)*tanh_f(pg1);
                float h0 = sigmoid_f(po0)*tanh_f(c[mt][0]);
                float h1 = sigmoid_f(po1)*tanh_f(c[mt][1]);
                hs[mt][0] += h0; hs[mt][1] += h1;
                nxt[rlo*36 + jw] = pack_h2(h0, h1);
            }
            // row hi (regs 2,3)
            {
                float pi0 = acc[mt][0][2] + iv[0][1].x;
                float pf0 = acc[mt][1][2] + iv[1][1].x;
                float pg0 = acc[mt][2][2] + iv[2][1].x;
                float po0 = acc[mt][3][2] + iv[3][1].x;
                float pi1 = acc[mt][0][3] + iv[0][1].y;
                float pf1 = acc[mt][1][3] + iv[1][1].y;
                float pg1 = acc[mt][2][3] + iv[2][1].y;
                float po1 = acc[mt][3][3] + iv[3][1].y;
                c[mt][2] = sigmoid_f(pf0)*c[mt][2] + sigmoid_f(pi0)*tanh_f(pg0);
                c[mt][3] = sigmoid_f(pf1)*c[mt][3] + sigmoid_f(pi1)*tanh_f(pg1);
                float h0 = sigmoid_f(po0)*tanh_f(c[mt][2]);
                float h1 = sigmoid_f(po1)*tanh_f(c[mt][3]);
                hs[mt][2] += h0; hs[mt][3] += h1;
                nxt[rhi*36 + jw] = pack_h2(h0, h1);
            }
        }
        __syncthreads();   // nxt complete before it becomes cur
        uint32_t* tmp = cur; cur = nxt; nxt = tmp;
    }

    // mean over K, store
    #pragma unroll
    for (int mt=0; mt<2; mt++) {
        int blo = b0 + mt*16 + lr, bhi = blo + 8;
        float2 v0; v0.x = hs[mt][0]*(1.0f/K_); v0.y = hs[mt][1]*(1.0f/K_);
        float2 v1; v1.x = hs[mt][2]*(1.0f/K_); v1.y = hs[mt][3]*(1.0f/K_);
        *(float2*)(g_AGG + ((size_t)t*B_ + blo)*128 + dir*64 + jb) = v0;
        *(float2*)(g_AGG + ((size_t)t*B_ + bhi)*128 + dir*64 + jb) = v1;
    }
}

// ---------------- stage C: attention combine (self embed gathered from CE type 0) ----------------
__global__ __launch_bounds__(256) void attn_kernel(const int* __restrict__ id_batch,
                                                   const float* __restrict__ att,
                                                   float* __restrict__ out)
{
    int warp = threadIdx.x >> 5;
    int lane = threadIdx.x & 31;
    int b = blockIdx.x*8 + warp;
    int id = id_batch[b];

    float e[12][4], a0[4], a1[4];
    #pragma unroll
    for (int i=0;i<4;i++) {
        int d = i*32 + lane;
        a0[i] = att[d];
        a1[i] = att[128+d];
        e[0][i] = g_CE[(size_t)id*128 + d];    // c_self = CE type-0 row
    }
    #pragma unroll
    for (int t=0;t<T_;t++)
        #pragma unroll
        for (int i=0;i<4;i++)
            e[1+t][i] = g_AGG[((size_t)t*B_ + b)*128 + i*32 + lane];

    float pself = 0.f;
    #pragma unroll
    for (int i=0;i<4;i++) pself += e[0][i]*a0[i];
    float sc[12];
    #pragma unroll
    for (int j=0;j<12;j++) {
        float p = 0.f;
        #pragma unroll
        for (int i=0;i<4;i++) p += e[j][i]*a1[i];
        sc[j] = p;
    }
    #pragma unroll
    for (int off=16; off>0; off>>=1) {
        pself += __shfl_xor_sync(0xffffffff, pself, off);
        #pragma unroll
        for (int j=0;j<12;j++) sc[j] += __shfl_xor_sync(0xffffffff, sc[j], off);
    }
    float mx = -1e30f;
    #pragma unroll
    for (int j=0;j<12;j++) {
        float s = pself + sc[j];
        s = (s > 0.f) ? s : 0.01f*s;    // leaky_relu(0.01)
        sc[j] = s;
        mx = fmaxf(mx, s);
    }
    float sum = 0.f;
    #pragma unroll
    for (int j=0;j<12;j++) { sc[j] = expf(sc[j]-mx); sum += sc[j]; }
    float inv = 1.f/sum;
    #pragma unroll
    for (int i=0;i<4;i++) {
        float o = 0.f;
        #pragma unroll
        for (int j=0;j<12;j++) o += sc[j]*e[j][i];
        out[(size_t)b*128 + i*32 + lane] = o*inv;
    }
}

// ---------------- launch (single stream, 5 launches) ----------------
extern "C" void kernel_launch(void* const* d_in, const int* in_sizes, int n_in,
                              void* d_out, int out_size)
{
    const float* features = (const float*)d_in[0];
    const int*   id_batch = (const int*)d_in[1];
    const int*   neigh_ids= (const int*)d_in[2];
    const float* cWih_f   = (const float*)d_in[3];
    const float* cb_f     = (const float*)d_in[5];
    const float* cWih_b   = (const float*)d_in[6];
    const float* cb_b     = (const float*)d_in[8];
    const float* nWih_f   = (const float*)d_in[9];
    const float* nWhh_f   = (const float*)d_in[10];
    const float* nb_f     = (const float*)d_in[11];
    const float* nWih_b   = (const float*)d_in[12];
    const float* nWhh_b   = (const float*)d_in[13];
    const float* nb_b     = (const float*)d_in[14];
    const float* att      = (const float*)d_in[15];
    float* out = (float*)d_out;

    const int SMEM_CONTENT = (64*68 + 16*200) * 4;              // 30208
    const int SMEM_IG      = (64*68 + 16*136) * 4;              // 26112
    const int SMEM_RECUR   = (32*264 + 2*32*36 + 32*K_) * 4;    // 44288
    cudaFuncSetAttribute(content_kernel, cudaFuncAttributeMaxDynamicSharedMemorySize, SMEM_CONTENT);
    cudaFuncSetAttribute(ig_kernel,      cudaFuncAttributeMaxDynamicSharedMemorySize, SMEM_IG);
    cudaFuncSetAttribute(recur_kernel,   cudaFuncAttributeMaxDynamicSharedMemorySize, SMEM_RECUR);

    pack_kernel<<<512, 256>>>(cWih_f, cb_f, cWih_b, cb_b,
                              nWih_f, nb_f, nWih_b, nb_b, nWhh_f, nWhh_b);

    {   // content encode, all types
        dim3 g(MROW_BLKS, 2, T_);
        content_kernel<<<g, 256, SMEM_CONTENT>>>(features);
    }
    {   // seq-LSTM input projections, all types
        dim3 g(MROW_BLKS, 4, T_);
        ig_kernel<<<g, 256, SMEM_IG>>>();
    }
    {   // recurrence, all types
        dim3 g(B_/32, 2, T_);
        recur_kernel<<<g, 256, SMEM_RECUR>>>(neigh_ids);
    }
    attn_kernel<<<B_/8, 256>>>(id_batch, att, out);
}

// round 15
// speedup vs baseline: 10.8606x; 1.0262x over previous
#include <cuda_runtime.h>
#include <cuda_fp16.h>
#include <stdint.h>
#include <stddef.h>
#include <math.h>

#define T_ 11
#define N_NODES 50000
#define D_ 128
#define H_ 64
#define B_ 16384
#define K_ 10
#define MROW_BLKS 782    // ceil(50000/64)

// ---------------- scratch (device globals; ~860 MB total) ----------------
__device__ uint32_t g_W1H[(size_t)T_*64*384];  // content Wih half2 k-pairs: [t][k2][n], n = dir*192+gate*64+j
__device__ float    g_B1[T_*384];
__device__ uint32_t g_W2H[(size_t)T_*64*512];  // seq Wih half2 k-pairs: [t][k2][n], n = dir*256+r
__device__ float    g_B2[T_*512];
__device__ uint32_t g_WhhH[(size_t)T_*2*32*256]; // [t][dir][k2][n=256] half2 (k-pairs), mma-B layout
__device__ float    g_CE[(size_t)T_*N_NODES*128]; // per-node content encodings, fp32 (282 MB)
__device__ uint32_t g_IGH[(size_t)T_*N_NODES*256]; // per-node seq preacts, half2-packed cols (563 MB)
__device__ float    g_AGG[(size_t)T_*B_*128];

// HW tanh (MUFU.TANH, sm_75+)
__device__ __forceinline__ float tanh_f(float x){
    float r; asm("tanh.approx.f32 %0, %1;" : "=f"(r) : "f"(x)); return r;
}
__device__ __forceinline__ float sigmoid_f(float x){
    float r; asm("tanh.approx.f32 %0, %1;" : "=f"(r) : "f"(0.5f*x));
    return fmaf(0.5f, r, 0.5f);
}
__device__ __forceinline__ void mma_f16(float& c0, float& c1, float& c2, float& c3,
                                        uint32_t a0, uint32_t a1, uint32_t a2, uint32_t a3,
                                        uint32_t b0, uint32_t b1){
    asm volatile("mma.sync.aligned.m16n8k16.row.col.f32.f16.f16.f32 "
                 "{%0,%1,%2,%3},{%4,%5,%6,%7},{%8,%9},{%0,%1,%2,%3};"
                 : "+f"(c0), "+f"(c1), "+f"(c2), "+f"(c3)
                 : "r"(a0), "r"(a1), "r"(a2), "r"(a3), "r"(b0), "r"(b1));
}
__device__ __forceinline__ uint32_t pack_h2(float a, float b){
    __half2 p = __floats2half2_rn(a, b);
    return *reinterpret_cast<uint32_t*>(&p);
}
__device__ __forceinline__ float2 unpack_h2(uint32_t w){
    return __half22float2(*reinterpret_cast<__half2*>(&w));
}

// ---------------- weight packing ----------------
__global__ void pack_kernel(const float* __restrict__ cWih_f, const float* __restrict__ cb_f,
                            const float* __restrict__ cWih_b, const float* __restrict__ cb_b,
                            const float* __restrict__ nWih_f, const float* __restrict__ nb_f,
                            const float* __restrict__ nWih_b, const float* __restrict__ nb_b,
                            const float* __restrict__ nWhh_f, const float* __restrict__ nWhh_b)
{
    int stride = gridDim.x*blockDim.x;
    int tid0 = blockIdx.x*blockDim.x + threadIdx.x;

    // W1H: [t][k2][n], n = dir*192 + gate*64 + j, gate 0:i 1:g 2:o (f-gate dead: zero state)
    for (size_t idx = tid0; idx < (size_t)T_*64*384; idx += stride) {
        int n = (int)(idx % 384); size_t rest = idx / 384;
        int k2 = (int)(rest % 64); int t = (int)(rest / 64);
        int dir = n/192, rem = n%192, g = rem/64, j = rem%64;
        int row = (g==0) ? j : (g==1) ? 128+j : 192+j;
        const float* W = dir ? cWih_b : cWih_f;
        float w0 = W[((size_t)t*256 + row)*128 + 2*k2];
        float w1 = W[((size_t)t*256 + row)*128 + 2*k2 + 1];
        g_W1H[idx] = pack_h2(w0, w1);
    }
    for (int idx = tid0; idx < T_*384; idx += stride) {
        int n = idx % 384; int t = idx / 384;
        int dir = n/192, rem = n%192, g = rem/64, j = rem%64;
        int row = (g==0) ? j : (g==1) ? 128+j : 192+j;
        g_B1[idx] = (dir ? cb_b : cb_f)[t*256 + row];
    }
    // W2H: [t][k2][n], n = dir*256 + r  (natural gate rows i,f,g,o)
    for (size_t idx = tid0; idx < (size_t)T_*64*512; idx += stride) {
        int n = (int)(idx % 512); size_t rest = idx/512;
        int k2 = (int)(rest % 64); int t = (int)(rest/64);
        int dir = n/256, r = n%256;
        const float* W = dir ? nWih_b : nWih_f;
        float w0 = W[((size_t)t*256 + r)*128 + 2*k2];
        float w1 = W[((size_t)t*256 + r)*128 + 2*k2 + 1];
        g_W2H[idx] = pack_h2(w0, w1);
    }
    for (int idx = tid0; idx < T_*512; idx += stride) {
        int n = idx % 512; int t = idx/512;
        int dir = n/256, r = n%256;
        g_B2[idx] = (dir ? nb_b : nb_f)[t*256 + r];
    }
    // Whh half2 mma-B layout: word(k2,n) = half2(W[n][2k2], W[n][2k2+1])
    for (size_t idx = tid0; idx < (size_t)T_*2*32*256; idx += stride) {
        int n = (int)(idx % 256); size_t rest = idx/256;
        int k2 = (int)(rest % 32); rest /= 32;
        int dir = (int)(rest % 2); int t = (int)(rest/2);
        const float* W = dir ? nWhh_b : nWhh_f;
        float w0 = W[((size_t)t*256 + n)*64 + 2*k2];
        float w1 = W[((size_t)t*256 + n)*64 + 2*k2 + 1];
        g_WhhH[idx] = pack_h2(w0, w1);
    }
}

// ---------------- stage A: dense per-node content encode, ALL types (fp16 mma) ----------------
// grid (782, 2 dirs, 11 types); block 256 (8 warps); tile 64(M) x 192(N); smem ~30.2 KB
__global__ __launch_bounds__(256) void content_kernel(const float* __restrict__ features)
{
    extern __shared__ float sm[];
    uint32_t* As  = (uint32_t*)sm;      // [64 rows][68] half2 words (64 used)
    uint32_t* W1s = As + 64*68;         // [16 k2][200] half2 words (192 used)

    int t = blockIdx.z;
    const float* feat = features + (size_t)t*N_NODES*128;
    float* ce = g_CE + (size_t)t*N_NODES*128;
    int dir = blockIdx.y;
    int m0 = blockIdx.x*64;
    int tid = threadIdx.x;
    int warp = tid >> 5, lane = tid & 31;
    int wm = warp >> 2;          // 0..1 : 32-row half
    int wj = warp & 3;           // 0..3 : 16-j slice
    int lr = lane >> 2;          // 0..7
    int lc = lane & 3;           // 0..3

    {   // stage A (64x128) as half2 words; clamp tail rows
        int rl = tid >> 5, c4 = tid & 31;
        #pragma unroll
        for (int it = 0; it < 8; it++) {
            int r = rl + it*8;
            int row = m0 + r; if (row >= N_NODES) row = N_NODES-1;
            float4 v = *(const float4*)(feat + (size_t)row*128 + c4*4);
            As[r*68 + 2*c4]     = pack_h2(v.x, v.y);
            As[r*68 + 2*c4 + 1] = pack_h2(v.z, v.w);
        }
    }

    float acc[2][3][2][4];   // [mtile][gate][jtile][c-regs]
    #pragma unroll
    for (int mt=0;mt<2;mt++)
        #pragma unroll
        for (int g=0;g<3;g++)
            #pragma unroll
            for (int jt=0;jt<2;jt++)
                #pragma unroll
                for (int r=0;r<4;r++) acc[mt][g][jt][r]=0.f;

    const uint32_t* W1t = g_W1H + (size_t)t*64*384 + dir*192;

    for (int kc = 0; kc < 4; kc++) {     // 16 k2-words per chunk (k=32)
        __syncthreads();
        for (int it = 0; it < 3; it++) {          // 16x48 uint4 = 768
            int idx = tid + it*256;
            int k2l = idx / 48, c4w = idx % 48;
            uint4 v = *(const uint4*)(W1t + (size_t)(kc*16+k2l)*384 + c4w*4);
            *(uint4*)&W1s[k2l*200 + c4w*4] = v;
        }
        __syncthreads();
        #pragma unroll
        for (int kit = 0; kit < 2; kit++) {
            int base = kit*8;
            uint32_t a[2][4];
            #pragma unroll
            for (int mt=0; mt<2; mt++) {
                const uint32_t* Ab = As + (wm*32 + mt*16 + lr)*68 + kc*16 + base;
                const uint32_t* Ab8 = Ab + 8*68;
                a[mt][0] = Ab[lc];
                a[mt][1] = Ab8[lc];
                a[mt][2] = Ab[lc+4];
                a[mt][3] = Ab8[lc+4];
            }
            uint32_t b[3][2][2];
            #pragma unroll
            for (int g=0; g<3; g++)
                #pragma unroll
                for (int jt=0; jt<2; jt++) {
                    int nb = g*64 + wj*16 + jt*8;
                    b[g][jt][0] = W1s[(base+lc)*200 + nb + lr];
                    b[g][jt][1] = W1s[(base+lc+4)*200 + nb + lr];
                }
            #pragma unroll
            for (int mt=0; mt<2; mt++)
                #pragma unroll
                for (int g=0; g<3; g++)
                    #pragma unroll
                    for (int jt=0; jt<2; jt++)
                        mma_f16(acc[mt][g][jt][0], acc[mt][g][jt][1],
                                acc[mt][g][jt][2], acc[mt][g][jt][3],
                                a[mt][0], a[mt][1], a[mt][2], a[mt][3],
                                b[g][jt][0], b[g][jt][1]);
        }
    }

    // epilogue: bias + LSTM nonlinearity, store CE (fp32)
    const float* B1t = g_B1 + t*384 + dir*192;
    #pragma unroll
    for (int mt=0; mt<2; mt++) {
        #pragma unroll
        for (int jt=0; jt<2; jt++) {
            int j = wj*16 + jt*8 + lc*2;
            float bi0 = B1t[j],     bi1 = B1t[j+1];
            float bg0 = B1t[64+j],  bg1 = B1t[64+j+1];
            float bo0 = B1t[128+j], bo1 = B1t[128+j+1];
            int r0 = m0 + wm*32 + mt*16 + lr;
            int r1 = r0 + 8;
            if (r0 < N_NODES) {
                float cc0 = sigmoid_f(acc[mt][0][jt][0]+bi0) * tanh_f(acc[mt][1][jt][0]+bg0);
                float cc1 = sigmoid_f(acc[mt][0][jt][1]+bi1) * tanh_f(acc[mt][1][jt][1]+bg1);
                float2 v;
                v.x = sigmoid_f(acc[mt][2][jt][0]+bo0) * tanh_f(cc0);
                v.y = sigmoid_f(acc[mt][2][jt][1]+bo1) * tanh_f(cc1);
                *(float2*)(ce + (size_t)r0*128 + dir*64 + j) = v;
            }
            if (r1 < N_NODES) {
                float cc0 = sigmoid_f(acc[mt][0][jt][2]+bi0) * tanh_f(acc[mt][1][jt][2]+bg0);
                float cc1 = sigmoid_f(acc[mt][0][jt][3]+bi1) * tanh_f(acc[mt][1][jt][3]+bg1);
                float2 v;
                v.x = sigmoid_f(acc[mt][2][jt][2]+bo0) * tanh_f(cc0);
                v.y = sigmoid_f(acc[mt][2][jt][3]+bo1) * tanh_f(cc1);
                *(float2*)(ce + (size_t)r1*128 + dir*64 + j) = v;
            }
        }
    }
}

// ---------------- stage B1: per-node seq-LSTM input projection (fp16 mma, half2 output) ----------------
// grid (782, 4, 11); block 256 (8 warps); tile 64(M) x 128(N); smem ~26.1 KB
__global__ __launch_bounds__(256) void ig_kernel()
{
    extern __shared__ float sm[];
    uint32_t* As = (uint32_t*)sm;       // [64 rows][68] half2 words
    uint32_t* Ws = As + 64*68;          // [16 k2][136] half2 words (128 used)

    int t = blockIdx.z;
    const float* ce = g_CE + (size_t)t*N_NODES*128;
    uint32_t* igb = g_IGH + (size_t)t*N_NODES*256;
    int nt = blockIdx.y;        // 0..3 : 128-col chunk of 512
    int m0 = blockIdx.x*64;
    int tid = threadIdx.x;
    int warp = tid >> 5, lane = tid & 31;
    int wm = warp >> 2;         // 0..1 : 32-row half
    int wn = warp & 3;          // 0..3 : 32-col slice
    int lr = lane >> 2;
    int lc = lane & 3;

    {   // stage CE tile (64x128) as half2 words
        int rl = tid >> 5, c4 = tid & 31;
        #pragma unroll
        for (int it=0; it<8; it++) {
            int r = rl + it*8;
            int row = m0 + r; if (row >= N_NODES) row = N_NODES-1;
            float4 v = *(const float4*)(ce + (size_t)row*128 + c4*4);
            As[r*68 + 2*c4]     = pack_h2(v.x, v.y);
            As[r*68 + 2*c4 + 1] = pack_h2(v.z, v.w);
        }
    }

    float acc[2][4][4];   // [mtile][ntile][c-regs]
    #pragma unroll
    for (int mt=0;mt<2;mt++)
        #pragma unroll
        for (int n8=0;n8<4;n8++)
            #pragma unroll
            for (int r=0;r<4;r++) acc[mt][n8][r]=0.f;

    const uint32_t* W2t = g_W2H + (size_t)t*64*512 + nt*128;

    for (int kc=0; kc<4; kc++) {        // 16 k2-words per chunk
        __syncthreads();
        for (int it=0; it<2; it++) {     // 16x32 uint4 = 512
            int idx = tid + it*256;
            int k2l = idx >> 5, c4w = idx & 31;
            uint4 v = *(const uint4*)(W2t + (size_t)(kc*16+k2l)*512 + c4w*4);
            *(uint4*)&Ws[k2l*136 + c4w*4] = v;
        }
        __syncthreads();
        #pragma unroll
        for (int kit=0; kit<2; kit++) {
            int base = kit*8;
            uint32_t a[2][4];
            #pragma unroll
            for (int mt=0; mt<2; mt++) {
                const uint32_t* Ab = As + (wm*32 + mt*16 + lr)*68 + kc*16 + base;
                const uint32_t* Ab8 = Ab + 8*68;
                a[mt][0] = Ab[lc];
                a[mt][1] = Ab8[lc];
                a[mt][2] = Ab[lc+4];
                a[mt][3] = Ab8[lc+4];
            }
            uint32_t b[4][2];
            #pragma unroll
            for (int n8=0; n8<4; n8++) {
                int nb = wn*32 + n8*8;
                b[n8][0] = Ws[(base+lc)*136 + nb + lr];
                b[n8][1] = Ws[(base+lc+4)*136 + nb + lr];
            }
            #pragma unroll
            for (int mt=0; mt<2; mt++)
                #pragma unroll
                for (int n8=0; n8<4; n8++)
                    mma_f16(acc[mt][n8][0], acc[mt][n8][1], acc[mt][n8][2], acc[mt][n8][3],
                            a[mt][0], a[mt][1], a[mt][2], a[mt][3],
                            b[n8][0], b[n8][1]);
        }
    }

    // epilogue: add bias (fp32), pack preacts to half2 words
    const float* B2t = g_B2 + t*512;
    #pragma unroll
    for (int mt=0; mt<2; mt++) {
        #pragma unroll
        for (int n8=0; n8<4; n8++) {
            int ncol = nt*128 + wn*32 + n8*8 + lc*2;
            int wcol = ncol >> 1;          // half2 word index (ncol even)
            float b0 = B2t[ncol], b1 = B2t[ncol+1];
            int r0 = m0 + wm*32 + mt*16 + lr;
            int r1 = r0 + 8;
            if (r0 < N_NODES)
                igb[(size_t)r0*256 + wcol] = pack_h2(acc[mt][n8][0]+b0, acc[mt][n8][1]+b1);
            if (r1 < N_NODES)
                igb[(size_t)r1*256 + wcol] = pack_h2(acc[mt][n8][2]+b0, acc[mt][n8][3]+b1);
        }
    }
}

// ---------------- stage B2: fp16 recurrence (round-13 layout, half2 IG gather) ----------------
// grid (512, 2 dirs, 11 types); block 256 (8 warps); 32 batch rows/block; smem ~44.3 KB
// warp: wm (0..1) 16-row m-tile, wj (0..3) 16-j slice (all 4 gates, 2 jt of 8)
__global__ __launch_bounds__(256) void recur_kernel(const int* __restrict__ neigh_ids)
{
    extern __shared__ float sm[];
    uint32_t* smw = (uint32_t*)sm;
    uint32_t* Whh_s = smw;               // [32 k2][264] half2 words
    uint32_t* hA0 = smw + 32*264;        // [32 rows][36] half2 words
    uint32_t* hA1 = hA0 + 32*36;
    int* ids_s = (int*)(hA1 + 32*36);    // [32][10]

    int t = blockIdx.z;
    int dir = blockIdx.y;
    int b0 = blockIdx.x*32;
    int tid = threadIdx.x;
    int warp = tid >> 5, lane = tid & 31;
    int wm = warp >> 2;            // 0..1
    int wj = warp & 3;             // 0..3
    int lr = lane >> 2, lc = lane & 3;

    // stage Whh half2 [32][256] -> smem [32][264]
    const uint32_t* Wsrc = g_WhhH + ((size_t)t*2 + dir)*32*256;
    #pragma unroll
    for (int it=0; it<8; it++) {          // 2048 uint4
        int idx = tid + it*256;
        int k2 = idx >> 6, c4 = idx & 63;
        uint4 v = *(const uint4*)(Wsrc + (size_t)k2*256 + c4*4);
        *(uint4*)&Whh_s[k2*264 + c4*4] = v;
    }
    for (int idx = tid; idx < 32*36; idx += 256) hA0[idx] = 0u;
    {
        const int* nsrc = neigh_ids + ((size_t)t*B_ + b0)*K_;
        for (int idx = tid; idx < 32*K_; idx += 256) ids_s[idx] = nsrc[idx];
    }
    __syncthreads();

    const uint32_t* ig = g_IGH + (size_t)t*N_NODES*256 + dir*128;   // word offset for dir
    int row_lo = wm*16 + lr;               // block-local rows: row_lo, row_lo+8

    float c[2][4], hs[2][4];               // [jt][0:lo.x 1:lo.y 2:hi.x 3:hi.y]
    #pragma unroll
    for (int jt=0;jt<2;jt++)
        #pragma unroll
        for (int e=0;e<4;e++){ c[jt][e]=0.f; hs[jt][e]=0.f; }

    uint32_t* cur = hA0; uint32_t* nxt = hA1;

    for (int step=0; step<K_; step++) {
        int k = dir ? (K_-1-step) : step;
        const uint32_t* ig_lo = ig + (size_t)ids_s[row_lo*K_ + k]*256;
        const uint32_t* ig_hi = ig + (size_t)ids_s[(row_lo+8)*K_ + k]*256;

        // prefetch IG preact words (both jt; 16 regs total), hidden under mma stream
        uint32_t igw[2][4][2];             // [jt][gate][lo/hi]
        #pragma unroll
        for (int jt=0; jt<2; jt++) {
            int wcol = wj*8 + jt*4 + lc;   // word index of cols (jb, jb+1)
            #pragma unroll
            for (int g=0; g<4; g++) {
                igw[jt][g][0] = ig_lo[g*32 + wcol];
                igw[jt][g][1] = ig_hi[g*32 + wcol];
            }
        }

        // acc = h_prev @ WhhT  (f16 m16n8k16 mma)
        float acc[4][2][4];                // [gate][jt][c-regs]
        #pragma unroll
        for (int g=0;g<4;g++)
            #pragma unroll
            for (int jt=0;jt<2;jt++)
                #pragma unroll
                for (int r=0;r<4;r++) acc[g][jt][r]=0.f;

        #pragma unroll
        for (int kit=0; kit<4; kit++) {
            int kb2 = kit*8;
            uint32_t a0 = cur[row_lo*36 + kb2 + lc];
            uint32_t a1 = cur[(row_lo+8)*36 + kb2 + lc];
            uint32_t a2 = cur[row_lo*36 + kb2 + lc + 4];
            uint32_t a3 = cur[(row_lo+8)*36 + kb2 + lc + 4];
            #pragma unroll
            for (int g=0; g<4; g++)
                #pragma unroll
                for (int jt=0; jt<2; jt++) {
                    int nb = g*64 + wj*16 + jt*8;
                    uint32_t bb0 = Whh_s[(kb2+lc)*264 + nb + lr];
                    uint32_t bb1 = Whh_s[(kb2+lc+4)*264 + nb + lr];
                    mma_f16(acc[g][jt][0], acc[g][jt][1], acc[g][jt][2], acc[g][jt][3],
                            a0, a1, a2, a3, bb0, bb1);
                }
        }

        // epilogue: gates, state update, h -> nxt (half2)
        #pragma unroll
        for (int jt=0; jt<2; jt++) {
            int jw = wj*8 + jt*4 + lc;
            // row lo (regs 0,1)
            {
                float2 vi = unpack_h2(igw[jt][0][0]);
                float2 vf = unpack_h2(igw[jt][1][0]);
                float2 vg = unpack_h2(igw[jt][2][0]);
                float2 vo = unpack_h2(igw[jt][3][0]);
                c[jt][0] = sigmoid_f(acc[1][jt][0]+vf.x)*c[jt][0]
                         + sigmoid_f(acc[0][jt][0]+vi.x)*tanh_f(acc[2][jt][0]+vg.x);
                c[jt][1] = sigmoid_f(acc[1][jt][1]+vf.y)*c[jt][1]
                         + sigmoid_f(acc[0][jt][1]+vi.y)*tanh_f(acc[2][jt][1]+vg.y);
                float h0 = sigmoid_f(acc[3][jt][0]+vo.x)*tanh_f(c[jt][0]);
                float h1 = sigmoid_f(acc[3][jt][1]+vo.y)*tanh_f(c[jt][1]);
                hs[jt][0] += h0; hs[jt][1] += h1;
                nxt[row_lo*36 + jw] = pack_h2(h0, h1);
            }
            // row hi (regs 2,3)
            {
                float2 vi = unpack_h2(igw[jt][0][1]);
                float2 vf = unpack_h2(igw[jt][1][1]);
                float2 vg = unpack_h2(igw[jt][2][1]);
                float2 vo = unpack_h2(igw[jt][3][1]);
                c[jt][2] = sigmoid_f(acc[1][jt][2]+vf.x)*c[jt][2]
                         + sigmoid_f(acc[0][jt][2]+vi.x)*tanh_f(acc[2][jt][2]+vg.x);
                c[jt][3] = sigmoid_f(acc[1][jt][3]+vf.y)*c[jt][3]
                         + sigmoid_f(acc[0][jt][3]+vi.y)*tanh_f(acc[2][jt][3]+vg.y);
                float h0 = sigmoid_f(acc[3][jt][2]+vo.x)*tanh_f(c[jt][2]);
                float h1 = sigmoid_f(acc[3][jt][3]+vo.y)*tanh_f(c[jt][3]);
                hs[jt][2] += h0; hs[jt][3] += h1;
                nxt[(row_lo+8)*36 + jw] = pack_h2(h0, h1);
            }
        }
        __syncthreads();   // nxt complete before it becomes cur
        uint32_t* tmp = cur; cur = nxt; nxt = tmp;
    }

    // mean over K, store
    #pragma unroll
    for (int jt=0; jt<2; jt++) {
        int jb = wj*16 + jt*8 + lc*2;
        int blo = b0 + row_lo, bhi = blo + 8;
        float2 v0; v0.x = hs[jt][0]*(1.0f/K_); v0.y = hs[jt][1]*(1.0f/K_);
        float2 v1; v1.x = hs[jt][2]*(1.0f/K_); v1.y = hs[jt][3]*(1.0f/K_);
        *(float2*)(g_AGG + ((size_t)t*B_ + blo)*128 + dir*64 + jb) = v0;
        *(float2*)(g_AGG + ((size_t)t*B_ + bhi)*128 + dir*64 + jb) = v1;
    }
}

// ---------------- stage C: attention combine (self embed gathered from CE type 0) ----------------
__global__ __launch_bounds__(256) void attn_kernel(const int* __restrict__ id_batch,
                                                   const float* __restrict__ att,
                                                   float* __restrict__ out)
{
    int warp = threadIdx.x >> 5;
    int lane = threadIdx.x & 31;
    int b = blockIdx.x*8 + warp;
    int id = id_batch[b];

    float e[12][4], a0[4], a1[4];
    #pragma unroll
    for (int i=0;i<4;i++) {
        int d = i*32 + lane;
        a0[i] = att[d];
        a1[i] = att[128+d];
        e[0][i] = g_CE[(size_t)id*128 + d];    // c_self = CE type-0 row
    }
    #pragma unroll
    for (int t=0;t<T_;t++)
        #pragma unroll
        for (int i=0;i<4;i++)
            e[1+t][i] = g_AGG[((size_t)t*B_ + b)*128 + i*32 + lane];

    float pself = 0.f;
    #pragma unroll
    for (int i=0;i<4;i++) pself += e[0][i]*a0[i];
    float sc[12];
    #pragma unroll
    for (int j=0;j<12;j++) {
        float p = 0.f;
        #pragma unroll
        for (int i=0;i<4;i++) p += e[j][i]*a1[i];
        sc[j] = p;
    }
    #pragma unroll
    for (int off=16; off>0; off>>=1) {
        pself += __shfl_xor_sync(0xffffffff, pself, off);
        #pragma unroll
        for (int j=0;j<12;j++) sc[j] += __shfl_xor_sync(0xffffffff, sc[j], off);
    }
    float mx = -1e30f;
    #pragma unroll
    for (int j=0;j<12;j++) {
        float s = pself + sc[j];
        s = (s > 0.f) ? s : 0.01f*s;    // leaky_relu(0.01)
        sc[j] = s;
        mx = fmaxf(mx, s);
    }
    float sum = 0.f;
    #pragma unroll
    for (int j=0;j<12;j++) { sc[j] = expf(sc[j]-mx); sum += sc[j]; }
    float inv = 1.f/sum;
    #pragma unroll
    for (int i=0;i<4;i++) {
        float o = 0.f;
        #pragma unroll
        for (int j=0;j<12;j++) o += sc[j]*e[j][i];
        out[(size_t)b*128 + i*32 + lane] = o*inv;
    }
}

// ---------------- launch (single stream, 5 launches) ----------------
extern "C" void kernel_launch(void* const* d_in, const int* in_sizes, int n_in,
                              void* d_out, int out_size)
{
    const float* features = (const float*)d_in[0];
    const int*   id_batch = (const int*)d_in[1];
    const int*   neigh_ids= (const int*)d_in[2];
    const float* cWih_f   = (const float*)d_in[3];
    const float* cb_f     = (const float*)d_in[5];
    const float* cWih_b   = (const float*)d_in[6];
    const float* cb_b     = (const float*)d_in[8];
    const float* nWih_f   = (const float*)d_in[9];
    const float* nWhh_f   = (const float*)d_in[10];
    const float* nb_f     = (const float*)d_in[11];
    const float* nWih_b   = (const float*)d_in[12];
    const float* nWhh_b   = (const float*)d_in[13];
    const float* nb_b     = (const float*)d_in[14];
    const float* att      = (const float*)d_in[15];
    float* out = (float*)d_out;

    const int SMEM_CONTENT = (64*68 + 16*200) * 4;              // 30208
    const int SMEM_IG      = (64*68 + 16*136) * 4;              // 26112
    const int SMEM_RECUR   = (32*264 + 2*32*36 + 32*K_) * 4;    // 44288
    cudaFuncSetAttribute(content_kernel, cudaFuncAttributeMaxDynamicSharedMemorySize, SMEM_CONTENT);
    cudaFuncSetAttribute(ig_kernel,      cudaFuncAttributeMaxDynamicSharedMemorySize, SMEM_IG);
    cudaFuncSetAttribute(recur_kernel,   cudaFuncAttributeMaxDynamicSharedMemorySize, SMEM_RECUR);

    pack_kernel<<<512, 256>>>(cWih_f, cb_f, cWih_b, cb_b,
                              nWih_f, nb_f, nWih_b, nb_b, nWhh_f, nWhh_b);

    {   // content encode, all types
        dim3 g(MROW_BLKS, 2, T_);
        content_kernel<<<g, 256, SMEM_CONTENT>>>(features);
    }
    {   // seq-LSTM input projections, all types
        dim3 g(MROW_BLKS, 4, T_);
        ig_kernel<<<g, 256, SMEM_IG>>>();
    }
    {   // recurrence, all types
        dim3 g(B_/32, 2, T_);
        recur_kernel<<<g, 256, SMEM_RECUR>>>(neigh_ids);
    }
    attn_kernel<<<B_/8, 256>>>(id_batch, att, out);
}

// round 16
// speedup vs baseline: 11.9449x; 1.0998x over previous
#include <cuda_runtime.h>
#include <cuda_fp16.h>
#include <stdint.h>
#include <stddef.h>
#include <math.h>

#define T_ 11
#define N_NODES 50000
#define D_ 128
#define H_ 64
#define B_ 16384
#define K_ 10
#define MROW_BLKS 782    // ceil(50000/64)

// ---------------- scratch (device globals; ~860 MB total) ----------------
__device__ uint32_t g_W1H[(size_t)T_*64*384];  // content Wih half2 k-pairs: [t][k2][n], n = dir*192+gate*64+j
__device__ float    g_B1[T_*384];
__device__ uint32_t g_W2H[(size_t)T_*64*512];  // seq Wih half2 k-pairs: [t][k2][n], n = dir*256+r
__device__ float    g_B2[T_*512];
__device__ uint32_t g_WhhH[(size_t)T_*2*32*256]; // [t][dir][k2][n=256] half2 (k-pairs), mma-B layout
__device__ float    g_CE[(size_t)T_*N_NODES*128]; // per-node content encodings, fp32 (282 MB)
// IG preacts, half2 words, GATE-INTERLEAVED: word(node, dir, col2, gate) at
// [node*256 + dir*128 + col2*4 + gate]; col2 = j/2 (0..31). One uint4 = all 4 gates.
__device__ uint32_t g_IGH[(size_t)T_*N_NODES*256];
__device__ float    g_AGG[(size_t)T_*B_*128];

// HW tanh (MUFU.TANH, sm_75+)
__device__ __forceinline__ float tanh_f(float x){
    float r; asm("tanh.approx.f32 %0, %1;" : "=f"(r) : "f"(x)); return r;
}
__device__ __forceinline__ float sigmoid_f(float x){
    float r; asm("tanh.approx.f32 %0, %1;" : "=f"(r) : "f"(0.5f*x));
    return fmaf(0.5f, r, 0.5f);
}
__device__ __forceinline__ void mma_f16(float& c0, float& c1, float& c2, float& c3,
                                        uint32_t a0, uint32_t a1, uint32_t a2, uint32_t a3,
                                        uint32_t b0, uint32_t b1){
    asm volatile("mma.sync.aligned.m16n8k16.row.col.f32.f16.f16.f32 "
                 "{%0,%1,%2,%3},{%4,%5,%6,%7},{%8,%9},{%0,%1,%2,%3};"
                 : "+f"(c0), "+f"(c1), "+f"(c2), "+f"(c3)
                 : "r"(a0), "r"(a1), "r"(a2), "r"(a3), "r"(b0), "r"(b1));
}
__device__ __forceinline__ uint32_t pack_h2(float a, float b){
    __half2 p = __floats2half2_rn(a, b);
    return *reinterpret_cast<uint32_t*>(&p);
}
__device__ __forceinline__ float2 unpack_h2(uint32_t w){
    return __half22float2(*reinterpret_cast<__half2*>(&w));
}

// ---------------- weight packing ----------------
__global__ void pack_kernel(const float* __restrict__ cWih_f, const float* __restrict__ cb_f,
                            const float* __restrict__ cWih_b, const float* __restrict__ cb_b,
                            const float* __restrict__ nWih_f, const float* __restrict__ nb_f,
                            const float* __restrict__ nWih_b, const float* __restrict__ nb_b,
                            const float* __restrict__ nWhh_f, const float* __restrict__ nWhh_b)
{
    int stride = gridDim.x*blockDim.x;
    int tid0 = blockIdx.x*blockDim.x + threadIdx.x;

    // W1H: [t][k2][n], n = dir*192 + gate*64 + j, gate 0:i 1:g 2:o (f-gate dead: zero state)
    for (size_t idx = tid0; idx < (size_t)T_*64*384; idx += stride) {
        int n = (int)(idx % 384); size_t rest = idx / 384;
        int k2 = (int)(rest % 64); int t = (int)(rest / 64);
        int dir = n/192, rem = n%192, g = rem/64, j = rem%64;
        int row = (g==0) ? j : (g==1) ? 128+j : 192+j;
        const float* W = dir ? cWih_b : cWih_f;
        float w0 = W[((size_t)t*256 + row)*128 + 2*k2];
        float w1 = W[((size_t)t*256 + row)*128 + 2*k2 + 1];
        g_W1H[idx] = pack_h2(w0, w1);
    }
    for (int idx = tid0; idx < T_*384; idx += stride) {
        int n = idx % 384; int t = idx / 384;
        int dir = n/192, rem = n%192, g = rem/64, j = rem%64;
        int row = (g==0) ? j : (g==1) ? 128+j : 192+j;
        g_B1[idx] = (dir ? cb_b : cb_f)[t*256 + row];
    }
    // W2H: [t][k2][n], n = dir*256 + r  (natural gate rows i,f,g,o)
    for (size_t idx = tid0; idx < (size_t)T_*64*512; idx += stride) {
        int n = (int)(idx % 512); size_t rest = idx/512;
        int k2 = (int)(rest % 64); int t = (int)(rest/64);
        int dir = n/256, r = n%256;
        const float* W = dir ? nWih_b : nWih_f;
        float w0 = W[((size_t)t*256 + r)*128 + 2*k2];
        float w1 = W[((size_t)t*256 + r)*128 + 2*k2 + 1];
        g_W2H[idx] = pack_h2(w0, w1);
    }
    for (int idx = tid0; idx < T_*512; idx += stride) {
        int n = idx % 512; int t = idx/512;
        int dir = n/256, r = n%256;
        g_B2[idx] = (dir ? nb_b : nb_f)[t*256 + r];
    }
    // Whh half2 mma-B layout: word(k2,n) = half2(W[n][2k2], W[n][2k2+1])
    for (size_t idx = tid0; idx < (size_t)T_*2*32*256; idx += stride) {
        int n = (int)(idx % 256); size_t rest = idx/256;
        int k2 = (int)(rest % 32); rest /= 32;
        int dir = (int)(rest % 2); int t = (int)(rest/2);
        const float* W = dir ? nWhh_b : nWhh_f;
        float w0 = W[((size_t)t*256 + n)*64 + 2*k2];
        float w1 = W[((size_t)t*256 + n)*64 + 2*k2 + 1];
        g_WhhH[idx] = pack_h2(w0, w1);
    }
}

// ---------------- stage A: dense per-node content encode, ALL types (fp16 mma) ----------------
// grid (782, 2 dirs, 11 types); block 256 (8 warps); tile 64(M) x 192(N); smem ~30.2 KB
__global__ __launch_bounds__(256) void content_kernel(const float* __restrict__ features)
{
    extern __shared__ float sm[];
    uint32_t* As  = (uint32_t*)sm;      // [64 rows][68] half2 words (64 used)
    uint32_t* W1s = As + 64*68;         // [16 k2][200] half2 words (192 used)

    int t = blockIdx.z;
    const float* feat = features + (size_t)t*N_NODES*128;
    float* ce = g_CE + (size_t)t*N_NODES*128;
    int dir = blockIdx.y;
    int m0 = blockIdx.x*64;
    int tid = threadIdx.x;
    int warp = tid >> 5, lane = tid & 31;
    int wm = warp >> 2;          // 0..1 : 32-row half
    int wj = warp & 3;           // 0..3 : 16-j slice
    int lr = lane >> 2;          // 0..7
    int lc = lane & 3;           // 0..3

    {   // stage A (64x128) as half2 words; clamp tail rows
        int rl = tid >> 5, c4 = tid & 31;
        #pragma unroll
        for (int it = 0; it < 8; it++) {
            int r = rl + it*8;
            int row = m0 + r; if (row >= N_NODES) row = N_NODES-1;
            float4 v = *(const float4*)(feat + (size_t)row*128 + c4*4);
            As[r*68 + 2*c4]     = pack_h2(v.x, v.y);
            As[r*68 + 2*c4 + 1] = pack_h2(v.z, v.w);
        }
    }

    float acc[2][3][2][4];   // [mtile][gate][jtile][c-regs]
    #pragma unroll
    for (int mt=0;mt<2;mt++)
        #pragma unroll
        for (int g=0;g<3;g++)
            #pragma unroll
            for (int jt=0;jt<2;jt++)
                #pragma unroll
                for (int r=0;r<4;r++) acc[mt][g][jt][r]=0.f;

    const uint32_t* W1t = g_W1H + (size_t)t*64*384 + dir*192;

    for (int kc = 0; kc < 4; kc++) {     // 16 k2-words per chunk (k=32)
        __syncthreads();
        for (int it = 0; it < 3; it++) {          // 16x48 uint4 = 768
            int idx = tid + it*256;
            int k2l = idx / 48, c4w = idx % 48;
            uint4 v = *(const uint4*)(W1t + (size_t)(kc*16+k2l)*384 + c4w*4);
            *(uint4*)&W1s[k2l*200 + c4w*4] = v;
        }
        __syncthreads();
        #pragma unroll
        for (int kit = 0; kit < 2; kit++) {
            int base = kit*8;
            uint32_t a[2][4];
            #pragma unroll
            for (int mt=0; mt<2; mt++) {
                const uint32_t* Ab = As + (wm*32 + mt*16 + lr)*68 + kc*16 + base;
                const uint32_t* Ab8 = Ab + 8*68;
                a[mt][0] = Ab[lc];
                a[mt][1] = Ab8[lc];
                a[mt][2] = Ab[lc+4];
                a[mt][3] = Ab8[lc+4];
            }
            uint32_t b[3][2][2];
            #pragma unroll
            for (int g=0; g<3; g++)
                #pragma unroll
                for (int jt=0; jt<2; jt++) {
                    int nb = g*64 + wj*16 + jt*8;
                    b[g][jt][0] = W1s[(base+lc)*200 + nb + lr];
                    b[g][jt][1] = W1s[(base+lc+4)*200 + nb + lr];
                }
            #pragma unroll
            for (int mt=0; mt<2; mt++)
                #pragma unroll
                for (int g=0; g<3; g++)
                    #pragma unroll
                    for (int jt=0; jt<2; jt++)
                        mma_f16(acc[mt][g][jt][0], acc[mt][g][jt][1],
                                acc[mt][g][jt][2], acc[mt][g][jt][3],
                                a[mt][0], a[mt][1], a[mt][2], a[mt][3],
                                b[g][jt][0], b[g][jt][1]);
        }
    }

    // epilogue: bias + LSTM nonlinearity, store CE (fp32)
    const float* B1t = g_B1 + t*384 + dir*192;
    #pragma unroll
    for (int mt=0; mt<2; mt++) {
        #pragma unroll
        for (int jt=0; jt<2; jt++) {
            int j = wj*16 + jt*8 + lc*2;
            float bi0 = B1t[j],     bi1 = B1t[j+1];
            float bg0 = B1t[64+j],  bg1 = B1t[64+j+1];
            float bo0 = B1t[128+j], bo1 = B1t[128+j+1];
            int r0 = m0 + wm*32 + mt*16 + lr;
            int r1 = r0 + 8;
            if (r0 < N_NODES) {
                float cc0 = sigmoid_f(acc[mt][0][jt][0]+bi0) * tanh_f(acc[mt][1][jt][0]+bg0);
                float cc1 = sigmoid_f(acc[mt][0][jt][1]+bi1) * tanh_f(acc[mt][1][jt][1]+bg1);
                float2 v;
                v.x = sigmoid_f(acc[mt][2][jt][0]+bo0) * tanh_f(cc0);
                v.y = sigmoid_f(acc[mt][2][jt][1]+bo1) * tanh_f(cc1);
                *(float2*)(ce + (size_t)r0*128 + dir*64 + j) = v;
            }
            if (r1 < N_NODES) {
                float cc0 = sigmoid_f(acc[mt][0][jt][2]+bi0) * tanh_f(acc[mt][1][jt][2]+bg0);
                float cc1 = sigmoid_f(acc[mt][0][jt][3]+bi1) * tanh_f(acc[mt][1][jt][3]+bg1);
                float2 v;
                v.x = sigmoid_f(acc[mt][2][jt][2]+bo0) * tanh_f(cc0);
                v.y = sigmoid_f(acc[mt][2][jt][3]+bo1) * tanh_f(cc1);
                *(float2*)(ce + (size_t)r1*128 + dir*64 + j) = v;
            }
        }
    }
}

// ---------------- stage B1: per-node seq-LSTM input projection (fp16 mma, gate-interleaved half2 out) ----------------
// grid (782, 4, 11); block 256 (8 warps); tile 64(M) x 128(N); smem ~26.1 KB
__global__ __launch_bounds__(256) void ig_kernel()
{
    extern __shared__ float sm[];
    uint32_t* As = (uint32_t*)sm;       // [64 rows][68] half2 words
    uint32_t* Ws = As + 64*68;          // [16 k2][136] half2 words (128 used)

    int t = blockIdx.z;
    const float* ce = g_CE + (size_t)t*N_NODES*128;
    uint32_t* igb = g_IGH + (size_t)t*N_NODES*256;
    int nt = blockIdx.y;        // 0..3 : 128-col chunk of 512
    int m0 = blockIdx.x*64;
    int tid = threadIdx.x;
    int warp = tid >> 5, lane = tid & 31;
    int wm = warp >> 2;         // 0..1 : 32-row half
    int wn = warp & 3;          // 0..3 : 32-col slice
    int lr = lane >> 2;
    int lc = lane & 3;

    {   // stage CE tile (64x128) as half2 words
        int rl = tid >> 5, c4 = tid & 31;
        #pragma unroll
        for (int it=0; it<8; it++) {
            int r = rl + it*8;
            int row = m0 + r; if (row >= N_NODES) row = N_NODES-1;
            float4 v = *(const float4*)(ce + (size_t)row*128 + c4*4);
            As[r*68 + 2*c4]     = pack_h2(v.x, v.y);
            As[r*68 + 2*c4 + 1] = pack_h2(v.z, v.w);
        }
    }

    float acc[2][4][4];   // [mtile][ntile][c-regs]
    #pragma unroll
    for (int mt=0;mt<2;mt++)
        #pragma unroll
        for (int n8=0;n8<4;n8++)
            #pragma unroll
            for (int r=0;r<4;r++) acc[mt][n8][r]=0.f;

    const uint32_t* W2t = g_W2H + (size_t)t*64*512 + nt*128;

    for (int kc=0; kc<4; kc++) {        // 16 k2-words per chunk
        __syncthreads();
        for (int it=0; it<2; it++) {     // 16x32 uint4 = 512
            int idx = tid + it*256;
            int k2l = idx >> 5, c4w = idx & 31;
            uint4 v = *(const uint4*)(W2t + (size_t)(kc*16+k2l)*512 + c4w*4);
            *(uint4*)&Ws[k2l*136 + c4w*4] = v;
        }
        __syncthreads();
        #pragma unroll
        for (int kit=0; kit<2; kit++) {
            int base = kit*8;
            uint32_t a[2][4];
            #pragma unroll
            for (int mt=0; mt<2; mt++) {
                const uint32_t* Ab = As + (wm*32 + mt*16 + lr)*68 + kc*16 + base;
                const uint32_t* Ab8 = Ab + 8*68;
                a[mt][0] = Ab[lc];
                a[mt][1] = Ab8[lc];
                a[mt][2] = Ab[lc+4];
                a[mt][3] = Ab8[lc+4];
            }
            uint32_t b[4][2];
            #pragma unroll
            for (int n8=0; n8<4; n8++) {
                int nb = wn*32 + n8*8;
                b[n8][0] = Ws[(base+lc)*136 + nb + lr];
                b[n8][1] = Ws[(base+lc+4)*136 + nb + lr];
            }
            #pragma unroll
            for (int mt=0; mt<2; mt++)
                #pragma unroll
                for (int n8=0; n8<4; n8++)
                    mma_f16(acc[mt][n8][0], acc[mt][n8][1], acc[mt][n8][2], acc[mt][n8][3],
                            a[mt][0], a[mt][1], a[mt][2], a[mt][3],
                            b[n8][0], b[n8][1]);
        }
    }

    // epilogue: add bias (fp32), pack preacts to half2 words in gate-interleaved layout:
    // word(node) = dir*128 + col2*4 + gate, col2 = j/2
    const float* B2t = g_B2 + t*512;
    #pragma unroll
    for (int mt=0; mt<2; mt++) {
        #pragma unroll
        for (int n8=0; n8<4; n8++) {
            int ncol = nt*128 + wn*32 + n8*8 + lc*2;
            int dircol = ncol >> 8;            // 0/1
            int r256 = ncol & 255;
            int gate = r256 >> 6;
            int j = r256 & 63;
            int wnew = dircol*128 + (j >> 1)*4 + gate;
            float b0 = B2t[ncol], b1 = B2t[ncol+1];
            int r0 = m0 + wm*32 + mt*16 + lr;
            int r1 = r0 + 8;
            if (r0 < N_NODES)
                igb[(size_t)r0*256 + wnew] = pack_h2(acc[mt][n8][0]+b0, acc[mt][n8][1]+b1);
            if (r1 < N_NODES)
                igb[(size_t)r1*256 + wnew] = pack_h2(acc[mt][n8][2]+b0, acc[mt][n8][3]+b1);
        }
    }
}

// ---------------- stage B2: fp16 recurrence (vectorized uint4 IG gather) ----------------
// grid (512, 2 dirs, 11 types); block 256 (8 warps); 32 batch rows/block; smem ~44.3 KB
// warp: wm (0..1) 16-row m-tile, wj (0..3) 16-j slice (all 4 gates, 2 jt of 8)
__global__ __launch_bounds__(256) void recur_kernel(const int* __restrict__ neigh_ids)
{
    extern __shared__ float sm[];
    uint32_t* smw = (uint32_t*)sm;
    uint32_t* Whh_s = smw;               // [32 k2][264] half2 words
    uint32_t* hA0 = smw + 32*264;        // [32 rows][36] half2 words
    uint32_t* hA1 = hA0 + 32*36;
    int* ids_s = (int*)(hA1 + 32*36);    // [32][10]

    int t = blockIdx.z;
    int dir = blockIdx.y;
    int b0 = blockIdx.x*32;
    int tid = threadIdx.x;
    int warp = tid >> 5, lane = tid & 31;
    int wm = warp >> 2;            // 0..1
    int wj = warp & 3;             // 0..3
    int lr = lane >> 2, lc = lane & 3;

    // stage Whh half2 [32][256] -> smem [32][264]
    const uint32_t* Wsrc = g_WhhH + ((size_t)t*2 + dir)*32*256;
    #pragma unroll
    for (int it=0; it<8; it++) {          // 2048 uint4
        int idx = tid + it*256;
        int k2 = idx >> 6, c4 = idx & 63;
        uint4 v = *(const uint4*)(Wsrc + (size_t)k2*256 + c4*4);
        *(uint4*)&Whh_s[k2*264 + c4*4] = v;
    }
    for (int idx = tid; idx < 32*36; idx += 256) hA0[idx] = 0u;
    {
        const int* nsrc = neigh_ids + ((size_t)t*B_ + b0)*K_;
        for (int idx = tid; idx < 32*K_; idx += 256) ids_s[idx] = nsrc[idx];
    }
    __syncthreads();

    const uint32_t* ig = g_IGH + (size_t)t*N_NODES*256 + dir*128;
    int row_lo = wm*16 + lr;               // block-local rows: row_lo, row_lo+8

    float c[2][4], hs[2][4];               // [jt][0:lo.x 1:lo.y 2:hi.x 3:hi.y]
    #pragma unroll
    for (int jt=0;jt<2;jt++)
        #pragma unroll
        for (int e=0;e<4;e++){ c[jt][e]=0.f; hs[jt][e]=0.f; }

    uint32_t* cur = hA0; uint32_t* nxt = hA1;

    for (int step=0; step<K_; step++) {
        int k = dir ? (K_-1-step) : step;
        const uint32_t* ig_lo = ig + (size_t)ids_s[row_lo*K_ + k]*256;
        const uint32_t* ig_hi = ig + (size_t)ids_s[(row_lo+8)*K_ + k]*256;

        // vectorized IG gather: one uint4 = 4 gate-words for one column-pair.
        // per thread per step: 4 x LDG.128 (was 16 scalar LDGs); quad lanes are
        // contiguous 64B segments. Issued before the mma stream to hide latency.
        uint4 igq[2][2];                   // [jt][lo/hi]
        #pragma unroll
        for (int jt=0; jt<2; jt++) {
            int c2 = wj*8 + jt*4 + lc;     // col2 index
            igq[jt][0] = *(const uint4*)(ig_lo + c2*4);
            igq[jt][1] = *(const uint4*)(ig_hi + c2*4);
        }

        // acc = h_prev @ WhhT  (f16 m16n8k16 mma)
        float acc[4][2][4];                // [gate][jt][c-regs]
        #pragma unroll
        for (int g=0;g<4;g++)
            #pragma unroll
            for (int jt=0;jt<2;jt++)
                #pragma unroll
                for (int r=0;r<4;r++) acc[g][jt][r]=0.f;

        #pragma unroll
        for (int kit=0; kit<4; kit++) {
            int kb2 = kit*8;
            uint32_t a0 = cur[row_lo*36 + kb2 + lc];
            uint32_t a1 = cur[(row_lo+8)*36 + kb2 + lc];
            uint32_t a2 = cur[row_lo*36 + kb2 + lc + 4];
            uint32_t a3 = cur[(row_lo+8)*36 + kb2 + lc + 4];
            #pragma unroll
            for (int g=0; g<4; g++)
                #pragma unroll
                for (int jt=0; jt<2; jt++) {
                    int nb = g*64 + wj*16 + jt*8;
                    uint32_t bb0 = Whh_s[(kb2+lc)*264 + nb + lr];
                    uint32_t bb1 = Whh_s[(kb2+lc+4)*264 + nb + lr];
                    mma_f16(acc[g][jt][0], acc[g][jt][1], acc[g][jt][2], acc[g][jt][3],
                            a0, a1, a2, a3, bb0, bb1);
                }
        }

        // epilogue: gates, state update, h -> nxt (half2)
        #pragma unroll
        for (int jt=0; jt<2; jt++) {
            int jw = wj*8 + jt*4 + lc;
            // row lo (regs 0,1)
            {
                float2 vi = unpack_h2(igq[jt][0].x);
                float2 vf = unpack_h2(igq[jt][0].y);
                float2 vg = unpack_h2(igq[jt][0].z);
                float2 vo = unpack_h2(igq[jt][0].w);
                c[jt][0] = sigmoid_f(acc[1][jt][0]+vf.x)*c[jt][0]
                         + sigmoid_f(acc[0][jt][0]+vi.x)*tanh_f(acc[2][jt][0]+vg.x);
                c[jt][1] = sigmoid_f(acc[1][jt][1]+vf.y)*c[jt][1]
                         + sigmoid_f(acc[0][jt][1]+vi.y)*tanh_f(acc[2][jt][1]+vg.y);
                float h0 = sigmoid_f(acc[3][jt][0]+vo.x)*tanh_f(c[jt][0]);
                float h1 = sigmoid_f(acc[3][jt][1]+vo.y)*tanh_f(c[jt][1]);
                hs[jt][0] += h0; hs[jt][1] += h1;
                nxt[row_lo*36 + jw] = pack_h2(h0, h1);
            }
            // row hi (regs 2,3)
            {
                float2 vi = unpack_h2(igq[jt][1].x);
                float2 vf = unpack_h2(igq[jt][1].y);
                float2 vg = unpack_h2(igq[jt][1].z);
                float2 vo = unpack_h2(igq[jt][1].w);
                c[jt][2] = sigmoid_f(acc[1][jt][2]+vf.x)*c[jt][2]
                         + sigmoid_f(acc[0][jt][2]+vi.x)*tanh_f(acc[2][jt][2]+vg.x);
                c[jt][3] = sigmoid_f(acc[1][jt][3]+vf.y)*c[jt][3]
                         + sigmoid_f(acc[0][jt][3]+vi.y)*tanh_f(acc[2][jt][3]+vg.y);
                float h0 = sigmoid_f(acc[3][jt][2]+vo.x)*tanh_f(c[jt][2]);
                float h1 = sigmoid_f(acc[3][jt][3]+vo.y)*tanh_f(c[jt][3]);
                hs[jt][2] += h0; hs[jt][3] += h1;
                nxt[(row_lo+8)*36 + jw] = pack_h2(h0, h1);
            }
        }
        __syncthreads();   // nxt complete before it becomes cur
        uint32_t* tmp = cur; cur = nxt; nxt = tmp;
    }

    // mean over K, store
    #pragma unroll
    for (int jt=0; jt<2; jt++) {
        int jb = wj*16 + jt*8 + lc*2;
        int blo = b0 + row_lo, bhi = blo + 8;
        float2 v0; v0.x = hs[jt][0]*(1.0f/K_); v0.y = hs[jt][1]*(1.0f/K_);
        float2 v1; v1.x = hs[jt][2]*(1.0f/K_); v1.y = hs[jt][3]*(1.0f/K_);
        *(float2*)(g_AGG + ((size_t)t*B_ + blo)*128 + dir*64 + jb) = v0;
        *(float2*)(g_AGG + ((size_t)t*B_ + bhi)*128 + dir*64 + jb) = v1;
    }
}

// ---------------- stage C: attention combine (self embed gathered from CE type 0) ----------------
__global__ __launch_bounds__(256) void attn_kernel(const int* __restrict__ id_batch,
                                                   const float* __restrict__ att,
                                                   float* __restrict__ out)
{
    int warp = threadIdx.x >> 5;
    int lane = threadIdx.x & 31;
    int b = blockIdx.x*8 + warp;
    int id = id_batch[b];

    float e[12][4], a0[4], a1[4];
    #pragma unroll
    for (int i=0;i<4;i++) {
        int d = i*32 + lane;
        a0[i] = att[d];
        a1[i] = att[128+d];
        e[0][i] = g_CE[(size_t)id*128 + d];    // c_self = CE type-0 row
    }
    #pragma unroll
    for (int t=0;t<T_;t++)
        #pragma unroll
        for (int i=0;i<4;i++)
            e[1+t][i] = g_AGG[((size_t)t*B_ + b)*128 + i*32 + lane];

    float pself = 0.f;
    #pragma unroll
    for (int i=0;i<4;i++) pself += e[0][i]*a0[i];
    float sc[12];
    #pragma unroll
    for (int j=0;j<12;j++) {
        float p = 0.f;
        #pragma unroll
        for (int i=0;i<4;i++) p += e[j][i]*a1[i];
        sc[j] = p;
    }
    #pragma unroll
    for (int off=16; off>0; off>>=1) {
        pself += __shfl_xor_sync(0xffffffff, pself, off);
        #pragma unroll
        for (int j=0;j<12;j++) sc[j] += __shfl_xor_sync(0xffffffff, sc[j], off);
    }
    float mx = -1e30f;
    #pragma unroll
    for (int j=0;j<12;j++) {
        float s = pself + sc[j];
        s = (s > 0.f) ? s : 0.01f*s;    // leaky_relu(0.01)
        sc[j] = s;
        mx = fmaxf(mx, s);
    }
    float sum = 0.f;
    #pragma unroll
    for (int j=0;j<12;j++) { sc[j] = expf(sc[j]-mx); sum += sc[j]; }
    float inv = 1.f/sum;
    #pragma unroll
    for (int i=0;i<4;i++) {
        float o = 0.f;
        #pragma unroll
        for (int j=0;j<12;j++) o += sc[j]*e[j][i];
        out[(size_t)b*128 + i*32 + lane] = o*inv;
    }
}

// ---------------- launch (single stream, 5 launches) ----------------
extern "C" void kernel_launch(void* const* d_in, const int* in_sizes, int n_in,
                              void* d_out, int out_size)
{
    const float* features = (const float*)d_in[0];
    const int*   id_batch = (const int*)d_in[1];
    const int*   neigh_ids= (const int*)d_in[2];
    const float* cWih_f   = (const float*)d_in[3];
    const float* cb_f     = (const float*)d_in[5];
    const float* cWih_b   = (const float*)d_in[6];
    const float* cb_b     = (const float*)d_in[8];
    const float* nWih_f   = (const float*)d_in[9];
    const float* nWhh_f   = (const float*)d_in[10];
    const float* nb_f     = (const float*)d_in[11];
    const float* nWih_b   = (const float*)d_in[12];
    const float* nWhh_b   = (const float*)d_in[13];
    const float* nb_b     = (const float*)d_in[14];
    const float* att      = (const float*)d_in[15];
    float* out = (float*)d_out;

    const int SMEM_CONTENT = (64*68 + 16*200) * 4;              // 30208
    const int SMEM_IG      = (64*68 + 16*136) * 4;              // 26112
    const int SMEM_RECUR   = (32*264 + 2*32*36 + 32*K_) * 4;    // 44288
    cudaFuncSetAttribute(content_kernel, cudaFuncAttributeMaxDynamicSharedMemorySize, SMEM_CONTENT);
    cudaFuncSetAttribute(ig_kernel,      cudaFuncAttributeMaxDynamicSharedMemorySize, SMEM_IG);
    cudaFuncSetAttribute(recur_kernel,   cudaFuncAttributeMaxDynamicSharedMemorySize, SMEM_RECUR);

    pack_kernel<<<512, 256>>>(cWih_f, cb_f, cWih_b, cb_b,
                              nWih_f, nb_f, nWih_b, nb_b, nWhh_f, nWhh_b);

    {   // content encode, all types
        dim3 g(MROW_BLKS, 2, T_);
        content_kernel<<<g, 256, SMEM_CONTENT>>>(features);
    }
    {   // seq-LSTM input projections, all types
        dim3 g(MROW_BLKS, 4, T_);
        ig_kernel<<<g, 256, SMEM_IG>>>();
    }
    {   // recurrence, all types
        dim3 g(B_/32, 2, T_);
        recur_kernel<<<g, 256, SMEM_RECUR>>>(neigh_ids);
    }
    attn_kernel<<<B_/8, 256>>>(id_batch, att, out);
}

// round 17
// speedup vs baseline: 12.5444x; 1.0502x over previous
#include <cuda_runtime.h>
#include <cuda_fp16.h>
#include <stdint.h>
#include <stddef.h>
#include <math.h>

#define T_ 11
#define N_NODES 50000
#define D_ 128
#define H_ 64
#define B_ 16384
#define K_ 10
#define MROW_BLKS 782    // ceil(50000/64)

// ---------------- scratch (device globals; ~600 MB total) ----------------
__device__ uint32_t g_W1H[(size_t)T_*64*384];  // content Wih half2 k-pairs: [t][k2][n], n = dir*192+gate*64+j
__device__ float    g_B1[T_*384];
__device__ uint32_t g_W2H[(size_t)T_*64*512];  // seq Wih half2 k-pairs: [t][k2][n], n = dir*256+r
__device__ float    g_B2[T_*512];
__device__ uint32_t g_WhhH[(size_t)T_*2*32*256]; // [t][dir][k2][n=256] half2 (k-pairs), mma-B layout
__device__ float    g_CE0[(size_t)N_NODES*128];  // fp32 content encodings, TYPE 0 ONLY (attn self-embed)
// IG preacts, half2 words, GATE-INTERLEAVED: word(node, dir, col2, gate) at
// [node*256 + dir*128 + col2*4 + gate]; col2 = j/2. One uint4 = all 4 gates.
__device__ uint32_t g_IGH[(size_t)T_*N_NODES*256];
__device__ float    g_AGG[(size_t)T_*B_*128];

// HW tanh (MUFU.TANH, sm_75+)
__device__ __forceinline__ float tanh_f(float x){
    float r; asm("tanh.approx.f32 %0, %1;" : "=f"(r) : "f"(x)); return r;
}
__device__ __forceinline__ float sigmoid_f(float x){
    float r; asm("tanh.approx.f32 %0, %1;" : "=f"(r) : "f"(0.5f*x));
    return fmaf(0.5f, r, 0.5f);
}
__device__ __forceinline__ void mma_f16(float& c0, float& c1, float& c2, float& c3,
                                        uint32_t a0, uint32_t a1, uint32_t a2, uint32_t a3,
                                        uint32_t b0, uint32_t b1){
    asm volatile("mma.sync.aligned.m16n8k16.row.col.f32.f16.f16.f32 "
                 "{%0,%1,%2,%3},{%4,%5,%6,%7},{%8,%9},{%0,%1,%2,%3};"
                 : "+f"(c0), "+f"(c1), "+f"(c2), "+f"(c3)
                 : "r"(a0), "r"(a1), "r"(a2), "r"(a3), "r"(b0), "r"(b1));
}
__device__ __forceinline__ uint32_t pack_h2(float a, float b){
    __half2 p = __floats2half2_rn(a, b);
    return *reinterpret_cast<uint32_t*>(&p);
}
__device__ __forceinline__ float2 unpack_h2(uint32_t w){
    return __half22float2(*reinterpret_cast<__half2*>(&w));
}

// ---------------- weight packing ----------------
__global__ void pack_kernel(const float* __restrict__ cWih_f, const float* __restrict__ cb_f,
                            const float* __restrict__ cWih_b, const float* __restrict__ cb_b,
                            const float* __restrict__ nWih_f, const float* __restrict__ nb_f,
                            const float* __restrict__ nWih_b, const float* __restrict__ nb_b,
                            const float* __restrict__ nWhh_f, const float* __restrict__ nWhh_b)
{
    int stride = gridDim.x*blockDim.x;
    int tid0 = blockIdx.x*blockDim.x + threadIdx.x;

    // W1H: [t][k2][n], n = dir*192 + gate*64 + j, gate 0:i 1:g 2:o (f-gate dead: zero state)
    for (size_t idx = tid0; idx < (size_t)T_*64*384; idx += stride) {
        int n = (int)(idx % 384); size_t rest = idx / 384;
        int k2 = (int)(rest % 64); int t = (int)(rest / 64);
        int dir = n/192, rem = n%192, g = rem/64, j = rem%64;
        int row = (g==0) ? j : (g==1) ? 128+j : 192+j;
        const float* W = dir ? cWih_b : cWih_f;
        float w0 = W[((size_t)t*256 + row)*128 + 2*k2];
        float w1 = W[((size_t)t*256 + row)*128 + 2*k2 + 1];
        g_W1H[idx] = pack_h2(w0, w1);
    }
    for (int idx = tid0; idx < T_*384; idx += stride) {
        int n = idx % 384; int t = idx / 384;
        int dir = n/192, rem = n%192, g = rem/64, j = rem%64;
        int row = (g==0) ? j : (g==1) ? 128+j : 192+j;
        g_B1[idx] = (dir ? cb_b : cb_f)[t*256 + row];
    }
    // W2H: [t][k2][n], n = dir*256 + r  (natural gate rows i,f,g,o)
    for (size_t idx = tid0; idx < (size_t)T_*64*512; idx += stride) {
        int n = (int)(idx % 512); size_t rest = idx/512;
        int k2 = (int)(rest % 64); int t = (int)(rest/64);
        int dir = n/256, r = n%256;
        const float* W = dir ? nWih_b : nWih_f;
        float w0 = W[((size_t)t*256 + r)*128 + 2*k2];
        float w1 = W[((size_t)t*256 + r)*128 + 2*k2 + 1];
        g_W2H[idx] = pack_h2(w0, w1);
    }
    for (int idx = tid0; idx < T_*512; idx += stride) {
        int n = idx % 512; int t = idx/512;
        int dir = n/256, r = n%256;
        g_B2[idx] = (dir ? nb_b : nb_f)[t*256 + r];
    }
    // Whh half2 mma-B layout: word(k2,n) = half2(W[n][2k2], W[n][2k2+1])
    for (size_t idx = tid0; idx < (size_t)T_*2*32*256; idx += stride) {
        int n = (int)(idx % 256); size_t rest = idx/256;
        int k2 = (int)(rest % 32); rest /= 32;
        int dir = (int)(rest % 2); int t = (int)(rest/2);
        const float* W = dir ? nWhh_b : nWhh_f;
        float w0 = W[((size_t)t*256 + n)*64 + 2*k2];
        float w1 = W[((size_t)t*256 + n)*64 + 2*k2 + 1];
        g_WhhH[idx] = pack_h2(w0, w1);
    }
}

// ---------------- FUSED projection: content encode + seq-LSTM input projection ----------------
// grid (782, 11 types); block 256 (8 warps); 64 node-rows per block; smem ~47.6 KB
// Phase 1 (per dir): CE = LSTM(feat @ W1) -> half2 smem (fp32 gmem for t==0 only)
// Phase 2 (per 128-col chunk): IG = CE @ W2 + b -> g_IGH (gate-interleaved half2)
__global__ __launch_bounds__(256) void proj_kernel(const float* __restrict__ features)
{
    extern __shared__ float sm[];
    uint32_t* As  = (uint32_t*)sm;      // [64 rows][68] feat half2 words
    uint32_t* CEs = As + 64*68;         // [64 rows][68] CE half2 words (64 used)
    uint32_t* Ws  = CEs + 64*68;        // [16 k2][200] weight chunk (192/128 used)

    int t = blockIdx.y;
    const float* feat = features + (size_t)t*N_NODES*128;
    uint32_t* igb = g_IGH + (size_t)t*N_NODES*256;
    int m0 = blockIdx.x*64;
    int tid = threadIdx.x;
    int warp = tid >> 5, lane = tid & 31;
    int wm = warp >> 2;          // 0..1 : 32-row half
    int wj = warp & 3;           // 0..3
    int lr = lane >> 2;          // 0..7
    int lc = lane & 3;           // 0..3

    {   // stage feat tile (64x128) as half2 words; clamp tail rows
        int rl = tid >> 5, c4 = tid & 31;
        #pragma unroll
        for (int it = 0; it < 8; it++) {
            int r = rl + it*8;
            int row = m0 + r; if (row >= N_NODES) row = N_NODES-1;
            float4 v = *(const float4*)(feat + (size_t)row*128 + c4*4);
            As[r*68 + 2*c4]     = pack_h2(v.x, v.y);
            As[r*68 + 2*c4 + 1] = pack_h2(v.z, v.w);
        }
    }

    // ---- phase 1: content encode, one dir at a time ----
    for (int dir = 0; dir < 2; dir++) {
        float acc[2][3][2][4];   // [mtile][gate][jtile][c-regs]
        #pragma unroll
        for (int mt=0;mt<2;mt++)
            #pragma unroll
            for (int g=0;g<3;g++)
                #pragma unroll
                for (int jt=0;jt<2;jt++)
                    #pragma unroll
                    for (int r=0;r<4;r++) acc[mt][g][jt][r]=0.f;

        const uint32_t* W1t = g_W1H + (size_t)t*64*384 + dir*192;

        for (int kc = 0; kc < 4; kc++) {     // 16 k2-words per chunk (k=32)
            __syncthreads();
            for (int it = 0; it < 3; it++) {          // 16x48 uint4 = 768
                int idx = tid + it*256;
                int k2l = idx / 48, c4w = idx % 48;
                uint4 v = *(const uint4*)(W1t + (size_t)(kc*16+k2l)*384 + c4w*4);
                *(uint4*)&Ws[k2l*200 + c4w*4] = v;
            }
            __syncthreads();
            #pragma unroll
            for (int kit = 0; kit < 2; kit++) {
                int base = kit*8;
                uint32_t a[2][4];
                #pragma unroll
                for (int mt=0; mt<2; mt++) {
                    const uint32_t* Ab = As + (wm*32 + mt*16 + lr)*68 + kc*16 + base;
                    const uint32_t* Ab8 = Ab + 8*68;
                    a[mt][0] = Ab[lc];
                    a[mt][1] = Ab8[lc];
                    a[mt][2] = Ab[lc+4];
                    a[mt][3] = Ab8[lc+4];
                }
                uint32_t b[3][2][2];
                #pragma unroll
                for (int g=0; g<3; g++)
                    #pragma unroll
                    for (int jt=0; jt<2; jt++) {
                        int nb = g*64 + wj*16 + jt*8;
                        b[g][jt][0] = Ws[(base+lc)*200 + nb + lr];
                        b[g][jt][1] = Ws[(base+lc+4)*200 + nb + lr];
                    }
                #pragma unroll
                for (int mt=0; mt<2; mt++)
                    #pragma unroll
                    for (int g=0; g<3; g++)
                        #pragma unroll
                        for (int jt=0; jt<2; jt++)
                            mma_f16(acc[mt][g][jt][0], acc[mt][g][jt][1],
                                    acc[mt][g][jt][2], acc[mt][g][jt][3],
                                    a[mt][0], a[mt][1], a[mt][2], a[mt][3],
                                    b[g][jt][0], b[g][jt][1]);
            }
        }

        // epilogue: bias + LSTM nonlinearity -> CE half2 in smem (+ fp32 gmem for t==0)
        const float* B1t = g_B1 + t*384 + dir*192;
        #pragma unroll
        for (int mt=0; mt<2; mt++) {
            #pragma unroll
            for (int jt=0; jt<2; jt++) {
                int j = wj*16 + jt*8 + lc*2;
                float bi0 = B1t[j],     bi1 = B1t[j+1];
                float bg0 = B1t[64+j],  bg1 = B1t[64+j+1];
                float bo0 = B1t[128+j], bo1 = B1t[128+j+1];
                int rloc0 = wm*32 + mt*16 + lr;
                int rloc1 = rloc0 + 8;
                int cew = dir*32 + wj*8 + jt*4 + lc;   // CE half2 word index
                {
                    float cc0 = sigmoid_f(acc[mt][0][jt][0]+bi0) * tanh_f(acc[mt][1][jt][0]+bg0);
                    float cc1 = sigmoid_f(acc[mt][0][jt][1]+bi1) * tanh_f(acc[mt][1][jt][1]+bg1);
                    float v0 = sigmoid_f(acc[mt][2][jt][0]+bo0) * tanh_f(cc0);
                    float v1 = sigmoid_f(acc[mt][2][jt][1]+bo1) * tanh_f(cc1);
                    CEs[rloc0*68 + cew] = pack_h2(v0, v1);
                    int row = m0 + rloc0;
                    if (t == 0 && row < N_NODES) {
                        float2 w; w.x = v0; w.y = v1;
                        *(float2*)(g_CE0 + (size_t)row*128 + dir*64 + j) = w;
                    }
                }
                {
                    float cc0 = sigmoid_f(acc[mt][0][jt][2]+bi0) * tanh_f(acc[mt][1][jt][2]+bg0);
                    float cc1 = sigmoid_f(acc[mt][0][jt][3]+bi1) * tanh_f(acc[mt][1][jt][3]+bg1);
                    float v0 = sigmoid_f(acc[mt][2][jt][2]+bo0) * tanh_f(cc0);
                    float v1 = sigmoid_f(acc[mt][2][jt][3]+bo1) * tanh_f(cc1);
                    CEs[rloc1*68 + cew] = pack_h2(v0, v1);
                    int row = m0 + rloc1;
                    if (t == 0 && row < N_NODES) {
                        float2 w; w.x = v0; w.y = v1;
                        *(float2*)(g_CE0 + (size_t)row*128 + dir*64 + j) = w;
                    }
                }
            }
        }
    }

    // ---- phase 2: IG projection from smem CE ----
    int wn = warp & 3;          // 0..3 : 32-col slice
    for (int nt = 0; nt < 4; nt++) {
        float acc[2][4][4];   // [mtile][ntile][c-regs]
        #pragma unroll
        for (int mt=0;mt<2;mt++)
            #pragma unroll
            for (int n8=0;n8<4;n8++)
                #pragma unroll
                for (int r=0;r<4;r++) acc[mt][n8][r]=0.f;

        const uint32_t* W2t = g_W2H + (size_t)t*64*512 + nt*128;

        for (int kc=0; kc<4; kc++) {        // 16 k2-words per chunk
            __syncthreads();                 // guards Ws overwrite AND (first pass) CEs writes
            for (int it=0; it<2; it++) {     // 16x32 uint4 = 512
                int idx = tid + it*256;
                int k2l = idx >> 5, c4w = idx & 31;
                uint4 v = *(const uint4*)(W2t + (size_t)(kc*16+k2l)*512 + c4w*4);
                *(uint4*)&Ws[k2l*200 + c4w*4] = v;
            }
            __syncthreads();
            #pragma unroll
            for (int kit=0; kit<2; kit++) {
                int base = kit*8;
                uint32_t a[2][4];
                #pragma unroll
                for (int mt=0; mt<2; mt++) {
                    const uint32_t* Ab = CEs + (wm*32 + mt*16 + lr)*68 + kc*16 + base;
                    const uint32_t* Ab8 = Ab + 8*68;
                    a[mt][0] = Ab[lc];
                    a[mt][1] = Ab8[lc];
                    a[mt][2] = Ab[lc+4];
                    a[mt][3] = Ab8[lc+4];
                }
                uint32_t b[4][2];
                #pragma unroll
                for (int n8=0; n8<4; n8++) {
                    int nb = wn*32 + n8*8;
                    b[n8][0] = Ws[(base+lc)*200 + nb + lr];
                    b[n8][1] = Ws[(base+lc+4)*200 + nb + lr];
                }
                #pragma unroll
                for (int mt=0; mt<2; mt++)
                    #pragma unroll
                    for (int n8=0; n8<4; n8++)
                        mma_f16(acc[mt][n8][0], acc[mt][n8][1], acc[mt][n8][2], acc[mt][n8][3],
                                a[mt][0], a[mt][1], a[mt][2], a[mt][3],
                                b[n8][0], b[n8][1]);
            }
        }

        // epilogue: add bias (fp32), scatter preacts to gate-interleaved half2 layout
        const float* B2t = g_B2 + t*512;
        #pragma unroll
        for (int mt=0; mt<2; mt++) {
            #pragma unroll
            for (int n8=0; n8<4; n8++) {
                int ncol = nt*128 + wn*32 + n8*8 + lc*2;
                int dircol = ncol >> 8;            // 0/1
                int r256 = ncol & 255;
                int gate = r256 >> 6;
                int j = r256 & 63;
                int wnew = dircol*128 + (j >> 1)*4 + gate;
                float b0 = B2t[ncol], b1 = B2t[ncol+1];
                int r0 = m0 + wm*32 + mt*16 + lr;
                int r1 = r0 + 8;
                if (r0 < N_NODES)
                    igb[(size_t)r0*256 + wnew] = pack_h2(acc[mt][n8][0]+b0, acc[mt][n8][1]+b1);
                if (r1 < N_NODES)
                    igb[(size_t)r1*256 + wnew] = pack_h2(acc[mt][n8][2]+b0, acc[mt][n8][3]+b1);
            }
        }
    }
}

// ---------------- stage B2: fp16 recurrence (vectorized uint4 IG gather) ----------------
// grid (512, 2 dirs, 11 types); block 256 (8 warps); 32 batch rows/block; smem ~44.3 KB
__global__ __launch_bounds__(256) void recur_kernel(const int* __restrict__ neigh_ids)
{
    extern __shared__ float sm[];
    uint32_t* smw = (uint32_t*)sm;
    uint32_t* Whh_s = smw;               // [32 k2][264] half2 words
    uint32_t* hA0 = smw + 32*264;        // [32 rows][36] half2 words
    uint32_t* hA1 = hA0 + 32*36;
    int* ids_s = (int*)(hA1 + 32*36);    // [32][10]

    int t = blockIdx.z;
    int dir = blockIdx.y;
    int b0 = blockIdx.x*32;
    int tid = threadIdx.x;
    int warp = tid >> 5, lane = tid & 31;
    int wm = warp >> 2;            // 0..1
    int wj = warp & 3;             // 0..3
    int lr = lane >> 2, lc = lane & 3;

    // stage Whh half2 [32][256] -> smem [32][264]
    const uint32_t* Wsrc = g_WhhH + ((size_t)t*2 + dir)*32*256;
    #pragma unroll
    for (int it=0; it<8; it++) {          // 2048 uint4
        int idx = tid + it*256;
        int k2 = idx >> 6, c4 = idx & 63;
        uint4 v = *(const uint4*)(Wsrc + (size_t)k2*256 + c4*4);
        *(uint4*)&Whh_s[k2*264 + c4*4] = v;
    }
    for (int idx = tid; idx < 32*36; idx += 256) hA0[idx] = 0u;
    {
        const int* nsrc = neigh_ids + ((size_t)t*B_ + b0)*K_;
        for (int idx = tid; idx < 32*K_; idx += 256) ids_s[idx] = nsrc[idx];
    }
    __syncthreads();

    const uint32_t* ig = g_IGH + (size_t)t*N_NODES*256 + dir*128;
    int row_lo = wm*16 + lr;               // block-local rows: row_lo, row_lo+8

    float c[2][4], hs[2][4];               // [jt][0:lo.x 1:lo.y 2:hi.x 3:hi.y]
    #pragma unroll
    for (int jt=0;jt<2;jt++)
        #pragma unroll
        for (int e=0;e<4;e++){ c[jt][e]=0.f; hs[jt][e]=0.f; }

    uint32_t* cur = hA0; uint32_t* nxt = hA1;

    for (int step=0; step<K_; step++) {
        int k = dir ? (K_-1-step) : step;
        const uint32_t* ig_lo = ig + (size_t)ids_s[row_lo*K_ + k]*256;
        const uint32_t* ig_hi = ig + (size_t)ids_s[(row_lo+8)*K_ + k]*256;

        // vectorized IG gather: one uint4 = 4 gate-words for one column-pair
        uint4 igq[2][2];                   // [jt][lo/hi]
        #pragma unroll
        for (int jt=0; jt<2; jt++) {
            int c2 = wj*8 + jt*4 + lc;     // col2 index
            igq[jt][0] = *(const uint4*)(ig_lo + c2*4);
            igq[jt][1] = *(const uint4*)(ig_hi + c2*4);
        }

        // acc = h_prev @ WhhT  (f16 m16n8k16 mma)
        float acc[4][2][4];                // [gate][jt][c-regs]
        #pragma unroll
        for (int g=0;g<4;g++)
            #pragma unroll
            for (int jt=0;jt<2;jt++)
                #pragma unroll
                for (int r=0;r<4;r++) acc[g][jt][r]=0.f;

        #pragma unroll
        for (int kit=0; kit<4; kit++) {
            int kb2 = kit*8;
            uint32_t a0 = cur[row_lo*36 + kb2 + lc];
            uint32_t a1 = cur[(row_lo+8)*36 + kb2 + lc];
            uint32_t a2 = cur[row_lo*36 + kb2 + lc + 4];
            uint32_t a3 = cur[(row_lo+8)*36 + kb2 + lc + 4];
            #pragma unroll
            for (int g=0; g<4; g++)
                #pragma unroll
                for (int jt=0; jt<2; jt++) {
                    int nb = g*64 + wj*16 + jt*8;
                    uint32_t bb0 = Whh_s[(kb2+lc)*264 + nb + lr];
                    uint32_t bb1 = Whh_s[(kb2+lc+4)*264 + nb + lr];
                    mma_f16(acc[g][jt][0], acc[g][jt][1], acc[g][jt][2], acc[g][jt][3],
                            a0, a1, a2, a3, bb0, bb1);
                }
        }

        // epilogue: gates, state update, h -> nxt (half2)
        #pragma unroll
        for (int jt=0; jt<2; jt++) {
            int jw = wj*8 + jt*4 + lc;
            // row lo (regs 0,1)
            {
                float2 vi = unpack_h2(igq[jt][0].x);
                float2 vf = unpack_h2(igq[jt][0].y);
                float2 vg = unpack_h2(igq[jt][0].z);
                float2 vo = unpack_h2(igq[jt][0].w);
                c[jt][0] = sigmoid_f(acc[1][jt][0]+vf.x)*c[jt][0]
                         + sigmoid_f(acc[0][jt][0]+vi.x)*tanh_f(acc[2][jt][0]+vg.x);
                c[jt][1] = sigmoid_f(acc[1][jt][1]+vf.y)*c[jt][1]
                         + sigmoid_f(acc[0][jt][1]+vi.y)*tanh_f(acc[2][jt][1]+vg.y);
                float h0 = sigmoid_f(acc[3][jt][0]+vo.x)*tanh_f(c[jt][0]);
                float h1 = sigmoid_f(acc[3][jt][1]+vo.y)*tanh_f(c[jt][1]);
                hs[jt][0] += h0; hs[jt][1] += h1;
                nxt[row_lo*36 + jw] = pack_h2(h0, h1);
            }
            // row hi (regs 2,3)
            {
                float2 vi = unpack_h2(igq[jt][1].x);
                float2 vf = unpack_h2(igq[jt][1].y);
                float2 vg = unpack_h2(igq[jt][1].z);
                float2 vo = unpack_h2(igq[jt][1].w);
                c[jt][2] = sigmoid_f(acc[1][jt][2]+vf.x)*c[jt][2]
                         + sigmoid_f(acc[0][jt][2]+vi.x)*tanh_f(acc[2][jt][2]+vg.x);
                c[jt][3] = sigmoid_f(acc[1][jt][3]+vf.y)*c[jt][3]
                         + sigmoid_f(acc[0][jt][3]+vi.y)*tanh_f(acc[2][jt][3]+vg.y);
                float h0 = sigmoid_f(acc[3][jt][2]+vo.x)*tanh_f(c[jt][2]);
                float h1 = sigmoid_f(acc[3][jt][3]+vo.y)*tanh_f(c[jt][3]);
                hs[jt][2] += h0; hs[jt][3] += h1;
                nxt[(row_lo+8)*36 + jw] = pack_h2(h0, h1);
            }
        }
        __syncthreads();   // nxt complete before it becomes cur
        uint32_t* tmp = cur; cur = nxt; nxt = tmp;
    }

    // mean over K, store
    #pragma unroll
    for (int jt=0; jt<2; jt++) {
        int jb = wj*16 + jt*8 + lc*2;
        int blo = b0 + row_lo, bhi = blo + 8;
        float2 v0; v0.x = hs[jt][0]*(1.0f/K_); v0.y = hs[jt][1]*(1.0f/K_);
        float2 v1; v1.x = hs[jt][2]*(1.0f/K_); v1.y = hs[jt][3]*(1.0f/K_);
        *(float2*)(g_AGG + ((size_t)t*B_ + blo)*128 + dir*64 + jb) = v0;
        *(float2*)(g_AGG + ((size_t)t*B_ + bhi)*128 + dir*64 + jb) = v1;
    }
}

// ---------------- stage C: attention combine (self embed from g_CE0) ----------------
__global__ __launch_bounds__(256) void attn_kernel(const int* __restrict__ id_batch,
                                                   const float* __restrict__ att,
                                                   float* __restrict__ out)
{
    int warp = threadIdx.x >> 5;
    int lane = threadIdx.x & 31;
    int b = blockIdx.x*8 + warp;
    int id = id_batch[b];

    float e[12][4], a0[4], a1[4];
    #pragma unroll
    for (int i=0;i<4;i++) {
        int d = i*32 + lane;
        a0[i] = att[d];
        a1[i] = att[128+d];
        e[0][i] = g_CE0[(size_t)id*128 + d];
    }
    #pragma unroll
    for (int t=0;t<T_;t++)
        #pragma unroll
        for (int i=0;i<4;i++)
            e[1+t][i] = g_AGG[((size_t)t*B_ + b)*128 + i*32 + lane];

    float pself = 0.f;
    #pragma unroll
    for (int i=0;i<4;i++) pself += e[0][i]*a0[i];
    float sc[12];
    #pragma unroll
    for (int j=0;j<12;j++) {
        float p = 0.f;
        #pragma unroll
        for (int i=0;i<4;i++) p += e[j][i]*a1[i];
        sc[j] = p;
    }
    #pragma unroll
    for (int off=16; off>0; off>>=1) {
        pself += __shfl_xor_sync(0xffffffff, pself, off);
        #pragma unroll
        for (int j=0;j<12;j++) sc[j] += __shfl_xor_sync(0xffffffff, sc[j], off);
    }
    float mx = -1e30f;
    #pragma unroll
    for (int j=0;j<12;j++) {
        float s = pself + sc[j];
        s = (s > 0.f) ? s : 0.01f*s;    // leaky_relu(0.01)
        sc[j] = s;
        mx = fmaxf(mx, s);
    }
    float sum = 0.f;
    #pragma unroll
    for (int j=0;j<12;j++) { sc[j] = expf(sc[j]-mx); sum += sc[j]; }
    float inv = 1.f/sum;
    #pragma unroll
    for (int i=0;i<4;i++) {
        float o = 0.f;
        #pragma unroll
        for (int j=0;j<12;j++) o += sc[j]*e[j][i];
        out[(size_t)b*128 + i*32 + lane] = o*inv;
    }
}

// ---------------- launch (single stream, 4 launches) ----------------
extern "C" void kernel_launch(void* const* d_in, const int* in_sizes, int n_in,
                              void* d_out, int out_size)
{
    const float* features = (const float*)d_in[0];
    const int*   id_batch = (const int*)d_in[1];
    const int*   neigh_ids= (const int*)d_in[2];
    const float* cWih_f   = (const float*)d_in[3];
    const float* cb_f     = (const float*)d_in[5];
    const float* cWih_b   = (const float*)d_in[6];
    const float* cb_b     = (const float*)d_in[8];
    const float* nWih_f   = (const float*)d_in[9];
    const float* nWhh_f   = (const float*)d_in[10];
    const float* nb_f     = (const float*)d_in[11];
    const float* nWih_b   = (const float*)d_in[12];
    const float* nWhh_b   = (const float*)d_in[13];
    const float* nb_b     = (const float*)d_in[14];
    const float* att      = (const float*)d_in[15];
    float* out = (float*)d_out;

    const int SMEM_PROJ  = (2*64*68 + 16*200) * 4;              // 47616
    const int SMEM_RECUR = (32*264 + 2*32*36 + 32*K_) * 4;      // 44288
    cudaFuncSetAttribute(proj_kernel,  cudaFuncAttributeMaxDynamicSharedMemorySize, SMEM_PROJ);
    cudaFuncSetAttribute(recur_kernel, cudaFuncAttributeMaxDynamicSharedMemorySize, SMEM_RECUR);

    pack_kernel<<<512, 256>>>(cWih_f, cb_f, cWih_b, cb_b,
                              nWih_f, nb_f, nWih_b, nb_b, nWhh_f, nWhh_b);

    {   // fused content encode + input projection, all types
        dim3 g(MROW_BLKS, T_);
        proj_kernel<<<g, 256, SMEM_PROJ>>>(features);
    }
    {   // recurrence, all types
        dim3 g(B_/32, 2, T_);
        recur_kernel<<<g, 256, SMEM_RECUR>>>(neigh_ids);
    }
    attn_kernel<<<B_/8, 256>>>(id_batch, att, out);
}